// round 1
// baseline (speedup 1.0000x reference)
#include <cuda_runtime.h>
#include <math.h>
#include <stdint.h>

// Problem constants
#define Bz 4
#define Tz 2048
#define Cz 768
#define NHz 12
#define HDz 64
#define TOKz (Bz * Tz)   // 8192

// Scratch (device globals — no allocations allowed)
__device__ float g_q[TOKz * Cz];
__device__ float g_k[TOKz * Cz];
__device__ float g_v[TOKz * Cz];
__device__ float g_y[TOKz * Cz];

// ---------------------------------------------------------------------------
// GEMM (NT): C[m][n] = sum_k A[m][k] * B[n][k]
// A: MxK row-major, B: NxK row-major, C: MxN row-major.
// 128x128 block tile, BK=8, 256 threads, 8x8 micro-tile.
// Requires M%128==0, N%128==0, K%8==0 (true for all our shapes).
// ---------------------------------------------------------------------------
__global__ __launch_bounds__(256) void gemm_nt(const float* __restrict__ A,
                                               const float* __restrict__ B,
                                               float* __restrict__ C,
                                               int M, int N, int K)
{
    __shared__ float As[8][128];
    __shared__ float Bs[8][128];

    const int tid = threadIdx.x;
    const int bm = blockIdx.y * 128;
    const int bn = blockIdx.x * 128;

    const int lrow = tid >> 1;        // 0..127
    const int lk   = (tid & 1) << 2;  // 0 or 4

    const float* Ap = A + (size_t)(bm + lrow) * K + lk;
    const float* Bp = B + (size_t)(bn + lrow) * K + lk;

    const int tm = (tid >> 4) << 3;   // 0..120 step 8
    const int tn = (tid & 15) << 3;   // 0..120 step 8

    float acc[8][8];
#pragma unroll
    for (int i = 0; i < 8; i++)
#pragma unroll
        for (int j = 0; j < 8; j++) acc[i][j] = 0.f;

    for (int k0 = 0; k0 < K; k0 += 8) {
        float4 a = *(const float4*)(Ap + k0);
        float4 b = *(const float4*)(Bp + k0);
        __syncthreads();   // previous iteration's compute done
        As[lk + 0][lrow] = a.x; As[lk + 1][lrow] = a.y;
        As[lk + 2][lrow] = a.z; As[lk + 3][lrow] = a.w;
        Bs[lk + 0][lrow] = b.x; Bs[lk + 1][lrow] = b.y;
        Bs[lk + 2][lrow] = b.z; Bs[lk + 3][lrow] = b.w;
        __syncthreads();

#pragma unroll
        for (int kk = 0; kk < 8; kk++) {
            float ra[8], rb[8];
            *(float4*)(ra)     = *(const float4*)&As[kk][tm];
            *(float4*)(ra + 4) = *(const float4*)&As[kk][tm + 4];
            *(float4*)(rb)     = *(const float4*)&Bs[kk][tn];
            *(float4*)(rb + 4) = *(const float4*)&Bs[kk][tn + 4];
#pragma unroll
            for (int i = 0; i < 8; i++)
#pragma unroll
                for (int j = 0; j < 8; j++)
                    acc[i][j] += ra[i] * rb[j];
        }
    }

#pragma unroll
    for (int i = 0; i < 8; i++) {
        float* cp = C + (size_t)(bm + tm + i) * N + bn + tn;
        *(float4*)(cp)     = make_float4(acc[i][0], acc[i][1], acc[i][2], acc[i][3]);
        *(float4*)(cp + 4) = make_float4(acc[i][4], acc[i][5], acc[i][6], acc[i][7]);
    }
}

// ---------------------------------------------------------------------------
// RoPE + RMSNorm(*1.2) on q/k (in place) + gated value-embedding add on v.
// One block per token (384 threads = 12 warps = 12 heads).
// ---------------------------------------------------------------------------
__global__ __launch_bounds__(384) void rope_rms_gate_kernel(
    const float* __restrict__ x, const float* __restrict__ ve,
    const float* __restrict__ cosb, const float* __restrict__ sinb,
    const float* __restrict__ Wg)
{
    const int tok = blockIdx.x;
    const int t = tok & (Tz - 1);
    const int h = threadIdx.x >> 5;
    const int lane = threadIdx.x & 31;
    const size_t base = (size_t)tok * Cz + h * HDz;

    const float cv = cosb[t * 32 + lane];
    const float sv = sinb[t * 32 + lane];

    // q: rope + rms
    {
        float x1 = g_q[base + lane], x2 = g_q[base + 32 + lane];
        float r1 = x1 * cv - x2 * sv;
        float r2 = x1 * sv + x2 * cv;
        float ss = r1 * r1 + r2 * r2;
#pragma unroll
        for (int o = 16; o > 0; o >>= 1) ss += __shfl_xor_sync(0xFFFFFFFFu, ss, o);
        float inv = rsqrtf(ss * (1.0f / 64.0f) + 1e-6f) * 1.2f;
        g_q[base + lane] = r1 * inv;
        g_q[base + 32 + lane] = r2 * inv;
    }
    // k: rope + rms
    {
        float x1 = g_k[base + lane], x2 = g_k[base + 32 + lane];
        float r1 = x1 * cv - x2 * sv;
        float r2 = x1 * sv + x2 * cv;
        float ss = r1 * r1 + r2 * r2;
#pragma unroll
        for (int o = 16; o > 0; o >>= 1) ss += __shfl_xor_sync(0xFFFFFFFFu, ss, o);
        float inv = rsqrtf(ss * (1.0f / 64.0f) + 1e-6f) * 1.2f;
        g_k[base + lane] = r1 * inv;
        g_k[base + 32 + lane] = r2 * inv;
    }
    // gate: 3*sigmoid(x[tok, 0:12] . Wg[h, :])
    {
        float p = (lane < 12) ? x[(size_t)tok * Cz + lane] * Wg[h * 12 + lane] : 0.f;
#pragma unroll
        for (int o = 16; o > 0; o >>= 1) p += __shfl_xor_sync(0xFFFFFFFFu, p, o);
        float gate = 3.0f / (1.0f + __expf(-p));
        g_v[base + lane]      += gate * ve[base + lane];
        g_v[base + 32 + lane] += gate * ve[base + 32 + lane];
    }
}

// ---------------------------------------------------------------------------
// Sliding-window flash attention (fp32).
// Block = 256 threads handles 64 queries for one (b, h).
// Per key tile of 64: S = Q K^T (64x64x64), online softmax, O += P V.
// Thread (g = tid/16, c = tid%16) owns S rows [4g..4g+3] x cols [4c..4c+3]
// and O rows [4g..4g+3] x dims [4c..4c+3].
// ---------------------------------------------------------------------------
#define APAD 68  // row pitch (floats): 272B, 16B-aligned, conflict-shifting

__global__ __launch_bounds__(256) void attn_kernel(const int* __restrict__ winp)
{
    extern __shared__ float sm[];
    float* Qs = sm;                  // [64][APAD]
    float* Ks = sm + 64 * APAD;      // [64][APAD]
    float* Vs = sm + 2 * 64 * APAD;  // [64][APAD]
    float* Ps = sm + 3 * 64 * APAD;  // [64][APAD]

    const int qt0 = blockIdx.x * 64;
    const int h = blockIdx.y;
    const int b = blockIdx.z;
    const int tid = threadIdx.x;
    const int W = *winp;

    const int g = tid >> 4;
    const int c = tid & 15;
    const int qi0 = g * 4;
    const int dc0 = c * 4;   // serves as both k-col offset (scores) and d offset (output)

    // Load Q tile (rows contiguous in gmem: stride C)
    {
        const float* qb = g_q + (size_t)(b * Tz + qt0) * Cz + h * HDz;
        for (int it = tid; it < 64 * 16; it += 256) {
            int row = it >> 4, d4 = (it & 15) << 2;
            *(float4*)&Qs[row * APAD + d4] = *(const float4*)(qb + (size_t)row * Cz + d4);
        }
    }

    float m[4], l[4], o[4][4];
#pragma unroll
    for (int i = 0; i < 4; i++) {
        m[i] = -1e30f; l[i] = 0.f;
#pragma unroll
        for (int j = 0; j < 4; j++) o[i][j] = 0.f;
    }

    int lo = qt0 - W; if (lo < 0) lo = 0;
    const int kt_begin = lo & ~63;

    for (int kt0 = kt_begin; kt0 <= qt0 + 63; kt0 += 64) {
        __syncthreads();  // previous PV done with Ps/Vs, previous S done with Ks
        {
            const float* kb = g_k + (size_t)(b * Tz + kt0) * Cz + h * HDz;
            const float* vb = g_v + (size_t)(b * Tz + kt0) * Cz + h * HDz;
            for (int it = tid; it < 64 * 16; it += 256) {
                int row = it >> 4, d4 = (it & 15) << 2;
                *(float4*)&Ks[row * APAD + d4] = *(const float4*)(kb + (size_t)row * Cz + d4);
                *(float4*)&Vs[row * APAD + d4] = *(const float4*)(vb + (size_t)row * Cz + d4);
            }
        }
        __syncthreads();

        // S = Q K^T for this tile
        float s[4][4];
#pragma unroll
        for (int i = 0; i < 4; i++)
#pragma unroll
            for (int j = 0; j < 4; j++) s[i][j] = 0.f;

#pragma unroll
        for (int d0 = 0; d0 < 64; d0 += 4) {
            float4 qa[4], kv[4];
#pragma unroll
            for (int i = 0; i < 4; i++) qa[i] = *(const float4*)&Qs[(qi0 + i) * APAD + d0];
#pragma unroll
            for (int j = 0; j < 4; j++) kv[j] = *(const float4*)&Ks[(dc0 + j) * APAD + d0];
#pragma unroll
            for (int i = 0; i < 4; i++)
#pragma unroll
                for (int j = 0; j < 4; j++)
                    s[i][j] += qa[i].x * kv[j].x + qa[i].y * kv[j].y +
                               qa[i].z * kv[j].z + qa[i].w * kv[j].w;
        }

        // Masked online softmax; write probabilities to Ps
#pragma unroll
        for (int i = 0; i < 4; i++) {
            const int tg = qt0 + qi0 + i;
            float rm = -1e30f;
#pragma unroll
            for (int j = 0; j < 4; j++) {
                const int jg = kt0 + dc0 + j;
                const bool ok = (jg <= tg) && (tg - jg <= W);
                s[i][j] = ok ? s[i][j] * 0.125f : -1e30f;
                rm = fmaxf(rm, s[i][j]);
            }
#pragma unroll
            for (int off = 8; off > 0; off >>= 1)
                rm = fmaxf(rm, __shfl_xor_sync(0xFFFFFFFFu, rm, off));
            const float mn = fmaxf(m[i], rm);
            const float corr = __expf(m[i] - mn);   // 1 when both -1e30 (l,o are 0)
            float rs = 0.f;
#pragma unroll
            for (int j = 0; j < 4; j++) {
                float p = (s[i][j] > -1e29f) ? __expf(s[i][j] - mn) : 0.f;
                Ps[(qi0 + i) * APAD + dc0 + j] = p;
                rs += p;
            }
#pragma unroll
            for (int off = 8; off > 0; off >>= 1)
                rs += __shfl_xor_sync(0xFFFFFFFFu, rs, off);
            l[i] = l[i] * corr + rs;
            m[i] = mn;
#pragma unroll
            for (int j = 0; j < 4; j++) o[i][j] *= corr;
        }
        __syncthreads();  // Ps visible

        // O += P V
#pragma unroll 8
        for (int jj = 0; jj < 64; jj++) {
            const float4 vv = *(const float4*)&Vs[jj * APAD + dc0];
#pragma unroll
            for (int i = 0; i < 4; i++) {
                const float p = Ps[(qi0 + i) * APAD + jj];
                o[i][0] += p * vv.x; o[i][1] += p * vv.y;
                o[i][2] += p * vv.z; o[i][3] += p * vv.w;
            }
        }
    }

    // Epilogue: normalize and write y (B,T,NH,HD layout = token-major Cz)
#pragma unroll
    for (int i = 0; i < 4; i++) {
        const float inv = 1.0f / l[i];
        float* yb = g_y + (size_t)(b * Tz + qt0 + qi0 + i) * Cz + h * HDz + dc0;
        *(float4*)yb = make_float4(o[i][0] * inv, o[i][1] * inv,
                                   o[i][2] * inv, o[i][3] * inv);
    }
}

// ---------------------------------------------------------------------------
extern "C" void kernel_launch(void* const* d_in, const int* in_sizes, int n_in,
                              void* d_out, int out_size)
{
    const float* x     = (const float*)d_in[0];
    const float* ve    = (const float*)d_in[1];
    const float* cosb  = (const float*)d_in[2];
    const float* sinb  = (const float*)d_in[3];
    const float* Wq    = (const float*)d_in[4];
    const float* Wk    = (const float*)d_in[5];
    const float* Wv    = (const float*)d_in[6];
    const float* Wproj = (const float*)d_in[7];
    const float* Wg    = (const float*)d_in[8];
    const int*   win   = (const int*)d_in[9];
    float* out = (float*)d_out;

    float *qp, *kp, *vp, *yp;
    cudaGetSymbolAddress((void**)&qp, g_q);
    cudaGetSymbolAddress((void**)&kp, g_k);
    cudaGetSymbolAddress((void**)&vp, g_v);
    cudaGetSymbolAddress((void**)&yp, g_y);

    dim3 gg(Cz / 128, TOKz / 128);   // (6, 64)
    gemm_nt<<<gg, 256>>>(x, Wq, qp, TOKz, Cz, Cz);
    gemm_nt<<<gg, 256>>>(x, Wk, kp, TOKz, Cz, Cz);
    gemm_nt<<<gg, 256>>>(x, Wv, vp, TOKz, Cz, Cz);

    rope_rms_gate_kernel<<<TOKz, 384>>>(x, ve, cosb, sinb, Wg);

    const size_t ASMEM = (size_t)4 * 64 * APAD * sizeof(float);  // 69632 B
    cudaFuncSetAttribute(attn_kernel, cudaFuncAttributeMaxDynamicSharedMemorySize,
                         (int)ASMEM);
    attn_kernel<<<dim3(Tz / 64, NHz, Bz), 256, ASMEM>>>(win);

    gemm_nt<<<gg, 256>>>(yp, Wproj, out, TOKz, Cz, Cz);
}

// round 3
// speedup vs baseline: 1.6055x; 1.6055x over previous
#include <cuda_runtime.h>
#include <cuda_bf16.h>
#include <math.h>
#include <stdint.h>

// Problem constants
#define Bz 4
#define Tz 2048
#define Cz 768
#define NHz 12
#define HDz 64
#define TOKz (Bz * Tz)   // 8192

// fp32 intermediates
__device__ float g_q[TOKz * Cz];
__device__ float g_k[TOKz * Cz];
__device__ float g_v[TOKz * Cz];
__device__ float g_y[TOKz * Cz];

// split-bf16 operands
__device__ __nv_bfloat16 g_xhi[TOKz * Cz];
__device__ __nv_bfloat16 g_xlo[TOKz * Cz];
__device__ __nv_bfloat16 g_yhi[TOKz * Cz];
__device__ __nv_bfloat16 g_ylo[TOKz * Cz];
__device__ __nv_bfloat16 g_whi[4 * Cz * Cz];
__device__ __nv_bfloat16 g_wlo[4 * Cz * Cz];

// ---------------------------------------------------------------------------
// Helpers
// ---------------------------------------------------------------------------
__device__ __forceinline__ uint32_t smem_u32(const void* p) {
    uint32_t a;
    asm("{ .reg .u64 t; cvta.to.shared.u64 t, %1; cvt.u32.u64 %0, t; }"
        : "=r"(a) : "l"(p));
    return a;
}

#define LDSM4(r, addr)                                                        \
    asm volatile("ldmatrix.sync.aligned.m8n8.x4.shared.b16 {%0,%1,%2,%3}, [%4];" \
                 : "=r"((r)[0]), "=r"((r)[1]), "=r"((r)[2]), "=r"((r)[3])     \
                 : "r"(addr))

#define LDSM2(r, addr)                                                        \
    asm volatile("ldmatrix.sync.aligned.m8n8.x2.shared.b16 {%0,%1}, [%2];"    \
                 : "=r"((r)[0]), "=r"((r)[1]) : "r"(addr))

#define MMA16816(c, a, b)                                                     \
    asm volatile("mma.sync.aligned.m16n8k16.row.col.f32.bf16.bf16.f32 "      \
                 "{%0,%1,%2,%3}, {%4,%5,%6,%7}, {%8,%9}, {%0,%1,%2,%3};"     \
                 : "+f"((c)[0]), "+f"((c)[1]), "+f"((c)[2]), "+f"((c)[3])    \
                 : "r"((a)[0]), "r"((a)[1]), "r"((a)[2]), "r"((a)[3]),       \
                   "r"((b)[0]), "r"((b)[1]))

#define CPASYNC16(s, g)                                                       \
    asm volatile("cp.async.ca.shared.global [%0], [%1], 16;" :: "r"(s), "l"(g))

// ---------------------------------------------------------------------------
// Split-bf16 HMMA GEMM (NT): C[8192x768] = A[8192x768] * B[768x768]^T
// Block 128x128, chunks of K=64, 8 warps (2x4), warp tile 64x32.
// SW128-swizzled smem, ldmatrix fragment loads, cp.async double buffer.
// ---------------------------------------------------------------------------
#define GK 768
#define NCH 12
#define ARR 16384                 // one 128x64 bf16 array (swizzled)
#define STG (4 * ARR)             // Ahi, Alo, Bhi, Blo = 64 KB
#define GSMEM (2 * STG)           // 128 KB

__global__ __launch_bounds__(256) void gemm_mma(
    const __nv_bfloat16* __restrict__ Ahi, const __nv_bfloat16* __restrict__ Alo,
    const __nv_bfloat16* __restrict__ Bhi, const __nv_bfloat16* __restrict__ Blo,
    float* __restrict__ C)
{
    extern __shared__ __align__(1024) char dsm[];
    const uint32_t sb = smem_u32(dsm);
    const int tid = threadIdx.x;
    const int wid = tid >> 5, lane = tid & 31;
    const int bm = blockIdx.y << 7;
    const int bn = blockIdx.x << 7;
    const int warp_m = wid >> 2;     // 0..1
    const int warp_n = wid & 3;      // 0..3

    const __nv_bfloat16* gA[2] = { Ahi + (size_t)bm * GK, Alo + (size_t)bm * GK };
    const __nv_bfloat16* gB[2] = { Bhi + (size_t)bn * GK, Blo + (size_t)bn * GK };

    // per-thread load geometry: 4 segments per array, 16B each
    const int lrow = tid >> 3;       // base row (tid covers rows 0..31 x 8 chunks)
    const int lc16 = tid & 7;        // 16B-chunk within 128B row

    float acc[4][4][4];
#pragma unroll
    for (int i = 0; i < 4; i++)
#pragma unroll
        for (int j = 0; j < 4; j++)
#pragma unroll
            for (int k = 0; k < 4; k++) acc[i][j][k] = 0.f;

    // issue cp.async for one chunk into stage s
    auto issue = [&](int c, int s) {
        uint32_t sbase = sb + s * STG;
#pragma unroll
        for (int i = 0; i < 4; i++) {
            int row = lrow + i * 32;
            uint32_t so = (uint32_t)(row * 128 + lc16 * 16) ^ (uint32_t)((row & 7) << 4);
            size_t go = (size_t)row * GK + c * 64 + lc16 * 8;
            CPASYNC16(sbase + 0 * ARR + so, (const char*)(gA[0] + go));
            CPASYNC16(sbase + 1 * ARR + so, (const char*)(gA[1] + go));
            CPASYNC16(sbase + 2 * ARR + so, (const char*)(gB[0] + go));
            CPASYNC16(sbase + 3 * ARR + so, (const char*)(gB[1] + go));
        }
        asm volatile("cp.async.commit_group;");
    };

    issue(0, 0);

    // fragment address components (constant per lane)
    const uint32_t aswz = (uint32_t)((lane & 7) << 4);
    const int arow = warp_m * 64 + (lane & 15);
    const int brow = warp_n * 32 + (lane & 7);
    const uint32_t akhi = (uint32_t)((lane >> 4) << 4);      // +16B for matrices 2,3
    const uint32_t bkhi = (uint32_t)(((lane >> 3) & 1) << 4);

#pragma unroll 1
    for (int c = 0; c < NCH; ++c) {
        if (c + 1 < NCH) {
            issue(c + 1, (c + 1) & 1);
            asm volatile("cp.async.wait_group 1;");
        } else {
            asm volatile("cp.async.wait_group 0;");
        }
        __syncthreads();

        const uint32_t sbase = sb + (c & 1) * STG;
#pragma unroll
        for (int ks = 0; ks < 4; ++ks) {
            uint32_t ah[4][4], al[4][4], bh[4][2], bl[4][2];
            const uint32_t ak = ((uint32_t)(ks * 32) + akhi) ^ aswz;
            const uint32_t bk = ((uint32_t)(ks * 32) + bkhi) ^ aswz;
#pragma unroll
            for (int mt = 0; mt < 4; mt++) {
                uint32_t ra = sbase + (uint32_t)((arow + mt * 16) * 128) + ak;
                LDSM4(ah[mt], ra);
                LDSM4(al[mt], ra + ARR);
            }
#pragma unroll
            for (int nt = 0; nt < 4; nt++) {
                uint32_t rb = sbase + 2 * ARR + (uint32_t)((brow + nt * 8) * 128) + bk;
                LDSM2(bh[nt], rb);
                LDSM2(bl[nt], rb + ARR);
            }
#pragma unroll
            for (int mt = 0; mt < 4; mt++)
#pragma unroll
                for (int nt = 0; nt < 4; nt++) {
                    MMA16816(acc[mt][nt], ah[mt], bh[nt]);
                    MMA16816(acc[mt][nt], ah[mt], bl[nt]);
                    MMA16816(acc[mt][nt], al[mt], bh[nt]);
                }
        }
        __syncthreads();   // compute done before stage reuse
    }

    // epilogue
    const int crow = bm + warp_m * 64 + (lane >> 2);
    const int ccol = bn + warp_n * 32 + (lane & 3) * 2;
#pragma unroll
    for (int mt = 0; mt < 4; mt++)
#pragma unroll
        for (int nt = 0; nt < 4; nt++) {
            float* p0 = C + (size_t)(crow + mt * 16) * Cz + ccol + nt * 8;
            float* p1 = p0 + 8 * Cz;
            *(float2*)p0 = make_float2(acc[mt][nt][0], acc[mt][nt][1]);
            *(float2*)p1 = make_float2(acc[mt][nt][2], acc[mt][nt][3]);
        }
}

// ---------------------------------------------------------------------------
// fp32 -> split bf16 (hi + lo), float4-vectorized
// ---------------------------------------------------------------------------
__global__ void cvt_split4(const float4* __restrict__ s,
                           __nv_bfloat16* __restrict__ hi,
                           __nv_bfloat16* __restrict__ lo, int n4)
{
    int i = blockIdx.x * 256 + threadIdx.x;
    if (i >= n4) return;
    float4 v = s[i];
    __nv_bfloat16 h0 = __float2bfloat16(v.x);
    __nv_bfloat16 h1 = __float2bfloat16(v.y);
    __nv_bfloat16 h2 = __float2bfloat16(v.z);
    __nv_bfloat16 h3 = __float2bfloat16(v.w);
    __nv_bfloat16 l0 = __float2bfloat16(v.x - __bfloat162float(h0));
    __nv_bfloat16 l1 = __float2bfloat16(v.y - __bfloat162float(h1));
    __nv_bfloat16 l2 = __float2bfloat16(v.z - __bfloat162float(h2));
    __nv_bfloat16 l3 = __float2bfloat16(v.w - __bfloat162float(h3));
    ((__nv_bfloat162*)hi)[2 * i]     = __nv_bfloat162(h0, h1);
    ((__nv_bfloat162*)hi)[2 * i + 1] = __nv_bfloat162(h2, h3);
    ((__nv_bfloat162*)lo)[2 * i]     = __nv_bfloat162(l0, l1);
    ((__nv_bfloat162*)lo)[2 * i + 1] = __nv_bfloat162(l2, l3);
}

// ---------------------------------------------------------------------------
// RoPE + RMSNorm(*1.2) on q/k (in place) + gated value-embedding add on v.
// ---------------------------------------------------------------------------
__global__ __launch_bounds__(384) void rope_rms_gate_kernel(
    const float* __restrict__ x, const float* __restrict__ ve,
    const float* __restrict__ cosb, const float* __restrict__ sinb,
    const float* __restrict__ Wg)
{
    const int tok = blockIdx.x;
    const int t = tok & (Tz - 1);
    const int h = threadIdx.x >> 5;
    const int lane = threadIdx.x & 31;
    const size_t base = (size_t)tok * Cz + h * HDz;

    const float cv = cosb[t * 32 + lane];
    const float sv = sinb[t * 32 + lane];

    {
        float x1 = g_q[base + lane], x2 = g_q[base + 32 + lane];
        float r1 = x1 * cv - x2 * sv;
        float r2 = x1 * sv + x2 * cv;
        float ss = r1 * r1 + r2 * r2;
#pragma unroll
        for (int o = 16; o > 0; o >>= 1) ss += __shfl_xor_sync(0xFFFFFFFFu, ss, o);
        float inv = rsqrtf(ss * (1.0f / 64.0f) + 1e-6f) * 1.2f;
        g_q[base + lane] = r1 * inv;
        g_q[base + 32 + lane] = r2 * inv;
    }
    {
        float x1 = g_k[base + lane], x2 = g_k[base + 32 + lane];
        float r1 = x1 * cv - x2 * sv;
        float r2 = x1 * sv + x2 * cv;
        float ss = r1 * r1 + r2 * r2;
#pragma unroll
        for (int o = 16; o > 0; o >>= 1) ss += __shfl_xor_sync(0xFFFFFFFFu, ss, o);
        float inv = rsqrtf(ss * (1.0f / 64.0f) + 1e-6f) * 1.2f;
        g_k[base + lane] = r1 * inv;
        g_k[base + 32 + lane] = r2 * inv;
    }
    {
        float p = (lane < 12) ? x[(size_t)tok * Cz + lane] * Wg[h * 12 + lane] : 0.f;
#pragma unroll
        for (int o = 16; o > 0; o >>= 1) p += __shfl_xor_sync(0xFFFFFFFFu, p, o);
        float gate = 3.0f / (1.0f + __expf(-p));
        g_v[base + lane]      += gate * ve[base + lane];
        g_v[base + 32 + lane] += gate * ve[base + 32 + lane];
    }
}

// ---------------------------------------------------------------------------
// Sliding-window flash attention (fp32 SIMT).
// ---------------------------------------------------------------------------
#define APAD 68

__global__ __launch_bounds__(256) void attn_kernel(const int* __restrict__ winp)
{
    extern __shared__ float sm[];
    float* Qs = sm;
    float* Ks = sm + 64 * APAD;
    float* Vs = sm + 2 * 64 * APAD;
    float* Ps = sm + 3 * 64 * APAD;

    const int qt0 = blockIdx.x * 64;
    const int h = blockIdx.y;
    const int b = blockIdx.z;
    const int tid = threadIdx.x;
    const int W = *winp;

    const int g = tid >> 4;
    const int c = tid & 15;
    const int qi0 = g * 4;
    const int dc0 = c * 4;

    {
        const float* qb = g_q + (size_t)(b * Tz + qt0) * Cz + h * HDz;
        for (int it = tid; it < 64 * 16; it += 256) {
            int row = it >> 4, d4 = (it & 15) << 2;
            *(float4*)&Qs[row * APAD + d4] = *(const float4*)(qb + (size_t)row * Cz + d4);
        }
    }

    float m[4], l[4], o[4][4];
#pragma unroll
    for (int i = 0; i < 4; i++) {
        m[i] = -1e30f; l[i] = 0.f;
#pragma unroll
        for (int j = 0; j < 4; j++) o[i][j] = 0.f;
    }

    int lo = qt0 - W; if (lo < 0) lo = 0;
    const int kt_begin = lo & ~63;

    for (int kt0 = kt_begin; kt0 <= qt0 + 63; kt0 += 64) {
        __syncthreads();
        {
            const float* kb = g_k + (size_t)(b * Tz + kt0) * Cz + h * HDz;
            const float* vb = g_v + (size_t)(b * Tz + kt0) * Cz + h * HDz;
            for (int it = tid; it < 64 * 16; it += 256) {
                int row = it >> 4, d4 = (it & 15) << 2;
                *(float4*)&Ks[row * APAD + d4] = *(const float4*)(kb + (size_t)row * Cz + d4);
                *(float4*)&Vs[row * APAD + d4] = *(const float4*)(vb + (size_t)row * Cz + d4);
            }
        }
        __syncthreads();

        float s[4][4];
#pragma unroll
        for (int i = 0; i < 4; i++)
#pragma unroll
            for (int j = 0; j < 4; j++) s[i][j] = 0.f;

#pragma unroll
        for (int d0 = 0; d0 < 64; d0 += 4) {
            float4 qa[4], kv[4];
#pragma unroll
            for (int i = 0; i < 4; i++) qa[i] = *(const float4*)&Qs[(qi0 + i) * APAD + d0];
#pragma unroll
            for (int j = 0; j < 4; j++) kv[j] = *(const float4*)&Ks[(dc0 + j) * APAD + d0];
#pragma unroll
            for (int i = 0; i < 4; i++)
#pragma unroll
                for (int j = 0; j < 4; j++)
                    s[i][j] += qa[i].x * kv[j].x + qa[i].y * kv[j].y +
                               qa[i].z * kv[j].z + qa[i].w * kv[j].w;
        }

#pragma unroll
        for (int i = 0; i < 4; i++) {
            const int tg = qt0 + qi0 + i;
            float rm = -1e30f;
#pragma unroll
            for (int j = 0; j < 4; j++) {
                const int jg = kt0 + dc0 + j;
                const bool ok = (jg <= tg) && (tg - jg <= W);
                s[i][j] = ok ? s[i][j] * 0.125f : -1e30f;
                rm = fmaxf(rm, s[i][j]);
            }
#pragma unroll
            for (int off = 8; off > 0; off >>= 1)
                rm = fmaxf(rm, __shfl_xor_sync(0xFFFFFFFFu, rm, off));
            const float mn = fmaxf(m[i], rm);
            const float corr = __expf(m[i] - mn);
            float rs = 0.f;
#pragma unroll
            for (int j = 0; j < 4; j++) {
                float p = (s[i][j] > -1e29f) ? __expf(s[i][j] - mn) : 0.f;
                Ps[(qi0 + i) * APAD + dc0 + j] = p;
                rs += p;
            }
#pragma unroll
            for (int off = 8; off > 0; off >>= 1)
                rs += __shfl_xor_sync(0xFFFFFFFFu, rs, off);
            l[i] = l[i] * corr + rs;
            m[i] = mn;
#pragma unroll
            for (int j = 0; j < 4; j++) o[i][j] *= corr;
        }
        __syncthreads();

#pragma unroll 8
        for (int jj = 0; jj < 64; jj++) {
            const float4 vv = *(const float4*)&Vs[jj * APAD + dc0];
#pragma unroll
            for (int i = 0; i < 4; i++) {
                const float p = Ps[(qi0 + i) * APAD + jj];
                o[i][0] += p * vv.x; o[i][1] += p * vv.y;
                o[i][2] += p * vv.z; o[i][3] += p * vv.w;
            }
        }
    }

#pragma unroll
    for (int i = 0; i < 4; i++) {
        const float inv = 1.0f / l[i];
        float* yb = g_y + (size_t)(b * Tz + qt0 + qi0 + i) * Cz + h * HDz + dc0;
        *(float4*)yb = make_float4(o[i][0] * inv, o[i][1] * inv,
                                   o[i][2] * inv, o[i][3] * inv);
    }
}

// ---------------------------------------------------------------------------
extern "C" void kernel_launch(void* const* d_in, const int* in_sizes, int n_in,
                              void* d_out, int out_size)
{
    const float* x     = (const float*)d_in[0];
    const float* ve    = (const float*)d_in[1];
    const float* cosb  = (const float*)d_in[2];
    const float* sinb  = (const float*)d_in[3];
    const float* Wq    = (const float*)d_in[4];
    const float* Wk    = (const float*)d_in[5];
    const float* Wv    = (const float*)d_in[6];
    const float* Wproj = (const float*)d_in[7];
    const float* Wg    = (const float*)d_in[8];
    const int*   win   = (const int*)d_in[9];
    float* out = (float*)d_out;

    float *qp, *kp, *vp, *yp;
    __nv_bfloat16 *xhi, *xlo, *yhi, *ylo, *whi, *wlo;
    cudaGetSymbolAddress((void**)&qp, g_q);
    cudaGetSymbolAddress((void**)&kp, g_k);
    cudaGetSymbolAddress((void**)&vp, g_v);
    cudaGetSymbolAddress((void**)&yp, g_y);
    cudaGetSymbolAddress((void**)&xhi, g_xhi);
    cudaGetSymbolAddress((void**)&xlo, g_xlo);
    cudaGetSymbolAddress((void**)&yhi, g_yhi);
    cudaGetSymbolAddress((void**)&ylo, g_ylo);
    cudaGetSymbolAddress((void**)&whi, g_whi);
    cudaGetSymbolAddress((void**)&wlo, g_wlo);

    const int WW = Cz * Cz;               // 589824
    const int n4x = TOKz * Cz / 4;
    const int n4w = WW / 4;

    cvt_split4<<<(n4x + 255) / 256, 256>>>((const float4*)x, xhi, xlo, n4x);
    cvt_split4<<<(n4w + 255) / 256, 256>>>((const float4*)Wq,    whi + 0 * WW, wlo + 0 * WW, n4w);
    cvt_split4<<<(n4w + 255) / 256, 256>>>((const float4*)Wk,    whi + 1 * WW, wlo + 1 * WW, n4w);
    cvt_split4<<<(n4w + 255) / 256, 256>>>((const float4*)Wv,    whi + 2 * WW, wlo + 2 * WW, n4w);
    cvt_split4<<<(n4w + 255) / 256, 256>>>((const float4*)Wproj, whi + 3 * WW, wlo + 3 * WW, n4w);

    cudaFuncSetAttribute(gemm_mma, cudaFuncAttributeMaxDynamicSharedMemorySize, GSMEM);
    dim3 gg(Cz / 128, TOKz / 128);   // (6, 64)
    gemm_mma<<<gg, 256, GSMEM>>>(xhi, xlo, whi + 0 * WW, wlo + 0 * WW, qp);
    gemm_mma<<<gg, 256, GSMEM>>>(xhi, xlo, whi + 1 * WW, wlo + 1 * WW, kp);
    gemm_mma<<<gg, 256, GSMEM>>>(xhi, xlo, whi + 2 * WW, wlo + 2 * WW, vp);

    rope_rms_gate_kernel<<<TOKz, 384>>>(x, ve, cosb, sinb, Wg);

    const size_t ASMEM = (size_t)4 * 64 * APAD * sizeof(float);
    cudaFuncSetAttribute(attn_kernel, cudaFuncAttributeMaxDynamicSharedMemorySize,
                         (int)ASMEM);
    attn_kernel<<<dim3(Tz / 64, NHz, Bz), 256, ASMEM>>>(win);

    cvt_split4<<<(n4x + 255) / 256, 256>>>((const float4*)yp, yhi, ylo, n4x);
    gemm_mma<<<gg, 256, GSMEM>>>(yhi, ylo, whi + 3 * WW, wlo + 3 * WW, out);
}

// round 4
// speedup vs baseline: 3.7875x; 2.3591x over previous
#include <cuda_runtime.h>
#include <cuda_bf16.h>
#include <math.h>
#include <stdint.h>

// Problem constants
#define Bz 4
#define Tz 2048
#define Cz 768
#define NHz 12
#define HDz 64
#define TOKz (Bz * Tz)   // 8192

// fp32 intermediates
__device__ float g_q[TOKz * Cz];
__device__ float g_k[TOKz * Cz];
__device__ float g_v[TOKz * Cz];
__device__ float g_y[TOKz * Cz];

// split-bf16 operands (GEMM)
__device__ __nv_bfloat16 g_xhi[TOKz * Cz];
__device__ __nv_bfloat16 g_xlo[TOKz * Cz];
__device__ __nv_bfloat16 g_yhi[TOKz * Cz];
__device__ __nv_bfloat16 g_ylo[TOKz * Cz];
__device__ __nv_bfloat16 g_whi[4 * Cz * Cz];
__device__ __nv_bfloat16 g_wlo[4 * Cz * Cz];

// split-bf16 q/k/v for MMA attention
__device__ __nv_bfloat16 g_qh[TOKz * Cz];
__device__ __nv_bfloat16 g_ql[TOKz * Cz];
__device__ __nv_bfloat16 g_kh[TOKz * Cz];
__device__ __nv_bfloat16 g_kl[TOKz * Cz];
__device__ __nv_bfloat16 g_vh[TOKz * Cz];
__device__ __nv_bfloat16 g_vl[TOKz * Cz];

// ---------------------------------------------------------------------------
// Helpers
// ---------------------------------------------------------------------------
__device__ __forceinline__ uint32_t smem_u32(const void* p) {
    uint32_t a;
    asm("{ .reg .u64 t; cvta.to.shared.u64 t, %1; cvt.u32.u64 %0, t; }"
        : "=r"(a) : "l"(p));
    return a;
}

#define LDSM4(r, addr)                                                        \
    asm volatile("ldmatrix.sync.aligned.m8n8.x4.shared.b16 {%0,%1,%2,%3}, [%4];" \
                 : "=r"((r)[0]), "=r"((r)[1]), "=r"((r)[2]), "=r"((r)[3])     \
                 : "r"(addr))

#define LDSM4T(r, addr)                                                       \
    asm volatile("ldmatrix.sync.aligned.m8n8.x4.trans.shared.b16 {%0,%1,%2,%3}, [%4];" \
                 : "=r"((r)[0]), "=r"((r)[1]), "=r"((r)[2]), "=r"((r)[3])     \
                 : "r"(addr))

#define LDSM2(r, addr)                                                        \
    asm volatile("ldmatrix.sync.aligned.m8n8.x2.shared.b16 {%0,%1}, [%2];"    \
                 : "=r"((r)[0]), "=r"((r)[1]) : "r"(addr))

#define MMA16816(c, a, b)                                                     \
    asm volatile("mma.sync.aligned.m16n8k16.row.col.f32.bf16.bf16.f32 "      \
                 "{%0,%1,%2,%3}, {%4,%5,%6,%7}, {%8,%9}, {%0,%1,%2,%3};"     \
                 : "+f"((c)[0]), "+f"((c)[1]), "+f"((c)[2]), "+f"((c)[3])    \
                 : "r"((a)[0]), "r"((a)[1]), "r"((a)[2]), "r"((a)[3]),       \
                   "r"((b)[0]), "r"((b)[1]))

#define MMA16816B(c, a, b0, b1)                                               \
    asm volatile("mma.sync.aligned.m16n8k16.row.col.f32.bf16.bf16.f32 "      \
                 "{%0,%1,%2,%3}, {%4,%5,%6,%7}, {%8,%9}, {%0,%1,%2,%3};"     \
                 : "+f"((c)[0]), "+f"((c)[1]), "+f"((c)[2]), "+f"((c)[3])    \
                 : "r"((a)[0]), "r"((a)[1]), "r"((a)[2]), "r"((a)[3]),       \
                   "r"(b0), "r"(b1))

#define CPASYNC16(s, g)                                                       \
    asm volatile("cp.async.ca.shared.global [%0], [%1], 16;" :: "r"(s), "l"(g))

__device__ __forceinline__ uint32_t pack_bf16x2(float lo, float hi) {
    __nv_bfloat162 t = __floats2bfloat162_rn(lo, hi);
    return *(uint32_t*)&t;
}

// ---------------------------------------------------------------------------
// Split-bf16 HMMA GEMM (NT): unchanged from R3 (validated).
// ---------------------------------------------------------------------------
#define GK 768
#define NCH 12
#define ARR 16384
#define STG (4 * ARR)
#define GSMEM (2 * STG)

__global__ __launch_bounds__(256) void gemm_mma(
    const __nv_bfloat16* __restrict__ Ahi, const __nv_bfloat16* __restrict__ Alo,
    const __nv_bfloat16* __restrict__ Bhi, const __nv_bfloat16* __restrict__ Blo,
    float* __restrict__ C)
{
    extern __shared__ __align__(1024) char dsm[];
    const uint32_t sb = smem_u32(dsm);
    const int tid = threadIdx.x;
    const int wid = tid >> 5, lane = tid & 31;
    const int bm = blockIdx.y << 7;
    const int bn = blockIdx.x << 7;
    const int warp_m = wid >> 2;
    const int warp_n = wid & 3;

    const __nv_bfloat16* gA[2] = { Ahi + (size_t)bm * GK, Alo + (size_t)bm * GK };
    const __nv_bfloat16* gB[2] = { Bhi + (size_t)bn * GK, Blo + (size_t)bn * GK };

    const int lrow = tid >> 3;
    const int lc16 = tid & 7;

    float acc[4][4][4];
#pragma unroll
    for (int i = 0; i < 4; i++)
#pragma unroll
        for (int j = 0; j < 4; j++)
#pragma unroll
            for (int k = 0; k < 4; k++) acc[i][j][k] = 0.f;

    auto issue = [&](int c, int s) {
        uint32_t sbase = sb + s * STG;
#pragma unroll
        for (int i = 0; i < 4; i++) {
            int row = lrow + i * 32;
            uint32_t so = (uint32_t)(row * 128 + lc16 * 16) ^ (uint32_t)((row & 7) << 4);
            size_t go = (size_t)row * GK + c * 64 + lc16 * 8;
            CPASYNC16(sbase + 0 * ARR + so, (const char*)(gA[0] + go));
            CPASYNC16(sbase + 1 * ARR + so, (const char*)(gA[1] + go));
            CPASYNC16(sbase + 2 * ARR + so, (const char*)(gB[0] + go));
            CPASYNC16(sbase + 3 * ARR + so, (const char*)(gB[1] + go));
        }
        asm volatile("cp.async.commit_group;");
    };

    issue(0, 0);

    const uint32_t aswz = (uint32_t)((lane & 7) << 4);
    const int arow = warp_m * 64 + (lane & 15);
    const int brow = warp_n * 32 + (lane & 7);
    const uint32_t akhi = (uint32_t)((lane >> 4) << 4);
    const uint32_t bkhi = (uint32_t)(((lane >> 3) & 1) << 4);

#pragma unroll 1
    for (int c = 0; c < NCH; ++c) {
        if (c + 1 < NCH) {
            issue(c + 1, (c + 1) & 1);
            asm volatile("cp.async.wait_group 1;");
        } else {
            asm volatile("cp.async.wait_group 0;");
        }
        __syncthreads();

        const uint32_t sbase = sb + (c & 1) * STG;
#pragma unroll
        for (int ks = 0; ks < 4; ++ks) {
            uint32_t ah[4][4], al[4][4], bh[4][2], bl[4][2];
            const uint32_t ak = ((uint32_t)(ks * 32) + akhi) ^ aswz;
            const uint32_t bk = ((uint32_t)(ks * 32) + bkhi) ^ aswz;
#pragma unroll
            for (int mt = 0; mt < 4; mt++) {
                uint32_t ra = sbase + (uint32_t)((arow + mt * 16) * 128) + ak;
                LDSM4(ah[mt], ra);
                LDSM4(al[mt], ra + ARR);
            }
#pragma unroll
            for (int nt = 0; nt < 4; nt++) {
                uint32_t rb = sbase + 2 * ARR + (uint32_t)((brow + nt * 8) * 128) + bk;
                LDSM2(bh[nt], rb);
                LDSM2(bl[nt], rb + ARR);
            }
#pragma unroll
            for (int mt = 0; mt < 4; mt++)
#pragma unroll
                for (int nt = 0; nt < 4; nt++) {
                    MMA16816(acc[mt][nt], ah[mt], bh[nt]);
                    MMA16816(acc[mt][nt], ah[mt], bl[nt]);
                    MMA16816(acc[mt][nt], al[mt], bh[nt]);
                }
        }
        __syncthreads();
    }

    const int crow = bm + warp_m * 64 + (lane >> 2);
    const int ccol = bn + warp_n * 32 + (lane & 3) * 2;
#pragma unroll
    for (int mt = 0; mt < 4; mt++)
#pragma unroll
        for (int nt = 0; nt < 4; nt++) {
            float* p0 = C + (size_t)(crow + mt * 16) * Cz + ccol + nt * 8;
            float* p1 = p0 + 8 * Cz;
            *(float2*)p0 = make_float2(acc[mt][nt][0], acc[mt][nt][1]);
            *(float2*)p1 = make_float2(acc[mt][nt][2], acc[mt][nt][3]);
        }
}

// ---------------------------------------------------------------------------
// fp32 -> split bf16
// ---------------------------------------------------------------------------
__global__ void cvt_split4(const float4* __restrict__ s,
                           __nv_bfloat16* __restrict__ hi,
                           __nv_bfloat16* __restrict__ lo, int n4)
{
    int i = blockIdx.x * 256 + threadIdx.x;
    if (i >= n4) return;
    float4 v = s[i];
    __nv_bfloat16 h0 = __float2bfloat16(v.x);
    __nv_bfloat16 h1 = __float2bfloat16(v.y);
    __nv_bfloat16 h2 = __float2bfloat16(v.z);
    __nv_bfloat16 h3 = __float2bfloat16(v.w);
    __nv_bfloat16 l0 = __float2bfloat16(v.x - __bfloat162float(h0));
    __nv_bfloat16 l1 = __float2bfloat16(v.y - __bfloat162float(h1));
    __nv_bfloat16 l2 = __float2bfloat16(v.z - __bfloat162float(h2));
    __nv_bfloat16 l3 = __float2bfloat16(v.w - __bfloat162float(h3));
    ((__nv_bfloat162*)hi)[2 * i]     = __nv_bfloat162(h0, h1);
    ((__nv_bfloat162*)hi)[2 * i + 1] = __nv_bfloat162(h2, h3);
    ((__nv_bfloat162*)lo)[2 * i]     = __nv_bfloat162(l0, l1);
    ((__nv_bfloat162*)lo)[2 * i + 1] = __nv_bfloat162(l2, l3);
}

// ---------------------------------------------------------------------------
// RoPE + RMSNorm(*1.2) + gated ve add; outputs split bf16 q/k/v.
// ---------------------------------------------------------------------------
__device__ __forceinline__ void split_store(__nv_bfloat16* hi, __nv_bfloat16* lo,
                                            size_t idx, float v) {
    __nv_bfloat16 h = __float2bfloat16(v);
    hi[idx] = h;
    lo[idx] = __float2bfloat16(v - __bfloat162float(h));
}

__global__ __launch_bounds__(384) void rope_rms_gate_kernel(
    const float* __restrict__ x, const float* __restrict__ ve,
    const float* __restrict__ cosb, const float* __restrict__ sinb,
    const float* __restrict__ Wg)
{
    const int tok = blockIdx.x;
    const int t = tok & (Tz - 1);
    const int h = threadIdx.x >> 5;
    const int lane = threadIdx.x & 31;
    const size_t base = (size_t)tok * Cz + h * HDz;

    const float cv = cosb[t * 32 + lane];
    const float sv = sinb[t * 32 + lane];

    {
        float x1 = g_q[base + lane], x2 = g_q[base + 32 + lane];
        float r1 = x1 * cv - x2 * sv;
        float r2 = x1 * sv + x2 * cv;
        float ss = r1 * r1 + r2 * r2;
#pragma unroll
        for (int o = 16; o > 0; o >>= 1) ss += __shfl_xor_sync(0xFFFFFFFFu, ss, o);
        float inv = rsqrtf(ss * (1.0f / 64.0f) + 1e-6f) * 1.2f;
        split_store(g_qh, g_ql, base + lane, r1 * inv);
        split_store(g_qh, g_ql, base + 32 + lane, r2 * inv);
    }
    {
        float x1 = g_k[base + lane], x2 = g_k[base + 32 + lane];
        float r1 = x1 * cv - x2 * sv;
        float r2 = x1 * sv + x2 * cv;
        float ss = r1 * r1 + r2 * r2;
#pragma unroll
        for (int o = 16; o > 0; o >>= 1) ss += __shfl_xor_sync(0xFFFFFFFFu, ss, o);
        float inv = rsqrtf(ss * (1.0f / 64.0f) + 1e-6f) * 1.2f;
        split_store(g_kh, g_kl, base + lane, r1 * inv);
        split_store(g_kh, g_kl, base + 32 + lane, r2 * inv);
    }
    {
        float p = (lane < 12) ? x[(size_t)tok * Cz + lane] * Wg[h * 12 + lane] : 0.f;
#pragma unroll
        for (int o = 16; o > 0; o >>= 1) p += __shfl_xor_sync(0xFFFFFFFFu, p, o);
        float gate = 3.0f / (1.0f + __expf(-p));
        float v1 = g_v[base + lane]      + gate * ve[base + lane];
        float v2 = g_v[base + 32 + lane] + gate * ve[base + 32 + lane];
        split_store(g_vh, g_vl, base + lane, v1);
        split_store(g_vh, g_vl, base + 32 + lane, v2);
    }
}

// ---------------------------------------------------------------------------
// MMA flash attention (split bf16), sliding window.
// CTA: 128 threads = 4 warps; 64 queries (16 rows/warp); 64-key tiles.
// smem: Qh,Ql (8KB each) + double-buffered Kh,Kl,Vh,Vl (8KB each) = 80KB.
// ---------------------------------------------------------------------------
#define ATT_Q 0
#define ATT_K 16384
#define ATT_STG 32768
#define ATT_SMEM 81920

__global__ __launch_bounds__(128) void attn_mma(const int* __restrict__ winp)
{
    extern __shared__ __align__(1024) char dsm[];
    const uint32_t sb = smem_u32(dsm);
    const int tid = threadIdx.x;
    const int wid = tid >> 5, lane = tid & 31;
    const int qt0 = blockIdx.x * 64;
    const int h = blockIdx.y;
    const int b = blockIdx.z;
    const int W = *winp;

    const size_t hoff = (size_t)h * HDz;
    const size_t btok = (size_t)b * Tz;

    const int lrow = tid >> 1;       // 0..63 (Q: 64 rows x 2 chunks... see below)
    // loader geometry: 64 rows x 8 chunks of 16B = 512; 128 thr -> 4 iters
    // per-iter: row = (i*128+tid)>>3, c16 = tid&7

    // ---- load Q (both hi/lo) via cp.async, group 0
    {
#pragma unroll
        for (int i = 0; i < 4; i++) {
            int row = (i * 128 + tid) >> 3;
            int c16 = tid & 7;
            uint32_t so = (uint32_t)(row * 128 + c16 * 16) ^ (uint32_t)((row & 7) << 4);
            size_t go = (btok + qt0 + row) * Cz + hoff + c16 * 8;
            CPASYNC16(sb + ATT_Q + so, (const char*)(g_qh + go));
            CPASYNC16(sb + ATT_Q + 8192 + so, (const char*)(g_ql + go));
        }
        asm volatile("cp.async.commit_group;");
    }

    auto issue_kv = [&](int kt0, int s) {
        uint32_t sbase = sb + ATT_K + s * ATT_STG;
#pragma unroll
        for (int i = 0; i < 4; i++) {
            int row = (i * 128 + tid) >> 3;
            int c16 = tid & 7;
            uint32_t so = (uint32_t)(row * 128 + c16 * 16) ^ (uint32_t)((row & 7) << 4);
            size_t go = (btok + kt0 + row) * Cz + hoff + c16 * 8;
            CPASYNC16(sbase + so,         (const char*)(g_kh + go));
            CPASYNC16(sbase + 8192 + so,  (const char*)(g_kl + go));
            CPASYNC16(sbase + 16384 + so, (const char*)(g_vh + go));
            CPASYNC16(sbase + 24576 + so, (const char*)(g_vl + go));
        }
        asm volatile("cp.async.commit_group;");
    };

    int lo = qt0 - W; if (lo < 0) lo = 0;
    const int kt_begin = lo & ~63;
    const int nt = ((qt0 - kt_begin) >> 6) + 1;

    issue_kv(kt_begin, 0);

    // fragment geometry
    const int arow = wid * 16 + (lane & 15);
    const uint32_t aswzQ = (uint32_t)((arow & 7) << 4);
    const uint32_t acol_hi = (uint32_t)((lane >> 4) << 4);

    // rows this thread owns
    const int r0 = qt0 + wid * 16 + (lane >> 2);
    const int r1 = r0 + 8;
    const int cbase = (lane & 3) * 2;

    float m0 = -1e30f, m1 = -1e30f, l0 = 0.f, l1 = 0.f;
    float o[8][4];
#pragma unroll
    for (int j = 0; j < 8; j++)
#pragma unroll
        for (int q = 0; q < 4; q++) o[j][q] = 0.f;

#pragma unroll 1
    for (int it = 0; it < nt; ++it) {
        const int kt0 = kt_begin + it * 64;
        if (it + 1 < nt) {
            issue_kv(kt0 + 64, (it + 1) & 1);
            asm volatile("cp.async.wait_group 1;");
        } else {
            asm volatile("cp.async.wait_group 0;");
        }
        __syncthreads();

        const uint32_t kvb = sb + ATT_K + (it & 1) * ATT_STG;

        // ---- S = Q K^T (split, 3 passes folded)
        float sa[8][4];
#pragma unroll
        for (int j = 0; j < 8; j++)
#pragma unroll
            for (int q = 0; q < 4; q++) sa[j][q] = 0.f;

#pragma unroll
        for (int kk = 0; kk < 4; ++kk) {
            uint32_t ah[4], al[4];
            {
                uint32_t bc = ((uint32_t)(kk * 32) + acol_hi) ^ aswzQ;
                uint32_t ra = sb + ATT_Q + (uint32_t)(arow * 128) + bc;
                LDSM4(ah, ra);
                LDSM4(al, ra + 8192);
            }
            // K frags: 4 x4-loads cover 8 n-steps (hi), 4 more (lo)
            uint32_t kh[4][4], kl[4][4];
            {
                const int grp = lane >> 3;
                const int krow_off = (grp >> 1) * 8 + (lane & 7);
                const uint32_t bc_off = (uint32_t)(kk * 32 + (grp & 1) * 16);
#pragma unroll
                for (int p = 0; p < 4; p++) {
                    int krow = p * 16 + krow_off;
                    uint32_t so = (uint32_t)(krow * 128) + (bc_off ^ ((uint32_t)(krow & 7) << 4));
                    LDSM4(kh[p], kvb + so);
                    LDSM4(kl[p], kvb + 8192 + so);
                }
            }
#pragma unroll
            for (int p = 0; p < 4; p++) {
                MMA16816B(sa[2 * p],     ah, kh[p][0], kh[p][1]);
                MMA16816B(sa[2 * p + 1], ah, kh[p][2], kh[p][3]);
                MMA16816B(sa[2 * p],     ah, kl[p][0], kl[p][1]);
                MMA16816B(sa[2 * p + 1], ah, kl[p][2], kl[p][3]);
                MMA16816B(sa[2 * p],     al, kh[p][0], kh[p][1]);
                MMA16816B(sa[2 * p + 1], al, kh[p][2], kh[p][3]);
            }
        }

        // ---- masked online softmax
        float rm0 = -1e30f, rm1 = -1e30f;
#pragma unroll
        for (int j = 0; j < 8; j++) {
            const int c0 = kt0 + j * 8 + cbase;
            const int c1 = c0 + 1;
            bool ok00 = (c0 <= r0) && (r0 - c0 <= W);
            bool ok01 = (c1 <= r0) && (r0 - c1 <= W);
            bool ok10 = (c0 <= r1) && (r1 - c0 <= W);
            bool ok11 = (c1 <= r1) && (r1 - c1 <= W);
            sa[j][0] = ok00 ? sa[j][0] * 0.125f : -1e30f;
            sa[j][1] = ok01 ? sa[j][1] * 0.125f : -1e30f;
            sa[j][2] = ok10 ? sa[j][2] * 0.125f : -1e30f;
            sa[j][3] = ok11 ? sa[j][3] * 0.125f : -1e30f;
            rm0 = fmaxf(rm0, fmaxf(sa[j][0], sa[j][1]));
            rm1 = fmaxf(rm1, fmaxf(sa[j][2], sa[j][3]));
        }
#pragma unroll
        for (int off = 1; off <= 2; off <<= 1) {
            rm0 = fmaxf(rm0, __shfl_xor_sync(0xFFFFFFFFu, rm0, off));
            rm1 = fmaxf(rm1, __shfl_xor_sync(0xFFFFFFFFu, rm1, off));
        }
        const float mn0 = fmaxf(m0, rm0);
        const float mn1 = fmaxf(m1, rm1);
        const float corr0 = __expf(m0 - mn0);
        const float corr1 = __expf(m1 - mn1);
        m0 = mn0; m1 = mn1;

        float rs0 = 0.f, rs1 = 0.f;
        uint32_t aph[4][4], apl[4][4];
#pragma unroll
        for (int p = 0; p < 4; p++) {
            float pv[2][4];  // [jl][q]
#pragma unroll
            for (int jl = 0; jl < 2; jl++) {
                const int j = 2 * p + jl;
                pv[jl][0] = (sa[j][0] > -1e29f) ? __expf(sa[j][0] - mn0) : 0.f;
                pv[jl][1] = (sa[j][1] > -1e29f) ? __expf(sa[j][1] - mn0) : 0.f;
                pv[jl][2] = (sa[j][2] > -1e29f) ? __expf(sa[j][2] - mn1) : 0.f;
                pv[jl][3] = (sa[j][3] > -1e29f) ? __expf(sa[j][3] - mn1) : 0.f;
                rs0 += pv[jl][0] + pv[jl][1];
                rs1 += pv[jl][2] + pv[jl][3];
            }
            // pack into A-frag layout: a0=(r0,c..c+1 of j=2p), a1=(r1,..), a2/a3 = j=2p+1
#pragma unroll
            for (int jl = 0; jl < 2; jl++) {
                uint32_t hi01 = pack_bf16x2(pv[jl][0], pv[jl][1]);
                uint32_t hi23 = pack_bf16x2(pv[jl][2], pv[jl][3]);
                __nv_bfloat162* h01 = (__nv_bfloat162*)&hi01;
                __nv_bfloat162* h23 = (__nv_bfloat162*)&hi23;
                uint32_t lo01 = pack_bf16x2(pv[jl][0] - __bfloat162float(h01->x),
                                            pv[jl][1] - __bfloat162float(h01->y));
                uint32_t lo23 = pack_bf16x2(pv[jl][2] - __bfloat162float(h23->x),
                                            pv[jl][3] - __bfloat162float(h23->y));
                aph[p][2 * jl + 0] = hi01;  // wait: layout a[0]=r0 j0, a[1]=r1 j0, a[2]=r0 j1, a[3]=r1 j1
                aph[p][2 * jl + 1] = hi23;
                apl[p][2 * jl + 0] = lo01;
                apl[p][2 * jl + 1] = lo23;
            }
        }
#pragma unroll
        for (int off = 1; off <= 2; off <<= 1) {
            rs0 += __shfl_xor_sync(0xFFFFFFFFu, rs0, off);
            rs1 += __shfl_xor_sync(0xFFFFFFFFu, rs1, off);
        }
        l0 = l0 * corr0 + rs0;
        l1 = l1 * corr1 + rs1;

        // rescale O
#pragma unroll
        for (int j = 0; j < 8; j++) {
            o[j][0] *= corr0; o[j][1] *= corr0;
            o[j][2] *= corr1; o[j][3] *= corr1;
        }

        // ---- O += P V (split)
        const uint32_t vbase = kvb + 16384;
        {
            const int vrow_off = lane & 15;
            const uint32_t vcol_hi = (uint32_t)((lane >> 4) << 4);
#pragma unroll
            for (int kk = 0; kk < 4; ++kk) {
                uint32_t vh[4][4], vl[4][4];
#pragma unroll
                for (int t = 0; t < 4; t++) {
                    int vrow = kk * 16 + vrow_off;
                    uint32_t bc = ((uint32_t)(t * 32) + vcol_hi) ^ ((uint32_t)(vrow & 7) << 4);
                    uint32_t so = (uint32_t)(vrow * 128) + bc;
                    LDSM4T(vh[t], vbase + so);
                    LDSM4T(vl[t], vbase + 8192 + so);
                }
#pragma unroll
                for (int t = 0; t < 4; t++) {
                    MMA16816B(o[2 * t],     aph[kk], vh[t][0], vh[t][1]);
                    MMA16816B(o[2 * t + 1], aph[kk], vh[t][2], vh[t][3]);
                    MMA16816B(o[2 * t],     aph[kk], vl[t][0], vl[t][1]);
                    MMA16816B(o[2 * t + 1], aph[kk], vl[t][2], vl[t][3]);
                    MMA16816B(o[2 * t],     apl[kk], vh[t][0], vh[t][1]);
                    MMA16816B(o[2 * t + 1], apl[kk], vh[t][2], vh[t][3]);
                }
            }
        }
        __syncthreads();
    }

    // epilogue
    const float i0 = 1.0f / l0;
    const float i1 = 1.0f / l1;
#pragma unroll
    for (int j = 0; j < 8; j++) {
        size_t col = hoff + j * 8 + cbase;
        float* p0 = g_y + (btok + r0) * Cz + col;
        float* p1 = g_y + (btok + r1) * Cz + col;
        *(float2*)p0 = make_float2(o[j][0] * i0, o[j][1] * i0);
        *(float2*)p1 = make_float2(o[j][2] * i1, o[j][3] * i1);
    }
}

// ---------------------------------------------------------------------------
extern "C" void kernel_launch(void* const* d_in, const int* in_sizes, int n_in,
                              void* d_out, int out_size)
{
    const float* x     = (const float*)d_in[0];
    const float* ve    = (const float*)d_in[1];
    const float* cosb  = (const float*)d_in[2];
    const float* sinb  = (const float*)d_in[3];
    const float* Wq    = (const float*)d_in[4];
    const float* Wk    = (const float*)d_in[5];
    const float* Wv    = (const float*)d_in[6];
    const float* Wproj = (const float*)d_in[7];
    const float* Wg    = (const float*)d_in[8];
    const int*   win   = (const int*)d_in[9];
    float* out = (float*)d_out;

    float *qp, *kp, *vp, *yp;
    __nv_bfloat16 *xhi, *xlo, *yhi, *ylo, *whi, *wlo;
    cudaGetSymbolAddress((void**)&qp, g_q);
    cudaGetSymbolAddress((void**)&kp, g_k);
    cudaGetSymbolAddress((void**)&vp, g_v);
    cudaGetSymbolAddress((void**)&yp, g_y);
    cudaGetSymbolAddress((void**)&xhi, g_xhi);
    cudaGetSymbolAddress((void**)&xlo, g_xlo);
    cudaGetSymbolAddress((void**)&yhi, g_yhi);
    cudaGetSymbolAddress((void**)&ylo, g_ylo);
    cudaGetSymbolAddress((void**)&whi, g_whi);
    cudaGetSymbolAddress((void**)&wlo, g_wlo);

    const int WW = Cz * Cz;
    const int n4x = TOKz * Cz / 4;
    const int n4w = WW / 4;

    cvt_split4<<<(n4x + 255) / 256, 256>>>((const float4*)x, xhi, xlo, n4x);
    cvt_split4<<<(n4w + 255) / 256, 256>>>((const float4*)Wq,    whi + 0 * WW, wlo + 0 * WW, n4w);
    cvt_split4<<<(n4w + 255) / 256, 256>>>((const float4*)Wk,    whi + 1 * WW, wlo + 1 * WW, n4w);
    cvt_split4<<<(n4w + 255) / 256, 256>>>((const float4*)Wv,    whi + 2 * WW, wlo + 2 * WW, n4w);
    cvt_split4<<<(n4w + 255) / 256, 256>>>((const float4*)Wproj, whi + 3 * WW, wlo + 3 * WW, n4w);

    cudaFuncSetAttribute(gemm_mma, cudaFuncAttributeMaxDynamicSharedMemorySize, GSMEM);
    dim3 gg(Cz / 128, TOKz / 128);
    gemm_mma<<<gg, 256, GSMEM>>>(xhi, xlo, whi + 0 * WW, wlo + 0 * WW, qp);
    gemm_mma<<<gg, 256, GSMEM>>>(xhi, xlo, whi + 1 * WW, wlo + 1 * WW, kp);
    gemm_mma<<<gg, 256, GSMEM>>>(xhi, xlo, whi + 2 * WW, wlo + 2 * WW, vp);

    rope_rms_gate_kernel<<<TOKz, 384>>>(x, ve, cosb, sinb, Wg);

    cudaFuncSetAttribute(attn_mma, cudaFuncAttributeMaxDynamicSharedMemorySize, ATT_SMEM);
    attn_mma<<<dim3(Tz / 64, NHz, Bz), 128, ATT_SMEM>>>(win);

    cvt_split4<<<(n4x + 255) / 256, 256>>>((const float4*)yp, yhi, ylo, n4x);
    gemm_mma<<<gg, 256, GSMEM>>>(yhi, ylo, whi + 3 * WW, wlo + 3 * WW, out);
}

// round 5
// speedup vs baseline: 5.3596x; 1.4151x over previous
#include <cuda_runtime.h>
#include <cuda_fp16.h>
#include <math.h>
#include <stdint.h>

// Problem constants
#define Bz 4
#define Tz 2048
#define Cz 768
#define NHz 12
#define HDz 64
#define TOKz (Bz * Tz)   // 8192
#define QKVN 2304        // fused q|k|v output width

// fp32 intermediate: fused qkv GEMM output
__device__ float g_qkv[TOKz * QKVN];

// split-fp16 operands
__device__ __half g_xhi[TOKz * Cz];
__device__ __half g_xlo[TOKz * Cz];
__device__ __half g_whi[4 * Cz * Cz];   // [Wq;Wk;Wv;Wproj] hi parts

// attention operands (q needs hi+lo; k,v hi only)
__device__ __half g_qh[TOKz * Cz];
__device__ __half g_ql[TOKz * Cz];
__device__ __half g_kh[TOKz * Cz];
__device__ __half g_vh[TOKz * Cz];

// attention output, split fp16 (A operand of proj GEMM)
__device__ __half g_yh[TOKz * Cz];
__device__ __half g_yl[TOKz * Cz];

// ---------------------------------------------------------------------------
// Helpers
// ---------------------------------------------------------------------------
__device__ __forceinline__ uint32_t smem_u32(const void* p) {
    uint32_t a;
    asm("{ .reg .u64 t; cvta.to.shared.u64 t, %1; cvt.u32.u64 %0, t; }"
        : "=r"(a) : "l"(p));
    return a;
}

#define LDSM4(r, addr)                                                        \
    asm volatile("ldmatrix.sync.aligned.m8n8.x4.shared.b16 {%0,%1,%2,%3}, [%4];" \
                 : "=r"((r)[0]), "=r"((r)[1]), "=r"((r)[2]), "=r"((r)[3])     \
                 : "r"(addr))

#define LDSM4T(r, addr)                                                       \
    asm volatile("ldmatrix.sync.aligned.m8n8.x4.trans.shared.b16 {%0,%1,%2,%3}, [%4];" \
                 : "=r"((r)[0]), "=r"((r)[1]), "=r"((r)[2]), "=r"((r)[3])     \
                 : "r"(addr))

#define LDSM2(r, addr)                                                        \
    asm volatile("ldmatrix.sync.aligned.m8n8.x2.shared.b16 {%0,%1}, [%2];"    \
                 : "=r"((r)[0]), "=r"((r)[1]) : "r"(addr))

#define MMAH(c, a, b0, b1)                                                    \
    asm volatile("mma.sync.aligned.m16n8k16.row.col.f32.f16.f16.f32 "        \
                 "{%0,%1,%2,%3}, {%4,%5,%6,%7}, {%8,%9}, {%0,%1,%2,%3};"     \
                 : "+f"((c)[0]), "+f"((c)[1]), "+f"((c)[2]), "+f"((c)[3])    \
                 : "r"((a)[0]), "r"((a)[1]), "r"((a)[2]), "r"((a)[3]),       \
                   "r"(b0), "r"(b1))

#define CPASYNC16(s, g)                                                       \
    asm volatile("cp.async.ca.shared.global [%0], [%1], 16;" :: "r"(s), "l"(g))

__device__ __forceinline__ uint32_t packh2(float a, float b) {
    __half2 t = __floats2half2_rn(a, b);
    return *(uint32_t*)&t;
}

// ---------------------------------------------------------------------------
// Split-fp16 2-pass HMMA GEMM (NT): C[M x N] = A * B^T, K=768.
// acc = Ahi*Bhi + Alo*Bhi  (B lo dropped; ~2^-12 rel).
// Block 128x128, K chunks of 64, 8 warps, warp tile 64x32, double buffer.
// ---------------------------------------------------------------------------
#define GK 768
#define NCH 12
#define ARR 16384                 // one 128x64 fp16 array (swizzled)
#define STG3 (3 * ARR)            // Ahi, Alo, Bhi = 48 KB
#define GSMEM (2 * STG3)          // 96 KB

__global__ __launch_bounds__(256) void gemm_mma(
    const __half* __restrict__ Ahi, const __half* __restrict__ Alo,
    const __half* __restrict__ Bh, float* __restrict__ C, int ldc)
{
    extern __shared__ __align__(1024) char dsm[];
    const uint32_t sb = smem_u32(dsm);
    const int tid = threadIdx.x;
    const int wid = tid >> 5, lane = tid & 31;
    const int bm = blockIdx.y << 7;
    const int bn = blockIdx.x << 7;
    const int warp_m = wid >> 2;
    const int warp_n = wid & 3;

    const __half* gA0 = Ahi + (size_t)bm * GK;
    const __half* gA1 = Alo + (size_t)bm * GK;
    const __half* gB  = Bh  + (size_t)bn * GK;

    const int lrow = tid >> 3;
    const int lc16 = tid & 7;

    float acc[4][4][4];
#pragma unroll
    for (int i = 0; i < 4; i++)
#pragma unroll
        for (int j = 0; j < 4; j++)
#pragma unroll
            for (int k = 0; k < 4; k++) acc[i][j][k] = 0.f;

    auto issue = [&](int c, int s) {
        uint32_t sbase = sb + s * STG3;
#pragma unroll
        for (int i = 0; i < 4; i++) {
            int row = lrow + i * 32;
            uint32_t so = (uint32_t)(row * 128 + lc16 * 16) ^ (uint32_t)((row & 7) << 4);
            size_t go = (size_t)row * GK + c * 64 + lc16 * 8;
            CPASYNC16(sbase + 0 * ARR + so, (const char*)(gA0 + go));
            CPASYNC16(sbase + 1 * ARR + so, (const char*)(gA1 + go));
            CPASYNC16(sbase + 2 * ARR + so, (const char*)(gB + go));
        }
        asm volatile("cp.async.commit_group;");
    };

    issue(0, 0);

    const uint32_t aswz = (uint32_t)((lane & 7) << 4);
    const int arow = warp_m * 64 + (lane & 15);
    const int brow = warp_n * 32 + (lane & 7);
    const uint32_t akhi = (uint32_t)((lane >> 4) << 4);
    const uint32_t bkhi = (uint32_t)(((lane >> 3) & 1) << 4);

#pragma unroll 1
    for (int c = 0; c < NCH; ++c) {
        if (c + 1 < NCH) {
            issue(c + 1, (c + 1) & 1);
            asm volatile("cp.async.wait_group 1;");
        } else {
            asm volatile("cp.async.wait_group 0;");
        }
        __syncthreads();

        const uint32_t sbase = sb + (c & 1) * STG3;
#pragma unroll
        for (int ks = 0; ks < 4; ++ks) {
            uint32_t ah[4][4], al[4][4], bh[4][2];
            const uint32_t ak = ((uint32_t)(ks * 32) + akhi) ^ aswz;
            const uint32_t bk = ((uint32_t)(ks * 32) + bkhi) ^ aswz;
#pragma unroll
            for (int mt = 0; mt < 4; mt++) {
                uint32_t ra = sbase + (uint32_t)((arow + mt * 16) * 128) + ak;
                LDSM4(ah[mt], ra);
                LDSM4(al[mt], ra + ARR);
            }
#pragma unroll
            for (int nt = 0; nt < 4; nt++) {
                uint32_t rb = sbase + 2 * ARR + (uint32_t)((brow + nt * 8) * 128) + bk;
                LDSM2(bh[nt], rb);
            }
#pragma unroll
            for (int mt = 0; mt < 4; mt++)
#pragma unroll
                for (int nt = 0; nt < 4; nt++) {
                    MMAH(acc[mt][nt], ah[mt], bh[nt][0], bh[nt][1]);
                    MMAH(acc[mt][nt], al[mt], bh[nt][0], bh[nt][1]);
                }
        }
        __syncthreads();
    }

    const int crow = bm + warp_m * 64 + (lane >> 2);
    const int ccol = bn + warp_n * 32 + (lane & 3) * 2;
#pragma unroll
    for (int mt = 0; mt < 4; mt++)
#pragma unroll
        for (int nt = 0; nt < 4; nt++) {
            float* p0 = C + (size_t)(crow + mt * 16) * ldc + ccol + nt * 8;
            float* p1 = p0 + 8 * ldc;
            *(float2*)p0 = make_float2(acc[mt][nt][0], acc[mt][nt][1]);
            *(float2*)p1 = make_float2(acc[mt][nt][2], acc[mt][nt][3]);
        }
}

// ---------------------------------------------------------------------------
// fp32 -> split fp16 (hi+lo) / hi-only converters
// ---------------------------------------------------------------------------
__global__ void cvt_split4(const float4* __restrict__ s,
                           __half* __restrict__ hi, __half* __restrict__ lo, int n4)
{
    int i = blockIdx.x * 256 + threadIdx.x;
    if (i >= n4) return;
    float4 v = s[i];
    __half h0 = __float2half(v.x), h1 = __float2half(v.y);
    __half h2 = __float2half(v.z), h3 = __float2half(v.w);
    ((__half2*)hi)[2 * i]     = __half2(h0, h1);
    ((__half2*)hi)[2 * i + 1] = __half2(h2, h3);
    ((__half2*)lo)[2 * i]     = __half2(__float2half(v.x - __half2float(h0)),
                                        __float2half(v.y - __half2float(h1)));
    ((__half2*)lo)[2 * i + 1] = __half2(__float2half(v.z - __half2float(h2)),
                                        __float2half(v.w - __half2float(h3)));
}

__global__ void cvt_hi4(const float4* __restrict__ s, __half* __restrict__ hi, int n4)
{
    int i = blockIdx.x * 256 + threadIdx.x;
    if (i >= n4) return;
    float4 v = s[i];
    ((__half2*)hi)[2 * i]     = __half2(__float2half(v.x), __float2half(v.y));
    ((__half2*)hi)[2 * i + 1] = __half2(__float2half(v.z), __float2half(v.w));
}

// ---------------------------------------------------------------------------
// RoPE + RMSNorm(*1.2) + gated ve add; reads fused qkv, writes split q + hi k,v
// ---------------------------------------------------------------------------
__global__ __launch_bounds__(384) void rope_rms_gate_kernel(
    const float* __restrict__ x, const float* __restrict__ ve,
    const float* __restrict__ cosb, const float* __restrict__ sinb,
    const float* __restrict__ Wg)
{
    const int tok = blockIdx.x;
    const int t = tok & (Tz - 1);
    const int h = threadIdx.x >> 5;
    const int lane = threadIdx.x & 31;
    const size_t qkvbase = (size_t)tok * QKVN + h * HDz;
    const size_t base = (size_t)tok * Cz + h * HDz;

    const float cv = cosb[t * 32 + lane];
    const float sv = sinb[t * 32 + lane];

    {   // q: rope + rms, split hi/lo
        float x1 = g_qkv[qkvbase + lane], x2 = g_qkv[qkvbase + 32 + lane];
        float r1 = x1 * cv - x2 * sv;
        float r2 = x1 * sv + x2 * cv;
        float ss = r1 * r1 + r2 * r2;
#pragma unroll
        for (int o = 16; o > 0; o >>= 1) ss += __shfl_xor_sync(0xFFFFFFFFu, ss, o);
        float inv = rsqrtf(ss * (1.0f / 64.0f) + 1e-6f) * 1.2f;
        float q1 = r1 * inv, q2 = r2 * inv;
        __half h1 = __float2half(q1), h2 = __float2half(q2);
        g_qh[base + lane] = h1;
        g_qh[base + 32 + lane] = h2;
        g_ql[base + lane] = __float2half(q1 - __half2float(h1));
        g_ql[base + 32 + lane] = __float2half(q2 - __half2float(h2));
    }
    {   // k: rope + rms, hi only
        float x1 = g_qkv[qkvbase + Cz + lane], x2 = g_qkv[qkvbase + Cz + 32 + lane];
        float r1 = x1 * cv - x2 * sv;
        float r2 = x1 * sv + x2 * cv;
        float ss = r1 * r1 + r2 * r2;
#pragma unroll
        for (int o = 16; o > 0; o >>= 1) ss += __shfl_xor_sync(0xFFFFFFFFu, ss, o);
        float inv = rsqrtf(ss * (1.0f / 64.0f) + 1e-6f) * 1.2f;
        g_kh[base + lane] = __float2half(r1 * inv);
        g_kh[base + 32 + lane] = __float2half(r2 * inv);
    }
    {   // v: gated ve add, hi only
        float p = (lane < 12) ? x[(size_t)tok * Cz + lane] * Wg[h * 12 + lane] : 0.f;
#pragma unroll
        for (int o = 16; o > 0; o >>= 1) p += __shfl_xor_sync(0xFFFFFFFFu, p, o);
        float gate = 3.0f / (1.0f + __expf(-p));
        float v1 = g_qkv[qkvbase + 2 * Cz + lane]      + gate * ve[base + lane];
        float v2 = g_qkv[qkvbase + 2 * Cz + 32 + lane] + gate * ve[base + 32 + lane];
        g_vh[base + lane] = __float2half(v1);
        g_vh[base + 32 + lane] = __float2half(v2);
    }
}

// ---------------------------------------------------------------------------
// MMA flash attention (split fp16, 2-pass), sliding window.
// CTA: 128 threads = 4 warps; 64 queries; 64-key tiles.
// smem: qh,ql (16KB) + double-buffered kh,vh (16KB each) = 48KB.
// ---------------------------------------------------------------------------
#define ATT_Q 0
#define ATT_K 16384
#define ATT_STG 16384
#define ATT_SMEM 49152

__global__ __launch_bounds__(128) void attn_mma(const int* __restrict__ winp)
{
    extern __shared__ __align__(1024) char dsm[];
    const uint32_t sb = smem_u32(dsm);
    const int tid = threadIdx.x;
    const int wid = tid >> 5, lane = tid & 31;
    const int qt0 = blockIdx.x * 64;
    const int h = blockIdx.y;
    const int b = blockIdx.z;
    const int W = *winp;

    const size_t hoff = (size_t)h * HDz;
    const size_t btok = (size_t)b * Tz;

    // ---- load Q (hi+lo)
    {
#pragma unroll
        for (int i = 0; i < 4; i++) {
            int row = (i * 128 + tid) >> 3;
            int c16 = tid & 7;
            uint32_t so = (uint32_t)(row * 128 + c16 * 16) ^ (uint32_t)((row & 7) << 4);
            size_t go = (btok + qt0 + row) * Cz + hoff + c16 * 8;
            CPASYNC16(sb + ATT_Q + so, (const char*)(g_qh + go));
            CPASYNC16(sb + ATT_Q + 8192 + so, (const char*)(g_ql + go));
        }
        asm volatile("cp.async.commit_group;");
    }

    auto issue_kv = [&](int kt0, int s) {
        uint32_t sbase = sb + ATT_K + s * ATT_STG;
#pragma unroll
        for (int i = 0; i < 4; i++) {
            int row = (i * 128 + tid) >> 3;
            int c16 = tid & 7;
            uint32_t so = (uint32_t)(row * 128 + c16 * 16) ^ (uint32_t)((row & 7) << 4);
            size_t go = (btok + kt0 + row) * Cz + hoff + c16 * 8;
            CPASYNC16(sbase + so,        (const char*)(g_kh + go));
            CPASYNC16(sbase + 8192 + so, (const char*)(g_vh + go));
        }
        asm volatile("cp.async.commit_group;");
    };

    int lo = qt0 - W; if (lo < 0) lo = 0;
    const int kt_begin = lo & ~63;
    const int nt = ((qt0 - kt_begin) >> 6) + 1;

    issue_kv(kt_begin, 0);

    const int arow = wid * 16 + (lane & 15);
    const uint32_t aswzQ = (uint32_t)((arow & 7) << 4);
    const uint32_t acol_hi = (uint32_t)((lane >> 4) << 4);

    const int r0 = qt0 + wid * 16 + (lane >> 2);
    const int r1 = r0 + 8;
    const int cbase = (lane & 3) * 2;

    float m0 = -1e30f, m1 = -1e30f, l0 = 0.f, l1 = 0.f;
    float o[8][4];
#pragma unroll
    for (int j = 0; j < 8; j++)
#pragma unroll
        for (int q = 0; q < 4; q++) o[j][q] = 0.f;

#pragma unroll 1
    for (int it = 0; it < nt; ++it) {
        const int kt0 = kt_begin + it * 64;
        if (it + 1 < nt) {
            issue_kv(kt0 + 64, (it + 1) & 1);
            asm volatile("cp.async.wait_group 1;");
        } else {
            asm volatile("cp.async.wait_group 0;");
        }
        __syncthreads();

        const uint32_t kvb = sb + ATT_K + (it & 1) * ATT_STG;

        // ---- S = Q K^T (2-pass)
        float sa[8][4];
#pragma unroll
        for (int j = 0; j < 8; j++)
#pragma unroll
            for (int q = 0; q < 4; q++) sa[j][q] = 0.f;

#pragma unroll
        for (int kk = 0; kk < 4; ++kk) {
            uint32_t ah[4], al[4];
            {
                uint32_t bc = ((uint32_t)(kk * 32) + acol_hi) ^ aswzQ;
                uint32_t ra = sb + ATT_Q + (uint32_t)(arow * 128) + bc;
                LDSM4(ah, ra);
                LDSM4(al, ra + 8192);
            }
            uint32_t kh[4][4];
            {
                const int grp = lane >> 3;
                const int krow_off = (grp >> 1) * 8 + (lane & 7);
                const uint32_t bc_off = (uint32_t)(kk * 32 + (grp & 1) * 16);
#pragma unroll
                for (int p = 0; p < 4; p++) {
                    int krow = p * 16 + krow_off;
                    uint32_t so = (uint32_t)(krow * 128) + (bc_off ^ ((uint32_t)(krow & 7) << 4));
                    LDSM4(kh[p], kvb + so);
                }
            }
#pragma unroll
            for (int p = 0; p < 4; p++) {
                MMAH(sa[2 * p],     ah, kh[p][0], kh[p][1]);
                MMAH(sa[2 * p + 1], ah, kh[p][2], kh[p][3]);
                MMAH(sa[2 * p],     al, kh[p][0], kh[p][1]);
                MMAH(sa[2 * p + 1], al, kh[p][2], kh[p][3]);
            }
        }

        // ---- masked online softmax
        float rm0 = -1e30f, rm1 = -1e30f;
#pragma unroll
        for (int j = 0; j < 8; j++) {
            const int c0 = kt0 + j * 8 + cbase;
            const int c1 = c0 + 1;
            bool ok00 = (c0 <= r0) && (r0 - c0 <= W);
            bool ok01 = (c1 <= r0) && (r0 - c1 <= W);
            bool ok10 = (c0 <= r1) && (r1 - c0 <= W);
            bool ok11 = (c1 <= r1) && (r1 - c1 <= W);
            sa[j][0] = ok00 ? sa[j][0] * 0.125f : -1e30f;
            sa[j][1] = ok01 ? sa[j][1] * 0.125f : -1e30f;
            sa[j][2] = ok10 ? sa[j][2] * 0.125f : -1e30f;
            sa[j][3] = ok11 ? sa[j][3] * 0.125f : -1e30f;
            rm0 = fmaxf(rm0, fmaxf(sa[j][0], sa[j][1]));
            rm1 = fmaxf(rm1, fmaxf(sa[j][2], sa[j][3]));
        }
#pragma unroll
        for (int off = 1; off <= 2; off <<= 1) {
            rm0 = fmaxf(rm0, __shfl_xor_sync(0xFFFFFFFFu, rm0, off));
            rm1 = fmaxf(rm1, __shfl_xor_sync(0xFFFFFFFFu, rm1, off));
        }
        const float mn0 = fmaxf(m0, rm0);
        const float mn1 = fmaxf(m1, rm1);
        const float corr0 = __expf(m0 - mn0);
        const float corr1 = __expf(m1 - mn1);
        m0 = mn0; m1 = mn1;

        float rs0 = 0.f, rs1 = 0.f;
        uint32_t aph[4][4], apl[4][4];
#pragma unroll
        for (int p = 0; p < 4; p++) {
#pragma unroll
            for (int jl = 0; jl < 2; jl++) {
                const int j = 2 * p + jl;
                float p0 = (sa[j][0] > -1e29f) ? __expf(sa[j][0] - mn0) : 0.f;
                float p1 = (sa[j][1] > -1e29f) ? __expf(sa[j][1] - mn0) : 0.f;
                float p2 = (sa[j][2] > -1e29f) ? __expf(sa[j][2] - mn1) : 0.f;
                float p3 = (sa[j][3] > -1e29f) ? __expf(sa[j][3] - mn1) : 0.f;
                rs0 += p0 + p1;
                rs1 += p2 + p3;
                uint32_t hi01 = packh2(p0, p1);
                uint32_t hi23 = packh2(p2, p3);
                __half2 h01 = *(__half2*)&hi01;
                __half2 h23 = *(__half2*)&hi23;
                aph[p][2 * jl + 0] = hi01;
                aph[p][2 * jl + 1] = hi23;
                apl[p][2 * jl + 0] = packh2(p0 - __half2float(h01.x),
                                            p1 - __half2float(h01.y));
                apl[p][2 * jl + 1] = packh2(p2 - __half2float(h23.x),
                                            p3 - __half2float(h23.y));
            }
        }
#pragma unroll
        for (int off = 1; off <= 2; off <<= 1) {
            rs0 += __shfl_xor_sync(0xFFFFFFFFu, rs0, off);
            rs1 += __shfl_xor_sync(0xFFFFFFFFu, rs1, off);
        }
        l0 = l0 * corr0 + rs0;
        l1 = l1 * corr1 + rs1;

#pragma unroll
        for (int j = 0; j < 8; j++) {
            o[j][0] *= corr0; o[j][1] *= corr0;
            o[j][2] *= corr1; o[j][3] *= corr1;
        }

        // ---- O += P V (2-pass)
        const uint32_t vbase = kvb + 8192;
        {
            const int vrow_off = lane & 15;
            const uint32_t vcol_hi = (uint32_t)((lane >> 4) << 4);
#pragma unroll
            for (int kk = 0; kk < 4; ++kk) {
                uint32_t vh[4][4];
#pragma unroll
                for (int t = 0; t < 4; t++) {
                    int vrow = kk * 16 + vrow_off;
                    uint32_t bc = ((uint32_t)(t * 32) + vcol_hi) ^ ((uint32_t)(vrow & 7) << 4);
                    LDSM4T(vh[t], vbase + (uint32_t)(vrow * 128) + bc);
                }
#pragma unroll
                for (int t = 0; t < 4; t++) {
                    MMAH(o[2 * t],     aph[kk], vh[t][0], vh[t][1]);
                    MMAH(o[2 * t + 1], aph[kk], vh[t][2], vh[t][3]);
                    MMAH(o[2 * t],     apl[kk], vh[t][0], vh[t][1]);
                    MMAH(o[2 * t + 1], apl[kk], vh[t][2], vh[t][3]);
                }
            }
        }
        __syncthreads();
    }

    // epilogue: normalize, write split-fp16 y
    const float i0 = 1.0f / l0;
    const float i1 = 1.0f / l1;
#pragma unroll
    for (int j = 0; j < 8; j++) {
        size_t col = hoff + j * 8 + cbase;
        size_t idx0 = (btok + r0) * Cz + col;
        size_t idx1 = (btok + r1) * Cz + col;
        float y00 = o[j][0] * i0, y01 = o[j][1] * i0;
        float y10 = o[j][2] * i1, y11 = o[j][3] * i1;
        __half2 h0 = __floats2half2_rn(y00, y01);
        __half2 h1 = __floats2half2_rn(y10, y11);
        *(__half2*)(g_yh + idx0) = h0;
        *(__half2*)(g_yh + idx1) = h1;
        *(__half2*)(g_yl + idx0) = __floats2half2_rn(y00 - __half2float(h0.x),
                                                     y01 - __half2float(h0.y));
        *(__half2*)(g_yl + idx1) = __floats2half2_rn(y10 - __half2float(h1.x),
                                                     y11 - __half2float(h1.y));
    }
}

// ---------------------------------------------------------------------------
extern "C" void kernel_launch(void* const* d_in, const int* in_sizes, int n_in,
                              void* d_out, int out_size)
{
    const float* x     = (const float*)d_in[0];
    const float* ve    = (const float*)d_in[1];
    const float* cosb  = (const float*)d_in[2];
    const float* sinb  = (const float*)d_in[3];
    const float* Wq    = (const float*)d_in[4];
    const float* Wk    = (const float*)d_in[5];
    const float* Wv    = (const float*)d_in[6];
    const float* Wproj = (const float*)d_in[7];
    const float* Wg    = (const float*)d_in[8];
    const int*   win   = (const int*)d_in[9];
    float* out = (float*)d_out;

    float* qkvp;
    __half *xhi, *xlo, *whi, *yh, *yl;
    cudaGetSymbolAddress((void**)&qkvp, g_qkv);
    cudaGetSymbolAddress((void**)&xhi, g_xhi);
    cudaGetSymbolAddress((void**)&xlo, g_xlo);
    cudaGetSymbolAddress((void**)&whi, g_whi);
    cudaGetSymbolAddress((void**)&yh, g_yh);
    cudaGetSymbolAddress((void**)&yl, g_yl);

    const int WW = Cz * Cz;
    const int n4x = TOKz * Cz / 4;
    const int n4w = WW / 4;

    cvt_split4<<<(n4x + 255) / 256, 256>>>((const float4*)x, xhi, xlo, n4x);
    cvt_hi4<<<(n4w + 255) / 256, 256>>>((const float4*)Wq,    whi + 0 * WW, n4w);
    cvt_hi4<<<(n4w + 255) / 256, 256>>>((const float4*)Wk,    whi + 1 * WW, n4w);
    cvt_hi4<<<(n4w + 255) / 256, 256>>>((const float4*)Wv,    whi + 2 * WW, n4w);
    cvt_hi4<<<(n4w + 255) / 256, 256>>>((const float4*)Wproj, whi + 3 * WW, n4w);

    cudaFuncSetAttribute(gemm_mma, cudaFuncAttributeMaxDynamicSharedMemorySize, GSMEM);

    // fused QKV GEMM: B = [Wq;Wk;Wv] hi, N = 2304
    gemm_mma<<<dim3(QKVN / 128, TOKz / 128), 256, GSMEM>>>(xhi, xlo, whi, qkvp, QKVN);

    rope_rms_gate_kernel<<<TOKz, 384>>>(x, ve, cosb, sinb, Wg);

    cudaFuncSetAttribute(attn_mma, cudaFuncAttributeMaxDynamicSharedMemorySize, ATT_SMEM);
    attn_mma<<<dim3(Tz / 64, NHz, Bz), 128, ATT_SMEM>>>(win);

    // projection GEMM: A = y (split), B = Wproj hi
    gemm_mma<<<dim3(Cz / 128, TOKz / 128), 256, GSMEM>>>(yh, yl, whi + 3 * WW, out, Cz);
}

// round 6
// speedup vs baseline: 5.4848x; 1.0234x over previous
#include <cuda_runtime.h>
#include <cuda_fp16.h>
#include <math.h>
#include <stdint.h>

// Problem constants
#define Bz 4
#define Tz 2048
#define Cz 768
#define NHz 12
#define HDz 64
#define TOKz (Bz * Tz)   // 8192
#define QKVN 2304        // fused q|k|v output width

// fp32 intermediate: fused qkv GEMM output
__device__ float g_qkv[TOKz * QKVN];

// split-fp16 operands
__device__ __half g_xhi[TOKz * Cz];
__device__ __half g_xlo[TOKz * Cz];
__device__ __half g_whi[4 * Cz * Cz];   // [Wq;Wk;Wv;Wproj] hi parts

// attention operands (q needs hi+lo; k,v hi only)
__device__ __half g_qh[TOKz * Cz];
__device__ __half g_ql[TOKz * Cz];
__device__ __half g_kh[TOKz * Cz];
__device__ __half g_vh[TOKz * Cz];

// attention output, split fp16 (A operand of proj GEMM)
__device__ __half g_yh[TOKz * Cz];
__device__ __half g_yl[TOKz * Cz];

// ---------------------------------------------------------------------------
// Helpers
// ---------------------------------------------------------------------------
__device__ __forceinline__ uint32_t smem_u32(const void* p) {
    uint32_t a;
    asm("{ .reg .u64 t; cvta.to.shared.u64 t, %1; cvt.u32.u64 %0, t; }"
        : "=r"(a) : "l"(p));
    return a;
}

#define LDSM4(r, addr)                                                        \
    asm volatile("ldmatrix.sync.aligned.m8n8.x4.shared.b16 {%0,%1,%2,%3}, [%4];" \
                 : "=r"((r)[0]), "=r"((r)[1]), "=r"((r)[2]), "=r"((r)[3])     \
                 : "r"(addr))

#define LDSM4T(r, addr)                                                       \
    asm volatile("ldmatrix.sync.aligned.m8n8.x4.trans.shared.b16 {%0,%1,%2,%3}, [%4];" \
                 : "=r"((r)[0]), "=r"((r)[1]), "=r"((r)[2]), "=r"((r)[3])     \
                 : "r"(addr))

#define LDSM2(r, addr)                                                        \
    asm volatile("ldmatrix.sync.aligned.m8n8.x2.shared.b16 {%0,%1}, [%2];"    \
                 : "=r"((r)[0]), "=r"((r)[1]) : "r"(addr))

#define MMAH(c, a, b0, b1)                                                    \
    asm volatile("mma.sync.aligned.m16n8k16.row.col.f32.f16.f16.f32 "        \
                 "{%0,%1,%2,%3}, {%4,%5,%6,%7}, {%8,%9}, {%0,%1,%2,%3};"     \
                 : "+f"((c)[0]), "+f"((c)[1]), "+f"((c)[2]), "+f"((c)[3])    \
                 : "r"((a)[0]), "r"((a)[1]), "r"((a)[2]), "r"((a)[3]),       \
                   "r"(b0), "r"(b1))

#define CPASYNC16(s, g)                                                       \
    asm volatile("cp.async.ca.shared.global [%0], [%1], 16;" :: "r"(s), "l"(g))

__device__ __forceinline__ uint32_t packh2(float a, float b) {
    __half2 t = __floats2half2_rn(a, b);
    return *(uint32_t*)&t;
}

// ---------------------------------------------------------------------------
// Split-fp16 2-pass HMMA GEMM (NT): C[M x N] = A * B^T, K=768.
// acc = Ahi*Bhi + Alo*Bhi. Block 128x128, chunks of 64, double buffer.
// Occupancy 2 (two CTAs per SM) for cross-CTA latency hiding.
// ---------------------------------------------------------------------------
#define GK 768
#define NCH 12
#define ARR 16384                 // one 128x64 fp16 array (swizzled)
#define STG3 (3 * ARR)            // Ahi, Alo, Bhi = 48 KB
#define GSMEM (2 * STG3)          // 96 KB

__global__ __launch_bounds__(256, 2) void gemm_mma(
    const __half* __restrict__ Ahi, const __half* __restrict__ Alo,
    const __half* __restrict__ Bh, float* __restrict__ C, int ldc)
{
    extern __shared__ __align__(1024) char dsm[];
    const uint32_t sb = smem_u32(dsm);
    const int tid = threadIdx.x;
    const int wid = tid >> 5, lane = tid & 31;
    const int bm = blockIdx.y << 7;
    const int bn = blockIdx.x << 7;
    const int warp_m = wid >> 2;
    const int warp_n = wid & 3;

    const __half* gA0 = Ahi + (size_t)bm * GK;
    const __half* gA1 = Alo + (size_t)bm * GK;
    const __half* gB  = Bh  + (size_t)bn * GK;

    const int lrow = tid >> 3;
    const int lc16 = tid & 7;

    float acc[4][4][4];
#pragma unroll
    for (int i = 0; i < 4; i++)
#pragma unroll
        for (int j = 0; j < 4; j++)
#pragma unroll
            for (int k = 0; k < 4; k++) acc[i][j][k] = 0.f;

    auto issue = [&](int c, int s) {
        uint32_t sbase = sb + s * STG3;
#pragma unroll
        for (int i = 0; i < 4; i++) {
            int row = lrow + i * 32;
            uint32_t so = (uint32_t)(row * 128 + lc16 * 16) ^ (uint32_t)((row & 7) << 4);
            size_t go = (size_t)row * GK + c * 64 + lc16 * 8;
            CPASYNC16(sbase + 0 * ARR + so, (const char*)(gA0 + go));
            CPASYNC16(sbase + 1 * ARR + so, (const char*)(gA1 + go));
            CPASYNC16(sbase + 2 * ARR + so, (const char*)(gB + go));
        }
        asm volatile("cp.async.commit_group;");
    };

    issue(0, 0);

    const uint32_t aswz = (uint32_t)((lane & 7) << 4);
    const int arow = warp_m * 64 + (lane & 15);
    const int brow = warp_n * 32 + (lane & 7);
    const uint32_t akhi = (uint32_t)((lane >> 4) << 4);
    const uint32_t bkhi = (uint32_t)(((lane >> 3) & 1) << 4);

#pragma unroll 1
    for (int c = 0; c < NCH; ++c) {
        if (c + 1 < NCH) {
            issue(c + 1, (c + 1) & 1);
            asm volatile("cp.async.wait_group 1;");
        } else {
            asm volatile("cp.async.wait_group 0;");
        }
        __syncthreads();

        const uint32_t sbase = sb + (c & 1) * STG3;
#pragma unroll
        for (int ks = 0; ks < 4; ++ks) {
            uint32_t ah[4][4], al[4][4], bh[4][2];
            const uint32_t ak = ((uint32_t)(ks * 32) + akhi) ^ aswz;
            const uint32_t bk = ((uint32_t)(ks * 32) + bkhi) ^ aswz;
#pragma unroll
            for (int mt = 0; mt < 4; mt++) {
                uint32_t ra = sbase + (uint32_t)((arow + mt * 16) * 128) + ak;
                LDSM4(ah[mt], ra);
                LDSM4(al[mt], ra + ARR);
            }
#pragma unroll
            for (int nt = 0; nt < 4; nt++) {
                uint32_t rb = sbase + 2 * ARR + (uint32_t)((brow + nt * 8) * 128) + bk;
                LDSM2(bh[nt], rb);
            }
#pragma unroll
            for (int mt = 0; mt < 4; mt++)
#pragma unroll
                for (int nt = 0; nt < 4; nt++) {
                    MMAH(acc[mt][nt], ah[mt], bh[nt][0], bh[nt][1]);
                    MMAH(acc[mt][nt], al[mt], bh[nt][0], bh[nt][1]);
                }
        }
        __syncthreads();
    }

    const int crow = bm + warp_m * 64 + (lane >> 2);
    const int ccol = bn + warp_n * 32 + (lane & 3) * 2;
#pragma unroll
    for (int mt = 0; mt < 4; mt++)
#pragma unroll
        for (int nt = 0; nt < 4; nt++) {
            float* p0 = C + (size_t)(crow + mt * 16) * ldc + ccol + nt * 8;
            float* p1 = p0 + 8 * ldc;
            *(float2*)p0 = make_float2(acc[mt][nt][0], acc[mt][nt][1]);
            *(float2*)p1 = make_float2(acc[mt][nt][2], acc[mt][nt][3]);
        }
}

// ---------------------------------------------------------------------------
// fp32 -> split fp16 (hi+lo) for x; hi-only for all 4 weight matrices (fused)
// ---------------------------------------------------------------------------
__global__ void cvt_split4(const float4* __restrict__ s,
                           __half* __restrict__ hi, __half* __restrict__ lo, int n4)
{
    int i = blockIdx.x * 256 + threadIdx.x;
    if (i >= n4) return;
    float4 v = s[i];
    __half h0 = __float2half(v.x), h1 = __float2half(v.y);
    __half h2 = __float2half(v.z), h3 = __float2half(v.w);
    ((__half2*)hi)[2 * i]     = __half2(h0, h1);
    ((__half2*)hi)[2 * i + 1] = __half2(h2, h3);
    ((__half2*)lo)[2 * i]     = __half2(__float2half(v.x - __half2float(h0)),
                                        __float2half(v.y - __half2float(h1)));
    ((__half2*)lo)[2 * i + 1] = __half2(__float2half(v.z - __half2float(h2)),
                                        __float2half(v.w - __half2float(h3)));
}

__global__ void cvt_weights(const float4* __restrict__ w0, const float4* __restrict__ w1,
                            const float4* __restrict__ w2, const float4* __restrict__ w3,
                            __half* __restrict__ hi, int n4each)
{
    int i = blockIdx.x * 256 + threadIdx.x;
    int m = i / n4each;
    int r = i - m * n4each;
    if (m >= 4) return;
    const float4* src = (m == 0) ? w0 : (m == 1) ? w1 : (m == 2) ? w2 : w3;
    float4 v = src[r];
    ((__half2*)hi)[2 * i]     = __half2(__float2half(v.x), __float2half(v.y));
    ((__half2*)hi)[2 * i + 1] = __half2(__float2half(v.z), __float2half(v.w));
}

// ---------------------------------------------------------------------------
// RoPE + RMSNorm(*1.2) + gated ve add; reads fused qkv, writes split q + hi k,v
// ---------------------------------------------------------------------------
__global__ __launch_bounds__(384) void rope_rms_gate_kernel(
    const float* __restrict__ x, const float* __restrict__ ve,
    const float* __restrict__ cosb, const float* __restrict__ sinb,
    const float* __restrict__ Wg)
{
    const int tok = blockIdx.x;
    const int t = tok & (Tz - 1);
    const int h = threadIdx.x >> 5;
    const int lane = threadIdx.x & 31;
    const size_t qkvbase = (size_t)tok * QKVN + h * HDz;
    const size_t base = (size_t)tok * Cz + h * HDz;

    const float cv = cosb[t * 32 + lane];
    const float sv = sinb[t * 32 + lane];

    {   // q: rope + rms, split hi/lo
        float x1 = g_qkv[qkvbase + lane], x2 = g_qkv[qkvbase + 32 + lane];
        float r1 = x1 * cv - x2 * sv;
        float r2 = x1 * sv + x2 * cv;
        float ss = r1 * r1 + r2 * r2;
#pragma unroll
        for (int o = 16; o > 0; o >>= 1) ss += __shfl_xor_sync(0xFFFFFFFFu, ss, o);
        float inv = rsqrtf(ss * (1.0f / 64.0f) + 1e-6f) * 1.2f;
        float q1 = r1 * inv, q2 = r2 * inv;
        __half h1 = __float2half(q1), h2 = __float2half(q2);
        g_qh[base + lane] = h1;
        g_qh[base + 32 + lane] = h2;
        g_ql[base + lane] = __float2half(q1 - __half2float(h1));
        g_ql[base + 32 + lane] = __float2half(q2 - __half2float(h2));
    }
    {   // k: rope + rms, hi only
        float x1 = g_qkv[qkvbase + Cz + lane], x2 = g_qkv[qkvbase + Cz + 32 + lane];
        float r1 = x1 * cv - x2 * sv;
        float r2 = x1 * sv + x2 * cv;
        float ss = r1 * r1 + r2 * r2;
#pragma unroll
        for (int o = 16; o > 0; o >>= 1) ss += __shfl_xor_sync(0xFFFFFFFFu, ss, o);
        float inv = rsqrtf(ss * (1.0f / 64.0f) + 1e-6f) * 1.2f;
        g_kh[base + lane] = __float2half(r1 * inv);
        g_kh[base + 32 + lane] = __float2half(r2 * inv);
    }
    {   // v: gated ve add, hi only
        float p = (lane < 12) ? x[(size_t)tok * Cz + lane] * Wg[h * 12 + lane] : 0.f;
#pragma unroll
        for (int o = 16; o > 0; o >>= 1) p += __shfl_xor_sync(0xFFFFFFFFu, p, o);
        float gate = 3.0f / (1.0f + __expf(-p));
        float v1 = g_qkv[qkvbase + 2 * Cz + lane]      + gate * ve[base + lane];
        float v2 = g_qkv[qkvbase + 2 * Cz + 32 + lane] + gate * ve[base + 32 + lane];
        g_vh[base + lane] = __float2half(v1);
        g_vh[base + 32 + lane] = __float2half(v2);
    }
}

// ---------------------------------------------------------------------------
// MMA flash attention (split fp16, 2-pass), sliding window.
// Longest-first scheduling: blockIdx.x reversed so 17-tile CTAs launch first.
// ---------------------------------------------------------------------------
#define ATT_Q 0
#define ATT_K 16384
#define ATT_STG 16384
#define ATT_SMEM 49152

__global__ __launch_bounds__(128, 4) void attn_mma(const int* __restrict__ winp)
{
    extern __shared__ __align__(1024) char dsm[];
    const uint32_t sb = smem_u32(dsm);
    const int tid = threadIdx.x;
    const int wid = tid >> 5, lane = tid & 31;
    const int qt0 = (gridDim.x - 1 - blockIdx.x) * 64;   // longest-first
    const int h = blockIdx.y;
    const int b = blockIdx.z;
    const int W = *winp;

    const size_t hoff = (size_t)h * HDz;
    const size_t btok = (size_t)b * Tz;

    // ---- load Q (hi+lo)
    {
#pragma unroll
        for (int i = 0; i < 4; i++) {
            int row = (i * 128 + tid) >> 3;
            int c16 = tid & 7;
            uint32_t so = (uint32_t)(row * 128 + c16 * 16) ^ (uint32_t)((row & 7) << 4);
            size_t go = (btok + qt0 + row) * Cz + hoff + c16 * 8;
            CPASYNC16(sb + ATT_Q + so, (const char*)(g_qh + go));
            CPASYNC16(sb + ATT_Q + 8192 + so, (const char*)(g_ql + go));
        }
        asm volatile("cp.async.commit_group;");
    }

    auto issue_kv = [&](int kt0, int s) {
        uint32_t sbase = sb + ATT_K + s * ATT_STG;
#pragma unroll
        for (int i = 0; i < 4; i++) {
            int row = (i * 128 + tid) >> 3;
            int c16 = tid & 7;
            uint32_t so = (uint32_t)(row * 128 + c16 * 16) ^ (uint32_t)((row & 7) << 4);
            size_t go = (btok + kt0 + row) * Cz + hoff + c16 * 8;
            CPASYNC16(sbase + so,        (const char*)(g_kh + go));
            CPASYNC16(sbase + 8192 + so, (const char*)(g_vh + go));
        }
        asm volatile("cp.async.commit_group;");
    };

    int lo = qt0 - W; if (lo < 0) lo = 0;
    const int kt_begin = lo & ~63;
    const int nt = ((qt0 - kt_begin) >> 6) + 1;

    issue_kv(kt_begin, 0);

    const int arow = wid * 16 + (lane & 15);
    const uint32_t aswzQ = (uint32_t)((arow & 7) << 4);
    const uint32_t acol_hi = (uint32_t)((lane >> 4) << 4);

    const int r0 = qt0 + wid * 16 + (lane >> 2);
    const int r1 = r0 + 8;
    const int cbase = (lane & 3) * 2;

    float m0 = -1e30f, m1 = -1e30f, l0 = 0.f, l1 = 0.f;
    float o[8][4];
#pragma unroll
    for (int j = 0; j < 8; j++)
#pragma unroll
        for (int q = 0; q < 4; q++) o[j][q] = 0.f;

#pragma unroll 1
    for (int it = 0; it < nt; ++it) {
        const int kt0 = kt_begin + it * 64;
        if (it + 1 < nt) {
            issue_kv(kt0 + 64, (it + 1) & 1);
            asm volatile("cp.async.wait_group 1;");
        } else {
            asm volatile("cp.async.wait_group 0;");
        }
        __syncthreads();

        const uint32_t kvb = sb + ATT_K + (it & 1) * ATT_STG;

        // ---- S = Q K^T (2-pass)
        float sa[8][4];
#pragma unroll
        for (int j = 0; j < 8; j++)
#pragma unroll
            for (int q = 0; q < 4; q++) sa[j][q] = 0.f;

#pragma unroll
        for (int kk = 0; kk < 4; ++kk) {
            uint32_t ah[4], al[4];
            {
                uint32_t bc = ((uint32_t)(kk * 32) + acol_hi) ^ aswzQ;
                uint32_t ra = sb + ATT_Q + (uint32_t)(arow * 128) + bc;
                LDSM4(ah, ra);
                LDSM4(al, ra + 8192);
            }
            uint32_t kh[4][4];
            {
                const int grp = lane >> 3;
                const int krow_off = (grp >> 1) * 8 + (lane & 7);
                const uint32_t bc_off = (uint32_t)(kk * 32 + (grp & 1) * 16);
#pragma unroll
                for (int p = 0; p < 4; p++) {
                    int krow = p * 16 + krow_off;
                    uint32_t so = (uint32_t)(krow * 128) + (bc_off ^ ((uint32_t)(krow & 7) << 4));
                    LDSM4(kh[p], kvb + so);
                }
            }
#pragma unroll
            for (int p = 0; p < 4; p++) {
                MMAH(sa[2 * p],     ah, kh[p][0], kh[p][1]);
                MMAH(sa[2 * p + 1], ah, kh[p][2], kh[p][3]);
                MMAH(sa[2 * p],     al, kh[p][0], kh[p][1]);
                MMAH(sa[2 * p + 1], al, kh[p][2], kh[p][3]);
            }
        }

        // ---- masked online softmax
        float rm0 = -1e30f, rm1 = -1e30f;
#pragma unroll
        for (int j = 0; j < 8; j++) {
            const int c0 = kt0 + j * 8 + cbase;
            const int c1 = c0 + 1;
            bool ok00 = (c0 <= r0) && (r0 - c0 <= W);
            bool ok01 = (c1 <= r0) && (r0 - c1 <= W);
            bool ok10 = (c0 <= r1) && (r1 - c0 <= W);
            bool ok11 = (c1 <= r1) && (r1 - c1 <= W);
            sa[j][0] = ok00 ? sa[j][0] * 0.125f : -1e30f;
            sa[j][1] = ok01 ? sa[j][1] * 0.125f : -1e30f;
            sa[j][2] = ok10 ? sa[j][2] * 0.125f : -1e30f;
            sa[j][3] = ok11 ? sa[j][3] * 0.125f : -1e30f;
            rm0 = fmaxf(rm0, fmaxf(sa[j][0], sa[j][1]));
            rm1 = fmaxf(rm1, fmaxf(sa[j][2], sa[j][3]));
        }
#pragma unroll
        for (int off = 1; off <= 2; off <<= 1) {
            rm0 = fmaxf(rm0, __shfl_xor_sync(0xFFFFFFFFu, rm0, off));
            rm1 = fmaxf(rm1, __shfl_xor_sync(0xFFFFFFFFu, rm1, off));
        }
        const float mn0 = fmaxf(m0, rm0);
        const float mn1 = fmaxf(m1, rm1);
        const float corr0 = __expf(m0 - mn0);
        const float corr1 = __expf(m1 - mn1);
        m0 = mn0; m1 = mn1;

        float rs0 = 0.f, rs1 = 0.f;
        uint32_t aph[4][4], apl[4][4];
#pragma unroll
        for (int p = 0; p < 4; p++) {
#pragma unroll
            for (int jl = 0; jl < 2; jl++) {
                const int j = 2 * p + jl;
                float p0 = (sa[j][0] > -1e29f) ? __expf(sa[j][0] - mn0) : 0.f;
                float p1 = (sa[j][1] > -1e29f) ? __expf(sa[j][1] - mn0) : 0.f;
                float p2 = (sa[j][2] > -1e29f) ? __expf(sa[j][2] - mn1) : 0.f;
                float p3 = (sa[j][3] > -1e29f) ? __expf(sa[j][3] - mn1) : 0.f;
                rs0 += p0 + p1;
                rs1 += p2 + p3;
                uint32_t hi01 = packh2(p0, p1);
                uint32_t hi23 = packh2(p2, p3);
                __half2 h01 = *(__half2*)&hi01;
                __half2 h23 = *(__half2*)&hi23;
                aph[p][2 * jl + 0] = hi01;
                aph[p][2 * jl + 1] = hi23;
                apl[p][2 * jl + 0] = packh2(p0 - __half2float(h01.x),
                                            p1 - __half2float(h01.y));
                apl[p][2 * jl + 1] = packh2(p2 - __half2float(h23.x),
                                            p3 - __half2float(h23.y));
            }
        }
#pragma unroll
        for (int off = 1; off <= 2; off <<= 1) {
            rs0 += __shfl_xor_sync(0xFFFFFFFFu, rs0, off);
            rs1 += __shfl_xor_sync(0xFFFFFFFFu, rs1, off);
        }
        l0 = l0 * corr0 + rs0;
        l1 = l1 * corr1 + rs1;

#pragma unroll
        for (int j = 0; j < 8; j++) {
            o[j][0] *= corr0; o[j][1] *= corr0;
            o[j][2] *= corr1; o[j][3] *= corr1;
        }

        // ---- O += P V (2-pass)
        const uint32_t vbase = kvb + 8192;
        {
            const int vrow_off = lane & 15;
            const uint32_t vcol_hi = (uint32_t)((lane >> 4) << 4);
#pragma unroll
            for (int kk = 0; kk < 4; ++kk) {
                uint32_t vh[4][4];
#pragma unroll
                for (int t = 0; t < 4; t++) {
                    int vrow = kk * 16 + vrow_off;
                    uint32_t bc = ((uint32_t)(t * 32) + vcol_hi) ^ ((uint32_t)(vrow & 7) << 4);
                    LDSM4T(vh[t], vbase + (uint32_t)(vrow * 128) + bc);
                }
#pragma unroll
                for (int t = 0; t < 4; t++) {
                    MMAH(o[2 * t],     aph[kk], vh[t][0], vh[t][1]);
                    MMAH(o[2 * t + 1], aph[kk], vh[t][2], vh[t][3]);
                    MMAH(o[2 * t],     apl[kk], vh[t][0], vh[t][1]);
                    MMAH(o[2 * t + 1], apl[kk], vh[t][2], vh[t][3]);
                }
            }
        }
        __syncthreads();
    }

    // epilogue: normalize, write split-fp16 y
    const float i0 = 1.0f / l0;
    const float i1 = 1.0f / l1;
#pragma unroll
    for (int j = 0; j < 8; j++) {
        size_t col = hoff + j * 8 + cbase;
        size_t idx0 = (btok + r0) * Cz + col;
        size_t idx1 = (btok + r1) * Cz + col;
        float y00 = o[j][0] * i0, y01 = o[j][1] * i0;
        float y10 = o[j][2] * i1, y11 = o[j][3] * i1;
        __half2 h0 = __floats2half2_rn(y00, y01);
        __half2 h1 = __floats2half2_rn(y10, y11);
        *(__half2*)(g_yh + idx0) = h0;
        *(__half2*)(g_yh + idx1) = h1;
        *(__half2*)(g_yl + idx0) = __floats2half2_rn(y00 - __half2float(h0.x),
                                                     y01 - __half2float(h0.y));
        *(__half2*)(g_yl + idx1) = __floats2half2_rn(y10 - __half2float(h1.x),
                                                     y11 - __half2float(h1.y));
    }
}

// ---------------------------------------------------------------------------
extern "C" void kernel_launch(void* const* d_in, const int* in_sizes, int n_in,
                              void* d_out, int out_size)
{
    const float* x     = (const float*)d_in[0];
    const float* ve    = (const float*)d_in[1];
    const float* cosb  = (const float*)d_in[2];
    const float* sinb  = (const float*)d_in[3];
    const float* Wq    = (const float*)d_in[4];
    const float* Wk    = (const float*)d_in[5];
    const float* Wv    = (const float*)d_in[6];
    const float* Wproj = (const float*)d_in[7];
    const float* Wg    = (const float*)d_in[8];
    const int*   win   = (const int*)d_in[9];
    float* out = (float*)d_out;

    float* qkvp;
    __half *xhi, *xlo, *whi, *yh, *yl;
    cudaGetSymbolAddress((void**)&qkvp, g_qkv);
    cudaGetSymbolAddress((void**)&xhi, g_xhi);
    cudaGetSymbolAddress((void**)&xlo, g_xlo);
    cudaGetSymbolAddress((void**)&whi, g_whi);
    cudaGetSymbolAddress((void**)&yh, g_yh);
    cudaGetSymbolAddress((void**)&yl, g_yl);

    const int WW = Cz * Cz;
    const int n4x = TOKz * Cz / 4;
    const int n4w = WW / 4;

    cvt_split4<<<(n4x + 255) / 256, 256>>>((const float4*)x, xhi, xlo, n4x);
    cvt_weights<<<(4 * n4w + 255) / 256, 256>>>((const float4*)Wq, (const float4*)Wk,
                                                (const float4*)Wv, (const float4*)Wproj,
                                                whi, n4w);

    cudaFuncSetAttribute(gemm_mma, cudaFuncAttributeMaxDynamicSharedMemorySize, GSMEM);

    // fused QKV GEMM: B = [Wq;Wk;Wv] hi, N = 2304
    gemm_mma<<<dim3(QKVN / 128, TOKz / 128), 256, GSMEM>>>(xhi, xlo, whi, qkvp, QKVN);

    rope_rms_gate_kernel<<<TOKz, 384>>>(x, ve, cosb, sinb, Wg);

    cudaFuncSetAttribute(attn_mma, cudaFuncAttributeMaxDynamicSharedMemorySize, ATT_SMEM);
    attn_mma<<<dim3(Tz / 64, NHz, Bz), 128, ATT_SMEM>>>(win);

    // projection GEMM: A = y (split), B = Wproj hi
    gemm_mma<<<dim3(Cz / 128, TOKz / 128), 256, GSMEM>>>(yh, yl, whi + 3 * WW, out, Cz);
}

// round 7
// speedup vs baseline: 5.5522x; 1.0123x over previous
#include <cuda_runtime.h>
#include <cuda_fp16.h>
#include <math.h>
#include <stdint.h>

// Problem constants
#define Bz 4
#define Tz 2048
#define Cz 768
#define NHz 12
#define HDz 64
#define TOKz (Bz * Tz)   // 8192
#define QKVN 2304        // fused q|k|v output width

// fp32 intermediate: fused qkv GEMM output
__device__ float g_qkv[TOKz * QKVN];

// split-fp16 operands
__device__ __half g_xhi[TOKz * Cz];
__device__ __half g_xlo[TOKz * Cz];
__device__ __half g_whi[4 * Cz * Cz];   // [Wq;Wk;Wv;Wproj] hi parts

// attention operands (q needs hi+lo; k,v hi only)
__device__ __half g_qh[TOKz * Cz];
__device__ __half g_ql[TOKz * Cz];
__device__ __half g_kh[TOKz * Cz];
__device__ __half g_vh[TOKz * Cz];

// attention output, split fp16 (A operand of proj GEMM)
__device__ __half g_yh[TOKz * Cz];
__device__ __half g_yl[TOKz * Cz];

// ---------------------------------------------------------------------------
// Helpers
// ---------------------------------------------------------------------------
__device__ __forceinline__ uint32_t smem_u32(const void* p) {
    uint32_t a;
    asm("{ .reg .u64 t; cvta.to.shared.u64 t, %1; cvt.u32.u64 %0, t; }"
        : "=r"(a) : "l"(p));
    return a;
}

#define LDSM4(r, addr)                                                        \
    asm volatile("ldmatrix.sync.aligned.m8n8.x4.shared.b16 {%0,%1,%2,%3}, [%4];" \
                 : "=r"((r)[0]), "=r"((r)[1]), "=r"((r)[2]), "=r"((r)[3])     \
                 : "r"(addr))

#define LDSM4T(r, addr)                                                       \
    asm volatile("ldmatrix.sync.aligned.m8n8.x4.trans.shared.b16 {%0,%1,%2,%3}, [%4];" \
                 : "=r"((r)[0]), "=r"((r)[1]), "=r"((r)[2]), "=r"((r)[3])     \
                 : "r"(addr))

#define LDSM2(r, addr)                                                        \
    asm volatile("ldmatrix.sync.aligned.m8n8.x2.shared.b16 {%0,%1}, [%2];"    \
                 : "=r"((r)[0]), "=r"((r)[1]) : "r"(addr))

#define MMAH(c, a, b0, b1)                                                    \
    asm volatile("mma.sync.aligned.m16n8k16.row.col.f32.f16.f16.f32 "        \
                 "{%0,%1,%2,%3}, {%4,%5,%6,%7}, {%8,%9}, {%0,%1,%2,%3};"     \
                 : "+f"((c)[0]), "+f"((c)[1]), "+f"((c)[2]), "+f"((c)[3])    \
                 : "r"((a)[0]), "r"((a)[1]), "r"((a)[2]), "r"((a)[3]),       \
                   "r"(b0), "r"(b1))

#define CPASYNC16(s, g)                                                       \
    asm volatile("cp.async.ca.shared.global [%0], [%1], 16;" :: "r"(s), "l"(g))

__device__ __forceinline__ uint32_t packh2(float a, float b) {
    __half2 t = __floats2half2_rn(a, b);
    return *(uint32_t*)&t;
}

// ---------------------------------------------------------------------------
// Split-fp16 2-pass HMMA GEMM (NT): C[M x N] = A * B^T, K=768.
// acc = Ahi*Bhi + Alo*Bhi. Block 128x128, chunks of 64, double buffer, occ 2.
// ---------------------------------------------------------------------------
#define GK 768
#define NCH 12
#define ARR 16384                 // one 128x64 fp16 array (swizzled)
#define STG3 (3 * ARR)            // Ahi, Alo, Bhi = 48 KB
#define GSMEM (2 * STG3)          // 96 KB

__global__ __launch_bounds__(256, 2) void gemm_mma(
    const __half* __restrict__ Ahi, const __half* __restrict__ Alo,
    const __half* __restrict__ Bh, float* __restrict__ C, int ldc)
{
    extern __shared__ __align__(1024) char dsm[];
    const uint32_t sb = smem_u32(dsm);
    const int tid = threadIdx.x;
    const int wid = tid >> 5, lane = tid & 31;
    const int bm = blockIdx.y << 7;
    const int bn = blockIdx.x << 7;
    const int warp_m = wid >> 2;
    const int warp_n = wid & 3;

    const __half* gA0 = Ahi + (size_t)bm * GK;
    const __half* gA1 = Alo + (size_t)bm * GK;
    const __half* gB  = Bh  + (size_t)bn * GK;

    const int lrow = tid >> 3;
    const int lc16 = tid & 7;

    float acc[4][4][4];
#pragma unroll
    for (int i = 0; i < 4; i++)
#pragma unroll
        for (int j = 0; j < 4; j++)
#pragma unroll
            for (int k = 0; k < 4; k++) acc[i][j][k] = 0.f;

    auto issue = [&](int c, int s) {
        uint32_t sbase = sb + s * STG3;
#pragma unroll
        for (int i = 0; i < 4; i++) {
            int row = lrow + i * 32;
            uint32_t so = (uint32_t)(row * 128 + lc16 * 16) ^ (uint32_t)((row & 7) << 4);
            size_t go = (size_t)row * GK + c * 64 + lc16 * 8;
            CPASYNC16(sbase + 0 * ARR + so, (const char*)(gA0 + go));
            CPASYNC16(sbase + 1 * ARR + so, (const char*)(gA1 + go));
            CPASYNC16(sbase + 2 * ARR + so, (const char*)(gB + go));
        }
        asm volatile("cp.async.commit_group;");
    };

    issue(0, 0);

    const uint32_t aswz = (uint32_t)((lane & 7) << 4);
    const int arow = warp_m * 64 + (lane & 15);
    const int brow = warp_n * 32 + (lane & 7);
    const uint32_t akhi = (uint32_t)((lane >> 4) << 4);
    const uint32_t bkhi = (uint32_t)(((lane >> 3) & 1) << 4);

#pragma unroll 1
    for (int c = 0; c < NCH; ++c) {
        if (c + 1 < NCH) {
            issue(c + 1, (c + 1) & 1);
            asm volatile("cp.async.wait_group 1;");
        } else {
            asm volatile("cp.async.wait_group 0;");
        }
        __syncthreads();

        const uint32_t sbase = sb + (c & 1) * STG3;
#pragma unroll
        for (int ks = 0; ks < 4; ++ks) {
            uint32_t ah[4][4], al[4][4], bh[4][2];
            const uint32_t ak = ((uint32_t)(ks * 32) + akhi) ^ aswz;
            const uint32_t bk = ((uint32_t)(ks * 32) + bkhi) ^ aswz;
#pragma unroll
            for (int mt = 0; mt < 4; mt++) {
                uint32_t ra = sbase + (uint32_t)((arow + mt * 16) * 128) + ak;
                LDSM4(ah[mt], ra);
                LDSM4(al[mt], ra + ARR);
            }
#pragma unroll
            for (int nt = 0; nt < 4; nt++) {
                uint32_t rb = sbase + 2 * ARR + (uint32_t)((brow + nt * 8) * 128) + bk;
                LDSM2(bh[nt], rb);
            }
#pragma unroll
            for (int mt = 0; mt < 4; mt++)
#pragma unroll
                for (int nt = 0; nt < 4; nt++) {
                    MMAH(acc[mt][nt], ah[mt], bh[nt][0], bh[nt][1]);
                    MMAH(acc[mt][nt], al[mt], bh[nt][0], bh[nt][1]);
                }
        }
        __syncthreads();
    }

    const int crow = bm + warp_m * 64 + (lane >> 2);
    const int ccol = bn + warp_n * 32 + (lane & 3) * 2;
#pragma unroll
    for (int mt = 0; mt < 4; mt++)
#pragma unroll
        for (int nt = 0; nt < 4; nt++) {
            float* p0 = C + (size_t)(crow + mt * 16) * ldc + ccol + nt * 8;
            float* p1 = p0 + 8 * ldc;
            *(float2*)p0 = make_float2(acc[mt][nt][0], acc[mt][nt][1]);
            *(float2*)p1 = make_float2(acc[mt][nt][2], acc[mt][nt][3]);
        }
}

// ---------------------------------------------------------------------------
// fp32 -> split fp16 (hi+lo) for x; hi-only for all 4 weight matrices (fused)
// ---------------------------------------------------------------------------
__global__ void cvt_split4(const float4* __restrict__ s,
                           __half* __restrict__ hi, __half* __restrict__ lo, int n4)
{
    int i = blockIdx.x * 256 + threadIdx.x;
    if (i >= n4) return;
    float4 v = s[i];
    __half h0 = __float2half(v.x), h1 = __float2half(v.y);
    __half h2 = __float2half(v.z), h3 = __float2half(v.w);
    ((__half2*)hi)[2 * i]     = __half2(h0, h1);
    ((__half2*)hi)[2 * i + 1] = __half2(h2, h3);
    ((__half2*)lo)[2 * i]     = __half2(__float2half(v.x - __half2float(h0)),
                                        __float2half(v.y - __half2float(h1)));
    ((__half2*)lo)[2 * i + 1] = __half2(__float2half(v.z - __half2float(h2)),
                                        __float2half(v.w - __half2float(h3)));
}

__global__ void cvt_weights(const float4* __restrict__ w0, const float4* __restrict__ w1,
                            const float4* __restrict__ w2, const float4* __restrict__ w3,
                            __half* __restrict__ hi, int n4each)
{
    int i = blockIdx.x * 256 + threadIdx.x;
    int m = i / n4each;
    int r = i - m * n4each;
    if (m >= 4) return;
    const float4* src = (m == 0) ? w0 : (m == 1) ? w1 : (m == 2) ? w2 : w3;
    float4 v = src[r];
    ((__half2*)hi)[2 * i]     = __half2(__float2half(v.x), __float2half(v.y));
    ((__half2*)hi)[2 * i + 1] = __half2(__float2half(v.z), __float2half(v.w));
}

// ---------------------------------------------------------------------------
// RoPE + RMSNorm(*1.2) + gated ve add; reads fused qkv, writes split q + hi k,v
// ---------------------------------------------------------------------------
__global__ __launch_bounds__(384) void rope_rms_gate_kernel(
    const float* __restrict__ x, const float* __restrict__ ve,
    const float* __restrict__ cosb, const float* __restrict__ sinb,
    const float* __restrict__ Wg)
{
    const int tok = blockIdx.x;
    const int t = tok & (Tz - 1);
    const int h = threadIdx.x >> 5;
    const int lane = threadIdx.x & 31;
    const size_t qkvbase = (size_t)tok * QKVN + h * HDz;
    const size_t base = (size_t)tok * Cz + h * HDz;

    const float cv = cosb[t * 32 + lane];
    const float sv = sinb[t * 32 + lane];

    {   // q: rope + rms, split hi/lo
        float x1 = g_qkv[qkvbase + lane], x2 = g_qkv[qkvbase + 32 + lane];
        float r1 = x1 * cv - x2 * sv;
        float r2 = x1 * sv + x2 * cv;
        float ss = r1 * r1 + r2 * r2;
#pragma unroll
        for (int o = 16; o > 0; o >>= 1) ss += __shfl_xor_sync(0xFFFFFFFFu, ss, o);
        float inv = rsqrtf(ss * (1.0f / 64.0f) + 1e-6f) * 1.2f;
        float q1 = r1 * inv, q2 = r2 * inv;
        __half h1 = __float2half(q1), h2 = __float2half(q2);
        g_qh[base + lane] = h1;
        g_qh[base + 32 + lane] = h2;
        g_ql[base + lane] = __float2half(q1 - __half2float(h1));
        g_ql[base + 32 + lane] = __float2half(q2 - __half2float(h2));
    }
    {   // k: rope + rms, hi only
        float x1 = g_qkv[qkvbase + Cz + lane], x2 = g_qkv[qkvbase + Cz + 32 + lane];
        float r1 = x1 * cv - x2 * sv;
        float r2 = x1 * sv + x2 * cv;
        float ss = r1 * r1 + r2 * r2;
#pragma unroll
        for (int o = 16; o > 0; o >>= 1) ss += __shfl_xor_sync(0xFFFFFFFFu, ss, o);
        float inv = rsqrtf(ss * (1.0f / 64.0f) + 1e-6f) * 1.2f;
        g_kh[base + lane] = __float2half(r1 * inv);
        g_kh[base + 32 + lane] = __float2half(r2 * inv);
    }
    {   // v: gated ve add, hi only
        float p = (lane < 12) ? x[(size_t)tok * Cz + lane] * Wg[h * 12 + lane] : 0.f;
#pragma unroll
        for (int o = 16; o > 0; o >>= 1) p += __shfl_xor_sync(0xFFFFFFFFu, p, o);
        float gate = 3.0f / (1.0f + __expf(-p));
        float v1 = g_qkv[qkvbase + 2 * Cz + lane]      + gate * ve[base + lane];
        float v2 = g_qkv[qkvbase + 2 * Cz + 32 + lane] + gate * ve[base + 32 + lane];
        g_vh[base + lane] = __float2half(v1);
        g_vh[base + 32 + lane] = __float2half(v2);
    }
}

// ---------------------------------------------------------------------------
// MMA flash attention, 128-query CTA tile (8 warps), sliding window.
// S = Qhi*K + Qlo*K (2-pass); PV = Phi*V (1-pass).
// smem: Qh 16K | Ql 16K | 2 stages of (Kh 8K + Vh 8K) = 64 KB.
// ---------------------------------------------------------------------------
#define ATT_QH 0
#define ATT_QL 16384
#define ATT_K  32768
#define ATT_STG 16384
#define ATT_SMEM 65536

__global__ __launch_bounds__(256, 2) void attn_mma(const int* __restrict__ winp)
{
    extern __shared__ __align__(1024) char dsm[];
    const uint32_t sb = smem_u32(dsm);
    const int tid = threadIdx.x;
    const int wid = tid >> 5, lane = tid & 31;
    const int qt0 = (gridDim.x - 1 - blockIdx.x) * 128;   // longest-first
    const int h = blockIdx.y;
    const int b = blockIdx.z;
    const int W = *winp;

    const size_t hoff = (size_t)h * HDz;
    const size_t btok = (size_t)b * Tz;

    // ---- load Q (hi+lo): 128 rows x 8 chunks = 1024 segs, 4 iters
    {
#pragma unroll
        for (int i = 0; i < 4; i++) {
            int row = (i * 256 + tid) >> 3;
            int c16 = tid & 7;
            uint32_t so = (uint32_t)(row * 128 + c16 * 16) ^ (uint32_t)((row & 7) << 4);
            size_t go = (btok + qt0 + row) * Cz + hoff + c16 * 8;
            CPASYNC16(sb + ATT_QH + so, (const char*)(g_qh + go));
            CPASYNC16(sb + ATT_QL + so, (const char*)(g_ql + go));
        }
        asm volatile("cp.async.commit_group;");
    }

    auto issue_kv = [&](int kt0, int s) {
        uint32_t sbase = sb + ATT_K + s * ATT_STG;
#pragma unroll
        for (int i = 0; i < 2; i++) {
            int row = (i * 256 + tid) >> 3;
            int c16 = tid & 7;
            uint32_t so = (uint32_t)(row * 128 + c16 * 16) ^ (uint32_t)((row & 7) << 4);
            size_t go = (btok + kt0 + row) * Cz + hoff + c16 * 8;
            CPASYNC16(sbase + so,        (const char*)(g_kh + go));
            CPASYNC16(sbase + 8192 + so, (const char*)(g_vh + go));
        }
        asm volatile("cp.async.commit_group;");
    };

    int lo = qt0 - W; if (lo < 0) lo = 0;
    const int kt_begin = lo & ~63;
    const int nt = ((qt0 + 64 - kt_begin) >> 6) + 1;   // cover queries up to qt0+127

    issue_kv(kt_begin, 0);

    const int arow = wid * 16 + (lane & 15);
    const uint32_t aswzQ = (uint32_t)((arow & 7) << 4);
    const uint32_t acol_hi = (uint32_t)((lane >> 4) << 4);

    const int r0 = qt0 + wid * 16 + (lane >> 2);
    const int r1 = r0 + 8;
    const int cbase = (lane & 3) * 2;

    float m0 = -1e30f, m1 = -1e30f, l0 = 0.f, l1 = 0.f;
    float o[8][4];
#pragma unroll
    for (int j = 0; j < 8; j++)
#pragma unroll
        for (int q = 0; q < 4; q++) o[j][q] = 0.f;

#pragma unroll 1
    for (int it = 0; it < nt; ++it) {
        const int kt0 = kt_begin + it * 64;
        if (it + 1 < nt) {
            issue_kv(kt0 + 64, (it + 1) & 1);
            asm volatile("cp.async.wait_group 1;");
        } else {
            asm volatile("cp.async.wait_group 0;");
        }
        __syncthreads();

        const uint32_t kvb = sb + ATT_K + (it & 1) * ATT_STG;

        // ---- S = Q K^T (2-pass)
        float sa[8][4];
#pragma unroll
        for (int j = 0; j < 8; j++)
#pragma unroll
            for (int q = 0; q < 4; q++) sa[j][q] = 0.f;

#pragma unroll
        for (int kk = 0; kk < 4; ++kk) {
            uint32_t ah[4], al[4];
            {
                uint32_t bc = ((uint32_t)(kk * 32) + acol_hi) ^ aswzQ;
                uint32_t ra = sb + ATT_QH + (uint32_t)(arow * 128) + bc;
                LDSM4(ah, ra);
                LDSM4(al, ra + (ATT_QL - ATT_QH));
            }
            uint32_t kh[4][4];
            {
                const int grp = lane >> 3;
                const int krow_off = (grp >> 1) * 8 + (lane & 7);
                const uint32_t bc_off = (uint32_t)(kk * 32 + (grp & 1) * 16);
#pragma unroll
                for (int p = 0; p < 4; p++) {
                    int krow = p * 16 + krow_off;
                    uint32_t so = (uint32_t)(krow * 128) + (bc_off ^ ((uint32_t)(krow & 7) << 4));
                    LDSM4(kh[p], kvb + so);
                }
            }
#pragma unroll
            for (int p = 0; p < 4; p++) {
                MMAH(sa[2 * p],     ah, kh[p][0], kh[p][1]);
                MMAH(sa[2 * p + 1], ah, kh[p][2], kh[p][3]);
                MMAH(sa[2 * p],     al, kh[p][0], kh[p][1]);
                MMAH(sa[2 * p + 1], al, kh[p][2], kh[p][3]);
            }
        }

        // ---- masked online softmax
        float rm0 = -1e30f, rm1 = -1e30f;
#pragma unroll
        for (int j = 0; j < 8; j++) {
            const int c0 = kt0 + j * 8 + cbase;
            const int c1 = c0 + 1;
            bool ok00 = (c0 <= r0) && (r0 - c0 <= W);
            bool ok01 = (c1 <= r0) && (r0 - c1 <= W);
            bool ok10 = (c0 <= r1) && (r1 - c0 <= W);
            bool ok11 = (c1 <= r1) && (r1 - c1 <= W);
            sa[j][0] = ok00 ? sa[j][0] * 0.125f : -1e30f;
            sa[j][1] = ok01 ? sa[j][1] * 0.125f : -1e30f;
            sa[j][2] = ok10 ? sa[j][2] * 0.125f : -1e30f;
            sa[j][3] = ok11 ? sa[j][3] * 0.125f : -1e30f;
            rm0 = fmaxf(rm0, fmaxf(sa[j][0], sa[j][1]));
            rm1 = fmaxf(rm1, fmaxf(sa[j][2], sa[j][3]));
        }
#pragma unroll
        for (int off = 1; off <= 2; off <<= 1) {
            rm0 = fmaxf(rm0, __shfl_xor_sync(0xFFFFFFFFu, rm0, off));
            rm1 = fmaxf(rm1, __shfl_xor_sync(0xFFFFFFFFu, rm1, off));
        }
        const float mn0 = fmaxf(m0, rm0);
        const float mn1 = fmaxf(m1, rm1);
        const float corr0 = __expf(m0 - mn0);
        const float corr1 = __expf(m1 - mn1);
        m0 = mn0; m1 = mn1;

        float rs0 = 0.f, rs1 = 0.f;
        uint32_t aph[4][4];
#pragma unroll
        for (int p = 0; p < 4; p++) {
#pragma unroll
            for (int jl = 0; jl < 2; jl++) {
                const int j = 2 * p + jl;
                float p0 = (sa[j][0] > -1e29f) ? __expf(sa[j][0] - mn0) : 0.f;
                float p1 = (sa[j][1] > -1e29f) ? __expf(sa[j][1] - mn0) : 0.f;
                float p2 = (sa[j][2] > -1e29f) ? __expf(sa[j][2] - mn1) : 0.f;
                float p3 = (sa[j][3] > -1e29f) ? __expf(sa[j][3] - mn1) : 0.f;
                rs0 += p0 + p1;
                rs1 += p2 + p3;
                aph[p][2 * jl + 0] = packh2(p0, p1);
                aph[p][2 * jl + 1] = packh2(p2, p3);
            }
        }
#pragma unroll
        for (int off = 1; off <= 2; off <<= 1) {
            rs0 += __shfl_xor_sync(0xFFFFFFFFu, rs0, off);
            rs1 += __shfl_xor_sync(0xFFFFFFFFu, rs1, off);
        }
        l0 = l0 * corr0 + rs0;
        l1 = l1 * corr1 + rs1;

#pragma unroll
        for (int j = 0; j < 8; j++) {
            o[j][0] *= corr0; o[j][1] *= corr0;
            o[j][2] *= corr1; o[j][3] *= corr1;
        }

        // ---- O += P V (1-pass, P hi only)
        const uint32_t vbase = kvb + 8192;
        {
            const int vrow_off = lane & 15;
            const uint32_t vcol_hi = (uint32_t)((lane >> 4) << 4);
#pragma unroll
            for (int kk = 0; kk < 4; ++kk) {
                uint32_t vh[4][4];
#pragma unroll
                for (int t = 0; t < 4; t++) {
                    int vrow = kk * 16 + vrow_off;
                    uint32_t bc = ((uint32_t)(t * 32) + vcol_hi) ^ ((uint32_t)(vrow & 7) << 4);
                    LDSM4T(vh[t], vbase + (uint32_t)(vrow * 128) + bc);
                }
#pragma unroll
                for (int t = 0; t < 4; t++) {
                    MMAH(o[2 * t],     aph[kk], vh[t][0], vh[t][1]);
                    MMAH(o[2 * t + 1], aph[kk], vh[t][2], vh[t][3]);
                }
            }
        }
        __syncthreads();
    }

    // epilogue: normalize, write split-fp16 y
    const float i0 = 1.0f / l0;
    const float i1 = 1.0f / l1;
#pragma unroll
    for (int j = 0; j < 8; j++) {
        size_t col = hoff + j * 8 + cbase;
        size_t idx0 = (btok + r0) * Cz + col;
        size_t idx1 = (btok + r1) * Cz + col;
        float y00 = o[j][0] * i0, y01 = o[j][1] * i0;
        float y10 = o[j][2] * i1, y11 = o[j][3] * i1;
        __half2 h0 = __floats2half2_rn(y00, y01);
        __half2 h1 = __floats2half2_rn(y10, y11);
        *(__half2*)(g_yh + idx0) = h0;
        *(__half2*)(g_yh + idx1) = h1;
        *(__half2*)(g_yl + idx0) = __floats2half2_rn(y00 - __half2float(h0.x),
                                                     y01 - __half2float(h0.y));
        *(__half2*)(g_yl + idx1) = __floats2half2_rn(y10 - __half2float(h1.x),
                                                     y11 - __half2float(h1.y));
    }
}

// ---------------------------------------------------------------------------
extern "C" void kernel_launch(void* const* d_in, const int* in_sizes, int n_in,
                              void* d_out, int out_size)
{
    const float* x     = (const float*)d_in[0];
    const float* ve    = (const float*)d_in[1];
    const float* cosb  = (const float*)d_in[2];
    const float* sinb  = (const float*)d_in[3];
    const float* Wq    = (const float*)d_in[4];
    const float* Wk    = (const float*)d_in[5];
    const float* Wv    = (const float*)d_in[6];
    const float* Wproj = (const float*)d_in[7];
    const float* Wg    = (const float*)d_in[8];
    const int*   win   = (const int*)d_in[9];
    float* out = (float*)d_out;

    float* qkvp;
    __half *xhi, *xlo, *whi, *yh, *yl;
    cudaGetSymbolAddress((void**)&qkvp, g_qkv);
    cudaGetSymbolAddress((void**)&xhi, g_xhi);
    cudaGetSymbolAddress((void**)&xlo, g_xlo);
    cudaGetSymbolAddress((void**)&whi, g_whi);
    cudaGetSymbolAddress((void**)&yh, g_yh);
    cudaGetSymbolAddress((void**)&yl, g_yl);

    const int WW = Cz * Cz;
    const int n4x = TOKz * Cz / 4;
    const int n4w = WW / 4;

    cvt_split4<<<(n4x + 255) / 256, 256>>>((const float4*)x, xhi, xlo, n4x);
    cvt_weights<<<(4 * n4w + 255) / 256, 256>>>((const float4*)Wq, (const float4*)Wk,
                                                (const float4*)Wv, (const float4*)Wproj,
                                                whi, n4w);

    cudaFuncSetAttribute(gemm_mma, cudaFuncAttributeMaxDynamicSharedMemorySize, GSMEM);

    // fused QKV GEMM: B = [Wq;Wk;Wv] hi, N = 2304
    gemm_mma<<<dim3(QKVN / 128, TOKz / 128), 256, GSMEM>>>(xhi, xlo, whi, qkvp, QKVN);

    rope_rms_gate_kernel<<<TOKz, 384>>>(x, ve, cosb, sinb, Wg);

    cudaFuncSetAttribute(attn_mma, cudaFuncAttributeMaxDynamicSharedMemorySize, ATT_SMEM);
    attn_mma<<<dim3(Tz / 128, NHz, Bz), 256, ATT_SMEM>>>(win);

    // projection GEMM: A = y (split), B = Wproj hi
    gemm_mma<<<dim3(Cz / 128, TOKz / 128), 256, GSMEM>>>(yh, yl, whi + 3 * WW, out, Cz);
}

// round 8
// speedup vs baseline: 6.4684x; 1.1650x over previous
#include <cuda_runtime.h>
#include <cuda_fp16.h>
#include <math.h>
#include <stdint.h>

// Problem constants
#define Bz 4
#define Tz 2048
#define Cz 768
#define NHz 12
#define HDz 64
#define TOKz (Bz * Tz)   // 8192
#define QKVN 2304        // fused q|k|v output width

// fp32 intermediate: fused qkv GEMM output
__device__ float g_qkv[TOKz * QKVN];

// fp16 operands
__device__ __half g_xhi[TOKz * Cz];
__device__ __half g_whi[4 * Cz * Cz];   // [Wq;Wk;Wv;Wproj] hi parts

// attention operands (q needs hi+lo; k,v hi only)
__device__ __half g_qh[TOKz * Cz];
__device__ __half g_ql[TOKz * Cz];
__device__ __half g_kh[TOKz * Cz];
__device__ __half g_vh[TOKz * Cz];

// attention output, split fp16 (A operand of proj GEMM)
__device__ __half g_yh[TOKz * Cz];
__device__ __half g_yl[TOKz * Cz];

// ---------------------------------------------------------------------------
// Helpers
// ---------------------------------------------------------------------------
__device__ __forceinline__ uint32_t smem_u32(const void* p) {
    uint32_t a;
    asm("{ .reg .u64 t; cvta.to.shared.u64 t, %1; cvt.u32.u64 %0, t; }"
        : "=r"(a) : "l"(p));
    return a;
}

#define LDSM4(r, addr)                                                        \
    asm volatile("ldmatrix.sync.aligned.m8n8.x4.shared.b16 {%0,%1,%2,%3}, [%4];" \
                 : "=r"((r)[0]), "=r"((r)[1]), "=r"((r)[2]), "=r"((r)[3])     \
                 : "r"(addr))

#define LDSM4T(r, addr)                                                       \
    asm volatile("ldmatrix.sync.aligned.m8n8.x4.trans.shared.b16 {%0,%1,%2,%3}, [%4];" \
                 : "=r"((r)[0]), "=r"((r)[1]), "=r"((r)[2]), "=r"((r)[3])     \
                 : "r"(addr))

#define LDSM2(r, addr)                                                        \
    asm volatile("ldmatrix.sync.aligned.m8n8.x2.shared.b16 {%0,%1}, [%2];"    \
                 : "=r"((r)[0]), "=r"((r)[1]) : "r"(addr))

#define MMAH(c, a, b0, b1)                                                    \
    asm volatile("mma.sync.aligned.m16n8k16.row.col.f32.f16.f16.f32 "        \
                 "{%0,%1,%2,%3}, {%4,%5,%6,%7}, {%8,%9}, {%0,%1,%2,%3};"     \
                 : "+f"((c)[0]), "+f"((c)[1]), "+f"((c)[2]), "+f"((c)[3])    \
                 : "r"((a)[0]), "r"((a)[1]), "r"((a)[2]), "r"((a)[3]),       \
                   "r"(b0), "r"(b1))

#define CPASYNC16(s, g)                                                       \
    asm volatile("cp.async.ca.shared.global [%0], [%1], 16;" :: "r"(s), "l"(g))

__device__ __forceinline__ uint32_t packh2(float a, float b) {
    __half2 t = __floats2half2_rn(a, b);
    return *(uint32_t*)&t;
}

// ---------------------------------------------------------------------------
// fp16 HMMA GEMM (NT): C[M x N] = A * B^T, K=768.
// TWOPASS=1: acc = Ahi*Bhi + Alo*Bhi (22-bit effective A).
// TWOPASS=0: acc = Ahi*Bhi (plain fp16 A).
// Block 128x128, chunks of 64, double buffer, occ 2.
// ---------------------------------------------------------------------------
#define GK 768
#define NCH 12
#define ARR 16384                 // one 128x64 fp16 array (swizzled)
#define STG3 (3 * ARR)            // Ahi, (Alo), Bhi slots = 48 KB
#define GSMEM (2 * STG3)          // 96 KB

template <int TWOPASS>
__global__ __launch_bounds__(256, 2) void gemm_mma(
    const __half* __restrict__ Ahi, const __half* __restrict__ Alo,
    const __half* __restrict__ Bh, float* __restrict__ C, int ldc)
{
    extern __shared__ __align__(1024) char dsm[];
    const uint32_t sb = smem_u32(dsm);
    const int tid = threadIdx.x;
    const int wid = tid >> 5, lane = tid & 31;
    const int bm = blockIdx.y << 7;
    const int bn = blockIdx.x << 7;
    const int warp_m = wid >> 2;
    const int warp_n = wid & 3;

    const __half* gA0 = Ahi + (size_t)bm * GK;
    const __half* gA1 = TWOPASS ? (Alo + (size_t)bm * GK) : gA0;
    const __half* gB  = Bh  + (size_t)bn * GK;

    const int lrow = tid >> 3;
    const int lc16 = tid & 7;

    float acc[4][4][4];
#pragma unroll
    for (int i = 0; i < 4; i++)
#pragma unroll
        for (int j = 0; j < 4; j++)
#pragma unroll
            for (int k = 0; k < 4; k++) acc[i][j][k] = 0.f;

    auto issue = [&](int c, int s) {
        uint32_t sbase = sb + s * STG3;
#pragma unroll
        for (int i = 0; i < 4; i++) {
            int row = lrow + i * 32;
            uint32_t so = (uint32_t)(row * 128 + lc16 * 16) ^ (uint32_t)((row & 7) << 4);
            size_t go = (size_t)row * GK + c * 64 + lc16 * 8;
            CPASYNC16(sbase + 0 * ARR + so, (const char*)(gA0 + go));
            if (TWOPASS) CPASYNC16(sbase + 1 * ARR + so, (const char*)(gA1 + go));
            CPASYNC16(sbase + 2 * ARR + so, (const char*)(gB + go));
        }
        asm volatile("cp.async.commit_group;");
    };

    issue(0, 0);

    const uint32_t aswz = (uint32_t)((lane & 7) << 4);
    const int arow = warp_m * 64 + (lane & 15);
    const int brow = warp_n * 32 + (lane & 7);
    const uint32_t akhi = (uint32_t)((lane >> 4) << 4);
    const uint32_t bkhi = (uint32_t)(((lane >> 3) & 1) << 4);

#pragma unroll 1
    for (int c = 0; c < NCH; ++c) {
        if (c + 1 < NCH) {
            issue(c + 1, (c + 1) & 1);
            asm volatile("cp.async.wait_group 1;");
        } else {
            asm volatile("cp.async.wait_group 0;");
        }
        __syncthreads();

        const uint32_t sbase = sb + (c & 1) * STG3;
#pragma unroll
        for (int ks = 0; ks < 4; ++ks) {
            uint32_t ah[4][4], al[4][4], bh[4][2];
            const uint32_t ak = ((uint32_t)(ks * 32) + akhi) ^ aswz;
            const uint32_t bk = ((uint32_t)(ks * 32) + bkhi) ^ aswz;
#pragma unroll
            for (int mt = 0; mt < 4; mt++) {
                uint32_t ra = sbase + (uint32_t)((arow + mt * 16) * 128) + ak;
                LDSM4(ah[mt], ra);
                if (TWOPASS) LDSM4(al[mt], ra + ARR);
            }
#pragma unroll
            for (int nt = 0; nt < 4; nt++) {
                uint32_t rb = sbase + 2 * ARR + (uint32_t)((brow + nt * 8) * 128) + bk;
                LDSM2(bh[nt], rb);
            }
#pragma unroll
            for (int mt = 0; mt < 4; mt++)
#pragma unroll
                for (int nt = 0; nt < 4; nt++) {
                    MMAH(acc[mt][nt], ah[mt], bh[nt][0], bh[nt][1]);
                    if (TWOPASS) MMAH(acc[mt][nt], al[mt], bh[nt][0], bh[nt][1]);
                }
        }
        __syncthreads();
    }

    const int crow = bm + warp_m * 64 + (lane >> 2);
    const int ccol = bn + warp_n * 32 + (lane & 3) * 2;
#pragma unroll
    for (int mt = 0; mt < 4; mt++)
#pragma unroll
        for (int nt = 0; nt < 4; nt++) {
            float* p0 = C + (size_t)(crow + mt * 16) * ldc + ccol + nt * 8;
            float* p1 = p0 + 8 * ldc;
            *(float2*)p0 = make_float2(acc[mt][nt][0], acc[mt][nt][1]);
            *(float2*)p1 = make_float2(acc[mt][nt][2], acc[mt][nt][3]);
        }
}

// ---------------------------------------------------------------------------
// fp32 -> fp16 hi-only for x; hi-only for all 4 weight matrices (fused)
// ---------------------------------------------------------------------------
__global__ void cvt_hi4(const float4* __restrict__ s, __half* __restrict__ hi, int n4)
{
    int i = blockIdx.x * 256 + threadIdx.x;
    if (i >= n4) return;
    float4 v = s[i];
    ((__half2*)hi)[2 * i]     = __half2(__float2half(v.x), __float2half(v.y));
    ((__half2*)hi)[2 * i + 1] = __half2(__float2half(v.z), __float2half(v.w));
}

__global__ void cvt_weights(const float4* __restrict__ w0, const float4* __restrict__ w1,
                            const float4* __restrict__ w2, const float4* __restrict__ w3,
                            __half* __restrict__ hi, int n4each)
{
    int i = blockIdx.x * 256 + threadIdx.x;
    int m = i / n4each;
    int r = i - m * n4each;
    if (m >= 4) return;
    const float4* src = (m == 0) ? w0 : (m == 1) ? w1 : (m == 2) ? w2 : w3;
    float4 v = src[r];
    ((__half2*)hi)[2 * i]     = __half2(__float2half(v.x), __float2half(v.y));
    ((__half2*)hi)[2 * i + 1] = __half2(__float2half(v.z), __float2half(v.w));
}

// ---------------------------------------------------------------------------
// RoPE + RMSNorm(*1.2) + gated ve add; reads fused qkv, writes split q + hi k,v
// ---------------------------------------------------------------------------
__global__ __launch_bounds__(384) void rope_rms_gate_kernel(
    const float* __restrict__ x, const float* __restrict__ ve,
    const float* __restrict__ cosb, const float* __restrict__ sinb,
    const float* __restrict__ Wg)
{
    const int tok = blockIdx.x;
    const int t = tok & (Tz - 1);
    const int h = threadIdx.x >> 5;
    const int lane = threadIdx.x & 31;
    const size_t qkvbase = (size_t)tok * QKVN + h * HDz;
    const size_t base = (size_t)tok * Cz + h * HDz;

    const float cv = cosb[t * 32 + lane];
    const float sv = sinb[t * 32 + lane];

    {   // q: rope + rms, split hi/lo
        float x1 = g_qkv[qkvbase + lane], x2 = g_qkv[qkvbase + 32 + lane];
        float r1 = x1 * cv - x2 * sv;
        float r2 = x1 * sv + x2 * cv;
        float ss = r1 * r1 + r2 * r2;
#pragma unroll
        for (int o = 16; o > 0; o >>= 1) ss += __shfl_xor_sync(0xFFFFFFFFu, ss, o);
        float inv = rsqrtf(ss * (1.0f / 64.0f) + 1e-6f) * 1.2f;
        float q1 = r1 * inv, q2 = r2 * inv;
        __half h1 = __float2half(q1), h2 = __float2half(q2);
        g_qh[base + lane] = h1;
        g_qh[base + 32 + lane] = h2;
        g_ql[base + lane] = __float2half(q1 - __half2float(h1));
        g_ql[base + 32 + lane] = __float2half(q2 - __half2float(h2));
    }
    {   // k: rope + rms, hi only
        float x1 = g_qkv[qkvbase + Cz + lane], x2 = g_qkv[qkvbase + Cz + 32 + lane];
        float r1 = x1 * cv - x2 * sv;
        float r2 = x1 * sv + x2 * cv;
        float ss = r1 * r1 + r2 * r2;
#pragma unroll
        for (int o = 16; o > 0; o >>= 1) ss += __shfl_xor_sync(0xFFFFFFFFu, ss, o);
        float inv = rsqrtf(ss * (1.0f / 64.0f) + 1e-6f) * 1.2f;
        g_kh[base + lane] = __float2half(r1 * inv);
        g_kh[base + 32 + lane] = __float2half(r2 * inv);
    }
    {   // v: gated ve add, hi only
        float p = (lane < 12) ? x[(size_t)tok * Cz + lane] * Wg[h * 12 + lane] : 0.f;
#pragma unroll
        for (int o = 16; o > 0; o >>= 1) p += __shfl_xor_sync(0xFFFFFFFFu, p, o);
        float gate = 3.0f / (1.0f + __expf(-p));
        float v1 = g_qkv[qkvbase + 2 * Cz + lane]      + gate * ve[base + lane];
        float v2 = g_qkv[qkvbase + 2 * Cz + 32 + lane] + gate * ve[base + 32 + lane];
        g_vh[base + lane] = __float2half(v1);
        g_vh[base + 32 + lane] = __float2half(v2);
    }
}

// ---------------------------------------------------------------------------
// MMA flash attention, 128-query CTA tile (8 warps), sliding window.
// S = Qhi*K + Qlo*K (2-pass); PV = Phi*V (1-pass).
// smem: Qh 16K | Ql 16K | 2 stages of (Kh 8K + Vh 8K) = 64 KB.
// ---------------------------------------------------------------------------
#define ATT_QH 0
#define ATT_QL 16384
#define ATT_K  32768
#define ATT_STG 16384
#define ATT_SMEM 65536

__global__ __launch_bounds__(256, 2) void attn_mma(const int* __restrict__ winp)
{
    extern __shared__ __align__(1024) char dsm[];
    const uint32_t sb = smem_u32(dsm);
    const int tid = threadIdx.x;
    const int wid = tid >> 5, lane = tid & 31;
    const int qt0 = (gridDim.x - 1 - blockIdx.x) * 128;   // longest-first
    const int h = blockIdx.y;
    const int b = blockIdx.z;
    const int W = *winp;

    const size_t hoff = (size_t)h * HDz;
    const size_t btok = (size_t)b * Tz;

    // ---- load Q (hi+lo): 128 rows x 8 chunks = 1024 segs, 4 iters
    {
#pragma unroll
        for (int i = 0; i < 4; i++) {
            int row = (i * 256 + tid) >> 3;
            int c16 = tid & 7;
            uint32_t so = (uint32_t)(row * 128 + c16 * 16) ^ (uint32_t)((row & 7) << 4);
            size_t go = (btok + qt0 + row) * Cz + hoff + c16 * 8;
            CPASYNC16(sb + ATT_QH + so, (const char*)(g_qh + go));
            CPASYNC16(sb + ATT_QL + so, (const char*)(g_ql + go));
        }
        asm volatile("cp.async.commit_group;");
    }

    auto issue_kv = [&](int kt0, int s) {
        uint32_t sbase = sb + ATT_K + s * ATT_STG;
#pragma unroll
        for (int i = 0; i < 2; i++) {
            int row = (i * 256 + tid) >> 3;
            int c16 = tid & 7;
            uint32_t so = (uint32_t)(row * 128 + c16 * 16) ^ (uint32_t)((row & 7) << 4);
            size_t go = (btok + kt0 + row) * Cz + hoff + c16 * 8;
            CPASYNC16(sbase + so,        (const char*)(g_kh + go));
            CPASYNC16(sbase + 8192 + so, (const char*)(g_vh + go));
        }
        asm volatile("cp.async.commit_group;");
    };

    int lo = qt0 - W; if (lo < 0) lo = 0;
    const int kt_begin = lo & ~63;
    const int nt = ((qt0 + 64 - kt_begin) >> 6) + 1;   // cover queries up to qt0+127

    issue_kv(kt_begin, 0);

    const int arow = wid * 16 + (lane & 15);
    const uint32_t aswzQ = (uint32_t)((arow & 7) << 4);
    const uint32_t acol_hi = (uint32_t)((lane >> 4) << 4);

    const int r0 = qt0 + wid * 16 + (lane >> 2);
    const int r1 = r0 + 8;
    const int cbase = (lane & 3) * 2;

    float m0 = -1e30f, m1 = -1e30f, l0 = 0.f, l1 = 0.f;
    float o[8][4];
#pragma unroll
    for (int j = 0; j < 8; j++)
#pragma unroll
        for (int q = 0; q < 4; q++) o[j][q] = 0.f;

#pragma unroll 1
    for (int it = 0; it < nt; ++it) {
        const int kt0 = kt_begin + it * 64;
        if (it + 1 < nt) {
            issue_kv(kt0 + 64, (it + 1) & 1);
            asm volatile("cp.async.wait_group 1;");
        } else {
            asm volatile("cp.async.wait_group 0;");
        }
        __syncthreads();

        const uint32_t kvb = sb + ATT_K + (it & 1) * ATT_STG;

        // ---- S = Q K^T (2-pass)
        float sa[8][4];
#pragma unroll
        for (int j = 0; j < 8; j++)
#pragma unroll
            for (int q = 0; q < 4; q++) sa[j][q] = 0.f;

#pragma unroll
        for (int kk = 0; kk < 4; ++kk) {
            uint32_t ah[4], al[4];
            {
                uint32_t bc = ((uint32_t)(kk * 32) + acol_hi) ^ aswzQ;
                uint32_t ra = sb + ATT_QH + (uint32_t)(arow * 128) + bc;
                LDSM4(ah, ra);
                LDSM4(al, ra + (ATT_QL - ATT_QH));
            }
            uint32_t kh[4][4];
            {
                const int grp = lane >> 3;
                const int krow_off = (grp >> 1) * 8 + (lane & 7);
                const uint32_t bc_off = (uint32_t)(kk * 32 + (grp & 1) * 16);
#pragma unroll
                for (int p = 0; p < 4; p++) {
                    int krow = p * 16 + krow_off;
                    uint32_t so = (uint32_t)(krow * 128) + (bc_off ^ ((uint32_t)(krow & 7) << 4));
                    LDSM4(kh[p], kvb + so);
                }
            }
#pragma unroll
            for (int p = 0; p < 4; p++) {
                MMAH(sa[2 * p],     ah, kh[p][0], kh[p][1]);
                MMAH(sa[2 * p + 1], ah, kh[p][2], kh[p][3]);
                MMAH(sa[2 * p],     al, kh[p][0], kh[p][1]);
                MMAH(sa[2 * p + 1], al, kh[p][2], kh[p][3]);
            }
        }

        // ---- masked online softmax
        float rm0 = -1e30f, rm1 = -1e30f;
#pragma unroll
        for (int j = 0; j < 8; j++) {
            const int c0 = kt0 + j * 8 + cbase;
            const int c1 = c0 + 1;
            bool ok00 = (c0 <= r0) && (r0 - c0 <= W);
            bool ok01 = (c1 <= r0) && (r0 - c1 <= W);
            bool ok10 = (c0 <= r1) && (r1 - c0 <= W);
            bool ok11 = (c1 <= r1) && (r1 - c1 <= W);
            sa[j][0] = ok00 ? sa[j][0] * 0.125f : -1e30f;
            sa[j][1] = ok01 ? sa[j][1] * 0.125f : -1e30f;
            sa[j][2] = ok10 ? sa[j][2] * 0.125f : -1e30f;
            sa[j][3] = ok11 ? sa[j][3] * 0.125f : -1e30f;
            rm0 = fmaxf(rm0, fmaxf(sa[j][0], sa[j][1]));
            rm1 = fmaxf(rm1, fmaxf(sa[j][2], sa[j][3]));
        }
#pragma unroll
        for (int off = 1; off <= 2; off <<= 1) {
            rm0 = fmaxf(rm0, __shfl_xor_sync(0xFFFFFFFFu, rm0, off));
            rm1 = fmaxf(rm1, __shfl_xor_sync(0xFFFFFFFFu, rm1, off));
        }
        const float mn0 = fmaxf(m0, rm0);
        const float mn1 = fmaxf(m1, rm1);
        const float corr0 = __expf(m0 - mn0);
        const float corr1 = __expf(m1 - mn1);
        m0 = mn0; m1 = mn1;

        float rs0 = 0.f, rs1 = 0.f;
        uint32_t aph[4][4];
#pragma unroll
        for (int p = 0; p < 4; p++) {
#pragma unroll
            for (int jl = 0; jl < 2; jl++) {
                const int j = 2 * p + jl;
                float p0 = (sa[j][0] > -1e29f) ? __expf(sa[j][0] - mn0) : 0.f;
                float p1 = (sa[j][1] > -1e29f) ? __expf(sa[j][1] - mn0) : 0.f;
                float p2 = (sa[j][2] > -1e29f) ? __expf(sa[j][2] - mn1) : 0.f;
                float p3 = (sa[j][3] > -1e29f) ? __expf(sa[j][3] - mn1) : 0.f;
                rs0 += p0 + p1;
                rs1 += p2 + p3;
                aph[p][2 * jl + 0] = packh2(p0, p1);
                aph[p][2 * jl + 1] = packh2(p2, p3);
            }
        }
#pragma unroll
        for (int off = 1; off <= 2; off <<= 1) {
            rs0 += __shfl_xor_sync(0xFFFFFFFFu, rs0, off);
            rs1 += __shfl_xor_sync(0xFFFFFFFFu, rs1, off);
        }
        l0 = l0 * corr0 + rs0;
        l1 = l1 * corr1 + rs1;

#pragma unroll
        for (int j = 0; j < 8; j++) {
            o[j][0] *= corr0; o[j][1] *= corr0;
            o[j][2] *= corr1; o[j][3] *= corr1;
        }

        // ---- O += P V (1-pass, P hi only)
        const uint32_t vbase = kvb + 8192;
        {
            const int vrow_off = lane & 15;
            const uint32_t vcol_hi = (uint32_t)((lane >> 4) << 4);
#pragma unroll
            for (int kk = 0; kk < 4; ++kk) {
                uint32_t vh[4][4];
#pragma unroll
                for (int t = 0; t < 4; t++) {
                    int vrow = kk * 16 + vrow_off;
                    uint32_t bc = ((uint32_t)(t * 32) + vcol_hi) ^ ((uint32_t)(vrow & 7) << 4);
                    LDSM4T(vh[t], vbase + (uint32_t)(vrow * 128) + bc);
                }
#pragma unroll
                for (int t = 0; t < 4; t++) {
                    MMAH(o[2 * t],     aph[kk], vh[t][0], vh[t][1]);
                    MMAH(o[2 * t + 1], aph[kk], vh[t][2], vh[t][3]);
                }
            }
        }
        __syncthreads();
    }

    // epilogue: normalize, write split-fp16 y
    const float i0 = 1.0f / l0;
    const float i1 = 1.0f / l1;
#pragma unroll
    for (int j = 0; j < 8; j++) {
        size_t col = hoff + j * 8 + cbase;
        size_t idx0 = (btok + r0) * Cz + col;
        size_t idx1 = (btok + r1) * Cz + col;
        float y00 = o[j][0] * i0, y01 = o[j][1] * i0;
        float y10 = o[j][2] * i1, y11 = o[j][3] * i1;
        __half2 h0 = __floats2half2_rn(y00, y01);
        __half2 h1 = __floats2half2_rn(y10, y11);
        *(__half2*)(g_yh + idx0) = h0;
        *(__half2*)(g_yh + idx1) = h1;
        *(__half2*)(g_yl + idx0) = __floats2half2_rn(y00 - __half2float(h0.x),
                                                     y01 - __half2float(h0.y));
        *(__half2*)(g_yl + idx1) = __floats2half2_rn(y10 - __half2float(h1.x),
                                                     y11 - __half2float(h1.y));
    }
}

// ---------------------------------------------------------------------------
extern "C" void kernel_launch(void* const* d_in, const int* in_sizes, int n_in,
                              void* d_out, int out_size)
{
    const float* x     = (const float*)d_in[0];
    const float* ve    = (const float*)d_in[1];
    const float* cosb  = (const float*)d_in[2];
    const float* sinb  = (const float*)d_in[3];
    const float* Wq    = (const float*)d_in[4];
    const float* Wk    = (const float*)d_in[5];
    const float* Wv    = (const float*)d_in[6];
    const float* Wproj = (const float*)d_in[7];
    const float* Wg    = (const float*)d_in[8];
    const int*   win   = (const int*)d_in[9];
    float* out = (float*)d_out;

    float* qkvp;
    __half *xhi, *whi, *yh, *yl;
    cudaGetSymbolAddress((void**)&qkvp, g_qkv);
    cudaGetSymbolAddress((void**)&xhi, g_xhi);
    cudaGetSymbolAddress((void**)&whi, g_whi);
    cudaGetSymbolAddress((void**)&yh, g_yh);
    cudaGetSymbolAddress((void**)&yl, g_yl);

    const int WW = Cz * Cz;
    const int n4x = TOKz * Cz / 4;
    const int n4w = WW / 4;

    cvt_hi4<<<(n4x + 255) / 256, 256>>>((const float4*)x, xhi, n4x);
    cvt_weights<<<(4 * n4w + 255) / 256, 256>>>((const float4*)Wq, (const float4*)Wk,
                                                (const float4*)Wv, (const float4*)Wproj,
                                                whi, n4w);

    cudaFuncSetAttribute(gemm_mma<0>, cudaFuncAttributeMaxDynamicSharedMemorySize, GSMEM);
    cudaFuncSetAttribute(gemm_mma<1>, cudaFuncAttributeMaxDynamicSharedMemorySize, GSMEM);

    // fused QKV GEMM (1-pass, hi-only): B = [Wq;Wk;Wv] hi, N = 2304
    gemm_mma<0><<<dim3(QKVN / 128, TOKz / 128), 256, GSMEM>>>(xhi, xhi, whi, qkvp, QKVN);

    rope_rms_gate_kernel<<<TOKz, 384>>>(x, ve, cosb, sinb, Wg);

    cudaFuncSetAttribute(attn_mma, cudaFuncAttributeMaxDynamicSharedMemorySize, ATT_SMEM);
    attn_mma<<<dim3(Tz / 128, NHz, Bz), 256, ATT_SMEM>>>(win);

    // projection GEMM (2-pass): A = y (split), B = Wproj hi
    gemm_mma<1><<<dim3(Cz / 128, TOKz / 128), 256, GSMEM>>>(yh, yl, whi + 3 * WW, out, Cz);
}

// round 9
// speedup vs baseline: 7.4239x; 1.1477x over previous
#include <cuda_runtime.h>
#include <cuda_fp16.h>
#include <math.h>
#include <stdint.h>

// Problem constants
#define Bz 4
#define Tz 2048
#define Cz 768
#define NHz 12
#define HDz 64
#define TOKz (Bz * Tz)   // 8192
#define QKVN 2304        // fused q|k|v output width

// fp32 intermediate: fused qkv GEMM output
__device__ float g_qkv[TOKz * QKVN];

// fp16 operands
__device__ __half g_xhi[TOKz * Cz];
__device__ __half g_whi[4 * Cz * Cz];   // [Wq;Wk;Wv;Wproj] hi parts

// attention operands (all hi-only now)
__device__ __half g_qh[TOKz * Cz];
__device__ __half g_kh[TOKz * Cz];
__device__ __half g_vh[TOKz * Cz];

// attention output (A operand of proj GEMM, hi-only)
__device__ __half g_yh[TOKz * Cz];

// ---------------------------------------------------------------------------
// Helpers
// ---------------------------------------------------------------------------
__device__ __forceinline__ uint32_t smem_u32(const void* p) {
    uint32_t a;
    asm("{ .reg .u64 t; cvta.to.shared.u64 t, %1; cvt.u32.u64 %0, t; }"
        : "=r"(a) : "l"(p));
    return a;
}

#define LDSM4(r, addr)                                                        \
    asm volatile("ldmatrix.sync.aligned.m8n8.x4.shared.b16 {%0,%1,%2,%3}, [%4];" \
                 : "=r"((r)[0]), "=r"((r)[1]), "=r"((r)[2]), "=r"((r)[3])     \
                 : "r"(addr))

#define LDSM4T(r, addr)                                                       \
    asm volatile("ldmatrix.sync.aligned.m8n8.x4.trans.shared.b16 {%0,%1,%2,%3}, [%4];" \
                 : "=r"((r)[0]), "=r"((r)[1]), "=r"((r)[2]), "=r"((r)[3])     \
                 : "r"(addr))

#define LDSM2(r, addr)                                                        \
    asm volatile("ldmatrix.sync.aligned.m8n8.x2.shared.b16 {%0,%1}, [%2];"    \
                 : "=r"((r)[0]), "=r"((r)[1]) : "r"(addr))

#define MMAH(c, a, b0, b1)                                                    \
    asm volatile("mma.sync.aligned.m16n8k16.row.col.f32.f16.f16.f32 "        \
                 "{%0,%1,%2,%3}, {%4,%5,%6,%7}, {%8,%9}, {%0,%1,%2,%3};"     \
                 : "+f"((c)[0]), "+f"((c)[1]), "+f"((c)[2]), "+f"((c)[3])    \
                 : "r"((a)[0]), "r"((a)[1]), "r"((a)[2]), "r"((a)[3]),       \
                   "r"(b0), "r"(b1))

#define CPASYNC16(s, g)                                                       \
    asm volatile("cp.async.ca.shared.global [%0], [%1], 16;" :: "r"(s), "l"(g))

__device__ __forceinline__ uint32_t packh2(float a, float b) {
    __half2 t = __floats2half2_rn(a, b);
    return *(uint32_t*)&t;
}

// ---------------------------------------------------------------------------
// fp16 HMMA GEMM (NT): C[M x N] = A * B^T, K=768.
// TWOPASS=1: acc = Ahi*Bhi + Alo*Bhi; TWOPASS=0: acc = Ahi*Bhi.
// Block 128x128, chunks of 64, double buffer, occ 2.
// ---------------------------------------------------------------------------
#define GK 768
#define NCH 12
#define ARR 16384                 // one 128x64 fp16 array (swizzled)
#define STG3 (3 * ARR)            // Ahi, (Alo), Bhi slots = 48 KB
#define GSMEM (2 * STG3)          // 96 KB

template <int TWOPASS>
__global__ __launch_bounds__(256, 2) void gemm_mma(
    const __half* __restrict__ Ahi, const __half* __restrict__ Alo,
    const __half* __restrict__ Bh, float* __restrict__ C, int ldc)
{
    extern __shared__ __align__(1024) char dsm[];
    const uint32_t sb = smem_u32(dsm);
    const int tid = threadIdx.x;
    const int wid = tid >> 5, lane = tid & 31;
    const int bm = blockIdx.y << 7;
    const int bn = blockIdx.x << 7;
    const int warp_m = wid >> 2;
    const int warp_n = wid & 3;

    const __half* gA0 = Ahi + (size_t)bm * GK;
    const __half* gA1 = TWOPASS ? (Alo + (size_t)bm * GK) : gA0;
    const __half* gB  = Bh  + (size_t)bn * GK;

    const int lrow = tid >> 3;
    const int lc16 = tid & 7;

    float acc[4][4][4];
#pragma unroll
    for (int i = 0; i < 4; i++)
#pragma unroll
        for (int j = 0; j < 4; j++)
#pragma unroll
            for (int k = 0; k < 4; k++) acc[i][j][k] = 0.f;

    auto issue = [&](int c, int s) {
        uint32_t sbase = sb + s * STG3;
#pragma unroll
        for (int i = 0; i < 4; i++) {
            int row = lrow + i * 32;
            uint32_t so = (uint32_t)(row * 128 + lc16 * 16) ^ (uint32_t)((row & 7) << 4);
            size_t go = (size_t)row * GK + c * 64 + lc16 * 8;
            CPASYNC16(sbase + 0 * ARR + so, (const char*)(gA0 + go));
            if (TWOPASS) CPASYNC16(sbase + 1 * ARR + so, (const char*)(gA1 + go));
            CPASYNC16(sbase + 2 * ARR + so, (const char*)(gB + go));
        }
        asm volatile("cp.async.commit_group;");
    };

    issue(0, 0);

    const uint32_t aswz = (uint32_t)((lane & 7) << 4);
    const int arow = warp_m * 64 + (lane & 15);
    const int brow = warp_n * 32 + (lane & 7);
    const uint32_t akhi = (uint32_t)((lane >> 4) << 4);
    const uint32_t bkhi = (uint32_t)(((lane >> 3) & 1) << 4);

#pragma unroll 1
    for (int c = 0; c < NCH; ++c) {
        if (c + 1 < NCH) {
            issue(c + 1, (c + 1) & 1);
            asm volatile("cp.async.wait_group 1;");
        } else {
            asm volatile("cp.async.wait_group 0;");
        }
        __syncthreads();

        const uint32_t sbase = sb + (c & 1) * STG3;
#pragma unroll
        for (int ks = 0; ks < 4; ++ks) {
            uint32_t ah[4][4], al[4][4], bh[4][2];
            const uint32_t ak = ((uint32_t)(ks * 32) + akhi) ^ aswz;
            const uint32_t bk = ((uint32_t)(ks * 32) + bkhi) ^ aswz;
#pragma unroll
            for (int mt = 0; mt < 4; mt++) {
                uint32_t ra = sbase + (uint32_t)((arow + mt * 16) * 128) + ak;
                LDSM4(ah[mt], ra);
                if (TWOPASS) LDSM4(al[mt], ra + ARR);
            }
#pragma unroll
            for (int nt = 0; nt < 4; nt++) {
                uint32_t rb = sbase + 2 * ARR + (uint32_t)((brow + nt * 8) * 128) + bk;
                LDSM2(bh[nt], rb);
            }
#pragma unroll
            for (int mt = 0; mt < 4; mt++)
#pragma unroll
                for (int nt = 0; nt < 4; nt++) {
                    MMAH(acc[mt][nt], ah[mt], bh[nt][0], bh[nt][1]);
                    if (TWOPASS) MMAH(acc[mt][nt], al[mt], bh[nt][0], bh[nt][1]);
                }
        }
        __syncthreads();
    }

    const int crow = bm + warp_m * 64 + (lane >> 2);
    const int ccol = bn + warp_n * 32 + (lane & 3) * 2;
#pragma unroll
    for (int mt = 0; mt < 4; mt++)
#pragma unroll
        for (int nt = 0; nt < 4; nt++) {
            float* p0 = C + (size_t)(crow + mt * 16) * ldc + ccol + nt * 8;
            float* p1 = p0 + 8 * ldc;
            *(float2*)p0 = make_float2(acc[mt][nt][0], acc[mt][nt][1]);
            *(float2*)p1 = make_float2(acc[mt][nt][2], acc[mt][nt][3]);
        }
}

// ---------------------------------------------------------------------------
// fp32 -> fp16 hi-only for x; hi-only for all 4 weight matrices (fused)
// ---------------------------------------------------------------------------
__global__ void cvt_hi4(const float4* __restrict__ s, __half* __restrict__ hi, int n4)
{
    int i = blockIdx.x * 256 + threadIdx.x;
    if (i >= n4) return;
    float4 v = s[i];
    ((__half2*)hi)[2 * i]     = __half2(__float2half(v.x), __float2half(v.y));
    ((__half2*)hi)[2 * i + 1] = __half2(__float2half(v.z), __float2half(v.w));
}

__global__ void cvt_weights(const float4* __restrict__ w0, const float4* __restrict__ w1,
                            const float4* __restrict__ w2, const float4* __restrict__ w3,
                            __half* __restrict__ hi, int n4each)
{
    int i = blockIdx.x * 256 + threadIdx.x;
    int m = i / n4each;
    int r = i - m * n4each;
    if (m >= 4) return;
    const float4* src = (m == 0) ? w0 : (m == 1) ? w1 : (m == 2) ? w2 : w3;
    float4 v = src[r];
    ((__half2*)hi)[2 * i]     = __half2(__float2half(v.x), __float2half(v.y));
    ((__half2*)hi)[2 * i + 1] = __half2(__float2half(v.z), __float2half(v.w));
}

// ---------------------------------------------------------------------------
// RoPE + RMSNorm(*1.2) + gated ve add; reads fused qkv, writes hi-only q,k,v
// ---------------------------------------------------------------------------
__global__ __launch_bounds__(384) void rope_rms_gate_kernel(
    const float* __restrict__ x, const float* __restrict__ ve,
    const float* __restrict__ cosb, const float* __restrict__ sinb,
    const float* __restrict__ Wg)
{
    const int tok = blockIdx.x;
    const int t = tok & (Tz - 1);
    const int h = threadIdx.x >> 5;
    const int lane = threadIdx.x & 31;
    const size_t qkvbase = (size_t)tok * QKVN + h * HDz;
    const size_t base = (size_t)tok * Cz + h * HDz;

    const float cv = cosb[t * 32 + lane];
    const float sv = sinb[t * 32 + lane];

    {   // q: rope + rms, hi only
        float x1 = g_qkv[qkvbase + lane], x2 = g_qkv[qkvbase + 32 + lane];
        float r1 = x1 * cv - x2 * sv;
        float r2 = x1 * sv + x2 * cv;
        float ss = r1 * r1 + r2 * r2;
#pragma unroll
        for (int o = 16; o > 0; o >>= 1) ss += __shfl_xor_sync(0xFFFFFFFFu, ss, o);
        float inv = rsqrtf(ss * (1.0f / 64.0f) + 1e-6f) * 1.2f;
        g_qh[base + lane] = __float2half(r1 * inv);
        g_qh[base + 32 + lane] = __float2half(r2 * inv);
    }
    {   // k: rope + rms, hi only
        float x1 = g_qkv[qkvbase + Cz + lane], x2 = g_qkv[qkvbase + Cz + 32 + lane];
        float r1 = x1 * cv - x2 * sv;
        float r2 = x1 * sv + x2 * cv;
        float ss = r1 * r1 + r2 * r2;
#pragma unroll
        for (int o = 16; o > 0; o >>= 1) ss += __shfl_xor_sync(0xFFFFFFFFu, ss, o);
        float inv = rsqrtf(ss * (1.0f / 64.0f) + 1e-6f) * 1.2f;
        g_kh[base + lane] = __float2half(r1 * inv);
        g_kh[base + 32 + lane] = __float2half(r2 * inv);
    }
    {   // v: gated ve add, hi only
        float p = (lane < 12) ? x[(size_t)tok * Cz + lane] * Wg[h * 12 + lane] : 0.f;
#pragma unroll
        for (int o = 16; o > 0; o >>= 1) p += __shfl_xor_sync(0xFFFFFFFFu, p, o);
        float gate = 3.0f / (1.0f + __expf(-p));
        float v1 = g_qkv[qkvbase + 2 * Cz + lane]      + gate * ve[base + lane];
        float v2 = g_qkv[qkvbase + 2 * Cz + 32 + lane] + gate * ve[base + 32 + lane];
        g_vh[base + lane] = __float2half(v1);
        g_vh[base + 32 + lane] = __float2half(v2);
    }
}

// ---------------------------------------------------------------------------
// MMA flash attention, 128-query CTA tile (8 warps), sliding window.
// S = Qhi*K (1-pass); PV = Phi*V (1-pass). All fp32 accumulate.
// smem: Qh 16K | 2 stages of (Kh 8K + Vh 8K) = 48 KB.
// ---------------------------------------------------------------------------
#define ATT_QH 0
#define ATT_K  16384
#define ATT_STG 16384
#define ATT_SMEM 49152

__global__ __launch_bounds__(256, 2) void attn_mma(const int* __restrict__ winp)
{
    extern __shared__ __align__(1024) char dsm[];
    const uint32_t sb = smem_u32(dsm);
    const int tid = threadIdx.x;
    const int wid = tid >> 5, lane = tid & 31;
    const int qt0 = (gridDim.x - 1 - blockIdx.x) * 128;   // longest-first
    const int h = blockIdx.y;
    const int b = blockIdx.z;
    const int W = *winp;

    const size_t hoff = (size_t)h * HDz;
    const size_t btok = (size_t)b * Tz;

    // ---- load Q (hi): 128 rows x 8 chunks = 1024 segs, 4 iters
    {
#pragma unroll
        for (int i = 0; i < 4; i++) {
            int row = (i * 256 + tid) >> 3;
            int c16 = tid & 7;
            uint32_t so = (uint32_t)(row * 128 + c16 * 16) ^ (uint32_t)((row & 7) << 4);
            size_t go = (btok + qt0 + row) * Cz + hoff + c16 * 8;
            CPASYNC16(sb + ATT_QH + so, (const char*)(g_qh + go));
        }
        asm volatile("cp.async.commit_group;");
    }

    auto issue_kv = [&](int kt0, int s) {
        uint32_t sbase = sb + ATT_K + s * ATT_STG;
#pragma unroll
        for (int i = 0; i < 2; i++) {
            int row = (i * 256 + tid) >> 3;
            int c16 = tid & 7;
            uint32_t so = (uint32_t)(row * 128 + c16 * 16) ^ (uint32_t)((row & 7) << 4);
            size_t go = (btok + kt0 + row) * Cz + hoff + c16 * 8;
            CPASYNC16(sbase + so,        (const char*)(g_kh + go));
            CPASYNC16(sbase + 8192 + so, (const char*)(g_vh + go));
        }
        asm volatile("cp.async.commit_group;");
    };

    int lo = qt0 - W; if (lo < 0) lo = 0;
    const int kt_begin = lo & ~63;
    const int nt = ((qt0 + 64 - kt_begin) >> 6) + 1;   // cover queries up to qt0+127

    issue_kv(kt_begin, 0);

    const int arow = wid * 16 + (lane & 15);
    const uint32_t aswzQ = (uint32_t)((arow & 7) << 4);
    const uint32_t acol_hi = (uint32_t)((lane >> 4) << 4);

    const int r0 = qt0 + wid * 16 + (lane >> 2);
    const int r1 = r0 + 8;
    const int cbase = (lane & 3) * 2;

    float m0 = -1e30f, m1 = -1e30f, l0 = 0.f, l1 = 0.f;
    float o[8][4];
#pragma unroll
    for (int j = 0; j < 8; j++)
#pragma unroll
        for (int q = 0; q < 4; q++) o[j][q] = 0.f;

#pragma unroll 1
    for (int it = 0; it < nt; ++it) {
        const int kt0 = kt_begin + it * 64;
        if (it + 1 < nt) {
            issue_kv(kt0 + 64, (it + 1) & 1);
            asm volatile("cp.async.wait_group 1;");
        } else {
            asm volatile("cp.async.wait_group 0;");
        }
        __syncthreads();

        const uint32_t kvb = sb + ATT_K + (it & 1) * ATT_STG;

        // ---- S = Q K^T (1-pass)
        float sa[8][4];
#pragma unroll
        for (int j = 0; j < 8; j++)
#pragma unroll
            for (int q = 0; q < 4; q++) sa[j][q] = 0.f;

#pragma unroll
        for (int kk = 0; kk < 4; ++kk) {
            uint32_t ah[4];
            {
                uint32_t bc = ((uint32_t)(kk * 32) + acol_hi) ^ aswzQ;
                uint32_t ra = sb + ATT_QH + (uint32_t)(arow * 128) + bc;
                LDSM4(ah, ra);
            }
            uint32_t kh[4][4];
            {
                const int grp = lane >> 3;
                const int krow_off = (grp >> 1) * 8 + (lane & 7);
                const uint32_t bc_off = (uint32_t)(kk * 32 + (grp & 1) * 16);
#pragma unroll
                for (int p = 0; p < 4; p++) {
                    int krow = p * 16 + krow_off;
                    uint32_t so = (uint32_t)(krow * 128) + (bc_off ^ ((uint32_t)(krow & 7) << 4));
                    LDSM4(kh[p], kvb + so);
                }
            }
#pragma unroll
            for (int p = 0; p < 4; p++) {
                MMAH(sa[2 * p],     ah, kh[p][0], kh[p][1]);
                MMAH(sa[2 * p + 1], ah, kh[p][2], kh[p][3]);
            }
        }

        // ---- masked online softmax
        float rm0 = -1e30f, rm1 = -1e30f;
#pragma unroll
        for (int j = 0; j < 8; j++) {
            const int c0 = kt0 + j * 8 + cbase;
            const int c1 = c0 + 1;
            bool ok00 = (c0 <= r0) && (r0 - c0 <= W);
            bool ok01 = (c1 <= r0) && (r0 - c1 <= W);
            bool ok10 = (c0 <= r1) && (r1 - c0 <= W);
            bool ok11 = (c1 <= r1) && (r1 - c1 <= W);
            sa[j][0] = ok00 ? sa[j][0] * 0.125f : -1e30f;
            sa[j][1] = ok01 ? sa[j][1] * 0.125f : -1e30f;
            sa[j][2] = ok10 ? sa[j][2] * 0.125f : -1e30f;
            sa[j][3] = ok11 ? sa[j][3] * 0.125f : -1e30f;
            rm0 = fmaxf(rm0, fmaxf(sa[j][0], sa[j][1]));
            rm1 = fmaxf(rm1, fmaxf(sa[j][2], sa[j][3]));
        }
#pragma unroll
        for (int off = 1; off <= 2; off <<= 1) {
            rm0 = fmaxf(rm0, __shfl_xor_sync(0xFFFFFFFFu, rm0, off));
            rm1 = fmaxf(rm1, __shfl_xor_sync(0xFFFFFFFFu, rm1, off));
        }
        const float mn0 = fmaxf(m0, rm0);
        const float mn1 = fmaxf(m1, rm1);
        const float corr0 = __expf(m0 - mn0);
        const float corr1 = __expf(m1 - mn1);
        m0 = mn0; m1 = mn1;

        float rs0 = 0.f, rs1 = 0.f;
        uint32_t aph[4][4];
#pragma unroll
        for (int p = 0; p < 4; p++) {
#pragma unroll
            for (int jl = 0; jl < 2; jl++) {
                const int j = 2 * p + jl;
                float p0 = (sa[j][0] > -1e29f) ? __expf(sa[j][0] - mn0) : 0.f;
                float p1 = (sa[j][1] > -1e29f) ? __expf(sa[j][1] - mn0) : 0.f;
                float p2 = (sa[j][2] > -1e29f) ? __expf(sa[j][2] - mn1) : 0.f;
                float p3 = (sa[j][3] > -1e29f) ? __expf(sa[j][3] - mn1) : 0.f;
                rs0 += p0 + p1;
                rs1 += p2 + p3;
                aph[p][2 * jl + 0] = packh2(p0, p1);
                aph[p][2 * jl + 1] = packh2(p2, p3);
            }
        }
#pragma unroll
        for (int off = 1; off <= 2; off <<= 1) {
            rs0 += __shfl_xor_sync(0xFFFFFFFFu, rs0, off);
            rs1 += __shfl_xor_sync(0xFFFFFFFFu, rs1, off);
        }
        l0 = l0 * corr0 + rs0;
        l1 = l1 * corr1 + rs1;

#pragma unroll
        for (int j = 0; j < 8; j++) {
            o[j][0] *= corr0; o[j][1] *= corr0;
            o[j][2] *= corr1; o[j][3] *= corr1;
        }

        // ---- O += P V (1-pass, P hi only)
        const uint32_t vbase = kvb + 8192;
        {
            const int vrow_off = lane & 15;
            const uint32_t vcol_hi = (uint32_t)((lane >> 4) << 4);
#pragma unroll
            for (int kk = 0; kk < 4; ++kk) {
                uint32_t vh[4][4];
#pragma unroll
                for (int t = 0; t < 4; t++) {
                    int vrow = kk * 16 + vrow_off;
                    uint32_t bc = ((uint32_t)(t * 32) + vcol_hi) ^ ((uint32_t)(vrow & 7) << 4);
                    LDSM4T(vh[t], vbase + (uint32_t)(vrow * 128) + bc);
                }
#pragma unroll
                for (int t = 0; t < 4; t++) {
                    MMAH(o[2 * t],     aph[kk], vh[t][0], vh[t][1]);
                    MMAH(o[2 * t + 1], aph[kk], vh[t][2], vh[t][3]);
                }
            }
        }
        __syncthreads();
    }

    // epilogue: normalize, write fp16 y (hi only)
    const float i0 = 1.0f / l0;
    const float i1 = 1.0f / l1;
#pragma unroll
    for (int j = 0; j < 8; j++) {
        size_t col = hoff + j * 8 + cbase;
        size_t idx0 = (btok + r0) * Cz + col;
        size_t idx1 = (btok + r1) * Cz + col;
        *(__half2*)(g_yh + idx0) = __floats2half2_rn(o[j][0] * i0, o[j][1] * i0);
        *(__half2*)(g_yh + idx1) = __floats2half2_rn(o[j][2] * i1, o[j][3] * i1);
    }
}

// ---------------------------------------------------------------------------
extern "C" void kernel_launch(void* const* d_in, const int* in_sizes, int n_in,
                              void* d_out, int out_size)
{
    const float* x     = (const float*)d_in[0];
    const float* ve    = (const float*)d_in[1];
    const float* cosb  = (const float*)d_in[2];
    const float* sinb  = (const float*)d_in[3];
    const float* Wq    = (const float*)d_in[4];
    const float* Wk    = (const float*)d_in[5];
    const float* Wv    = (const float*)d_in[6];
    const float* Wproj = (const float*)d_in[7];
    const float* Wg    = (const float*)d_in[8];
    const int*   win   = (const int*)d_in[9];
    float* out = (float*)d_out;

    float* qkvp;
    __half *xhi, *whi, *yh;
    cudaGetSymbolAddress((void**)&qkvp, g_qkv);
    cudaGetSymbolAddress((void**)&xhi, g_xhi);
    cudaGetSymbolAddress((void**)&whi, g_whi);
    cudaGetSymbolAddress((void**)&yh, g_yh);

    const int WW = Cz * Cz;
    const int n4x = TOKz * Cz / 4;
    const int n4w = WW / 4;

    cvt_hi4<<<(n4x + 255) / 256, 256>>>((const float4*)x, xhi, n4x);
    cvt_weights<<<(4 * n4w + 255) / 256, 256>>>((const float4*)Wq, (const float4*)Wk,
                                                (const float4*)Wv, (const float4*)Wproj,
                                                whi, n4w);

    cudaFuncSetAttribute(gemm_mma<0>, cudaFuncAttributeMaxDynamicSharedMemorySize, GSMEM);

    // fused QKV GEMM (1-pass, hi-only): B = [Wq;Wk;Wv] hi, N = 2304
    gemm_mma<0><<<dim3(QKVN / 128, TOKz / 128), 256, GSMEM>>>(xhi, xhi, whi, qkvp, QKVN);

    rope_rms_gate_kernel<<<TOKz, 384>>>(x, ve, cosb, sinb, Wg);

    cudaFuncSetAttribute(attn_mma, cudaFuncAttributeMaxDynamicSharedMemorySize, ATT_SMEM);
    attn_mma<<<dim3(Tz / 128, NHz, Bz), 256, ATT_SMEM>>>(win);

    // projection GEMM (1-pass, hi-only): A = y hi, B = Wproj hi
    gemm_mma<0><<<dim3(Cz / 128, TOKz / 128), 256, GSMEM>>>(yh, yh, whi + 3 * WW, out, Cz);
}

// round 10
// speedup vs baseline: 8.0813x; 1.0885x over previous
#include <cuda_runtime.h>
#include <cuda_fp16.h>
#include <math.h>
#include <stdint.h>

// Problem constants
#define Bz 4
#define Tz 2048
#define Cz 768
#define NHz 12
#define HDz 64
#define TOKz (Bz * Tz)   // 8192
#define QKVN 2304        // fused q|k|v output width

// fp16 intermediate: fused qkv GEMM output
__device__ __half g_qkvh[TOKz * QKVN];

// fp16 operands
__device__ __half g_xhi[TOKz * Cz];
__device__ __half g_whi[4 * Cz * Cz];   // [Wq;Wk;Wv;Wproj] hi parts

// attention operands (hi-only)
__device__ __half g_qh[TOKz * Cz];
__device__ __half g_kh[TOKz * Cz];
__device__ __half g_vh[TOKz * Cz];

// attention output (A operand of proj GEMM, hi-only)
__device__ __half g_yh[TOKz * Cz];

// ---------------------------------------------------------------------------
// Helpers
// ---------------------------------------------------------------------------
__device__ __forceinline__ uint32_t smem_u32(const void* p) {
    uint32_t a;
    asm("{ .reg .u64 t; cvta.to.shared.u64 t, %1; cvt.u32.u64 %0, t; }"
        : "=r"(a) : "l"(p));
    return a;
}

#define LDSM4(r, addr)                                                        \
    asm volatile("ldmatrix.sync.aligned.m8n8.x4.shared.b16 {%0,%1,%2,%3}, [%4];" \
                 : "=r"((r)[0]), "=r"((r)[1]), "=r"((r)[2]), "=r"((r)[3])     \
                 : "r"(addr))

#define LDSM4T(r, addr)                                                       \
    asm volatile("ldmatrix.sync.aligned.m8n8.x4.trans.shared.b16 {%0,%1,%2,%3}, [%4];" \
                 : "=r"((r)[0]), "=r"((r)[1]), "=r"((r)[2]), "=r"((r)[3])     \
                 : "r"(addr))

#define LDSM2(r, addr)                                                        \
    asm volatile("ldmatrix.sync.aligned.m8n8.x2.shared.b16 {%0,%1}, [%2];"    \
                 : "=r"((r)[0]), "=r"((r)[1]) : "r"(addr))

#define MMAH(c, a, b0, b1)                                                    \
    asm volatile("mma.sync.aligned.m16n8k16.row.col.f32.f16.f16.f32 "        \
                 "{%0,%1,%2,%3}, {%4,%5,%6,%7}, {%8,%9}, {%0,%1,%2,%3};"     \
                 : "+f"((c)[0]), "+f"((c)[1]), "+f"((c)[2]), "+f"((c)[3])    \
                 : "r"((a)[0]), "r"((a)[1]), "r"((a)[2]), "r"((a)[3]),       \
                   "r"(b0), "r"(b1))

#define CPASYNC16(s, g)                                                       \
    asm volatile("cp.async.ca.shared.global [%0], [%1], 16;" :: "r"(s), "l"(g))

__device__ __forceinline__ uint32_t packh2(float a, float b) {
    __half2 t = __floats2half2_rn(a, b);
    return *(uint32_t*)&t;
}

// ---------------------------------------------------------------------------
// fp16 HMMA GEMM (NT): C[M x N] = A * B^T, K=768.
// TWOPASS: add Alo*Bhi pass. HALFOUT: write C as fp16 (else fp32).
// Block 128x128, chunks of 64, double buffer, occ 2.
// ---------------------------------------------------------------------------
#define GK 768
#define NCH 12
#define ARR 16384                 // one 128x64 fp16 array (swizzled)
#define STG3 (3 * ARR)            // Ahi, (Alo), Bhi slots = 48 KB
#define GSMEM (2 * STG3)          // 96 KB

template <int TWOPASS, int HALFOUT>
__global__ __launch_bounds__(256, 2) void gemm_mma(
    const __half* __restrict__ Ahi, const __half* __restrict__ Alo,
    const __half* __restrict__ Bh, void* __restrict__ Cout, int ldc)
{
    extern __shared__ __align__(1024) char dsm[];
    const uint32_t sb = smem_u32(dsm);
    const int tid = threadIdx.x;
    const int wid = tid >> 5, lane = tid & 31;
    const int bm = blockIdx.y << 7;
    const int bn = blockIdx.x << 7;
    const int warp_m = wid >> 2;
    const int warp_n = wid & 3;

    const __half* gA0 = Ahi + (size_t)bm * GK;
    const __half* gA1 = TWOPASS ? (Alo + (size_t)bm * GK) : gA0;
    const __half* gB  = Bh  + (size_t)bn * GK;

    const int lrow = tid >> 3;
    const int lc16 = tid & 7;

    float acc[4][4][4];
#pragma unroll
    for (int i = 0; i < 4; i++)
#pragma unroll
        for (int j = 0; j < 4; j++)
#pragma unroll
            for (int k = 0; k < 4; k++) acc[i][j][k] = 0.f;

    auto issue = [&](int c, int s) {
        uint32_t sbase = sb + s * STG3;
#pragma unroll
        for (int i = 0; i < 4; i++) {
            int row = lrow + i * 32;
            uint32_t so = (uint32_t)(row * 128 + lc16 * 16) ^ (uint32_t)((row & 7) << 4);
            size_t go = (size_t)row * GK + c * 64 + lc16 * 8;
            CPASYNC16(sbase + 0 * ARR + so, (const char*)(gA0 + go));
            if (TWOPASS) CPASYNC16(sbase + 1 * ARR + so, (const char*)(gA1 + go));
            CPASYNC16(sbase + 2 * ARR + so, (const char*)(gB + go));
        }
        asm volatile("cp.async.commit_group;");
    };

    issue(0, 0);

    const uint32_t aswz = (uint32_t)((lane & 7) << 4);
    const int arow = warp_m * 64 + (lane & 15);
    const int brow = warp_n * 32 + (lane & 7);
    const uint32_t akhi = (uint32_t)((lane >> 4) << 4);
    const uint32_t bkhi = (uint32_t)(((lane >> 3) & 1) << 4);

#pragma unroll 1
    for (int c = 0; c < NCH; ++c) {
        if (c + 1 < NCH) {
            issue(c + 1, (c + 1) & 1);
            asm volatile("cp.async.wait_group 1;");
        } else {
            asm volatile("cp.async.wait_group 0;");
        }
        __syncthreads();

        const uint32_t sbase = sb + (c & 1) * STG3;
#pragma unroll
        for (int ks = 0; ks < 4; ++ks) {
            uint32_t ah[4][4], al[4][4], bh[4][2];
            const uint32_t ak = ((uint32_t)(ks * 32) + akhi) ^ aswz;
            const uint32_t bk = ((uint32_t)(ks * 32) + bkhi) ^ aswz;
#pragma unroll
            for (int mt = 0; mt < 4; mt++) {
                uint32_t ra = sbase + (uint32_t)((arow + mt * 16) * 128) + ak;
                LDSM4(ah[mt], ra);
                if (TWOPASS) LDSM4(al[mt], ra + ARR);
            }
#pragma unroll
            for (int nt = 0; nt < 4; nt++) {
                uint32_t rb = sbase + 2 * ARR + (uint32_t)((brow + nt * 8) * 128) + bk;
                LDSM2(bh[nt], rb);
            }
#pragma unroll
            for (int mt = 0; mt < 4; mt++)
#pragma unroll
                for (int nt = 0; nt < 4; nt++) {
                    MMAH(acc[mt][nt], ah[mt], bh[nt][0], bh[nt][1]);
                    if (TWOPASS) MMAH(acc[mt][nt], al[mt], bh[nt][0], bh[nt][1]);
                }
        }
        __syncthreads();
    }

    const int crow = bm + warp_m * 64 + (lane >> 2);
    const int ccol = bn + warp_n * 32 + (lane & 3) * 2;
    if (HALFOUT) {
        __half* C = (__half*)Cout;
#pragma unroll
        for (int mt = 0; mt < 4; mt++)
#pragma unroll
            for (int nt = 0; nt < 4; nt++) {
                __half* p0 = C + (size_t)(crow + mt * 16) * ldc + ccol + nt * 8;
                __half* p1 = p0 + 8 * ldc;
                *(__half2*)p0 = __floats2half2_rn(acc[mt][nt][0], acc[mt][nt][1]);
                *(__half2*)p1 = __floats2half2_rn(acc[mt][nt][2], acc[mt][nt][3]);
            }
    } else {
        float* C = (float*)Cout;
#pragma unroll
        for (int mt = 0; mt < 4; mt++)
#pragma unroll
            for (int nt = 0; nt < 4; nt++) {
                float* p0 = C + (size_t)(crow + mt * 16) * ldc + ccol + nt * 8;
                float* p1 = p0 + 8 * ldc;
                *(float2*)p0 = make_float2(acc[mt][nt][0], acc[mt][nt][1]);
                *(float2*)p1 = make_float2(acc[mt][nt][2], acc[mt][nt][3]);
            }
    }
}

// ---------------------------------------------------------------------------
// Fused fp32 -> fp16 convert: x (n4x float4s) then 4 weight matrices
// ---------------------------------------------------------------------------
__global__ void cvt_all(const float4* __restrict__ x,
                        const float4* __restrict__ w0, const float4* __restrict__ w1,
                        const float4* __restrict__ w2, const float4* __restrict__ w3,
                        __half* __restrict__ xhi, __half* __restrict__ whi,
                        int n4x, int n4w)
{
    int i = blockIdx.x * 256 + threadIdx.x;
    const float4* src;
    __half* dst;
    int r;
    if (i < n4x) {
        src = x; dst = xhi; r = i;
    } else {
        int j = i - n4x;
        int m = j / n4w;
        if (m >= 4) return;
        r = j - m * n4w;
        src = (m == 0) ? w0 : (m == 1) ? w1 : (m == 2) ? w2 : w3;
        dst = whi + (size_t)m * (Cz * Cz);
    }
    float4 v = src[r];
    ((__half2*)dst)[2 * r]     = __half2(__float2half(v.x), __float2half(v.y));
    ((__half2*)dst)[2 * r + 1] = __half2(__float2half(v.z), __float2half(v.w));
}

// ---------------------------------------------------------------------------
// RoPE + RMSNorm(*1.2) + gated ve add; reads fp16 qkv, writes hi-only q,k,v
// ---------------------------------------------------------------------------
__global__ __launch_bounds__(384) void rope_rms_gate_kernel(
    const float* __restrict__ x, const float* __restrict__ ve,
    const float* __restrict__ cosb, const float* __restrict__ sinb,
    const float* __restrict__ Wg)
{
    const int tok = blockIdx.x;
    const int t = tok & (Tz - 1);
    const int h = threadIdx.x >> 5;
    const int lane = threadIdx.x & 31;
    const size_t qkvbase = (size_t)tok * QKVN + h * HDz;
    const size_t base = (size_t)tok * Cz + h * HDz;

    const float cv = cosb[t * 32 + lane];
    const float sv = sinb[t * 32 + lane];

    {   // q: rope + rms
        float x1 = __half2float(g_qkvh[qkvbase + lane]);
        float x2 = __half2float(g_qkvh[qkvbase + 32 + lane]);
        float r1 = x1 * cv - x2 * sv;
        float r2 = x1 * sv + x2 * cv;
        float ss = r1 * r1 + r2 * r2;
#pragma unroll
        for (int o = 16; o > 0; o >>= 1) ss += __shfl_xor_sync(0xFFFFFFFFu, ss, o);
        float inv = rsqrtf(ss * (1.0f / 64.0f) + 1e-6f) * 1.2f;
        g_qh[base + lane] = __float2half(r1 * inv);
        g_qh[base + 32 + lane] = __float2half(r2 * inv);
    }
    {   // k: rope + rms
        float x1 = __half2float(g_qkvh[qkvbase + Cz + lane]);
        float x2 = __half2float(g_qkvh[qkvbase + Cz + 32 + lane]);
        float r1 = x1 * cv - x2 * sv;
        float r2 = x1 * sv + x2 * cv;
        float ss = r1 * r1 + r2 * r2;
#pragma unroll
        for (int o = 16; o > 0; o >>= 1) ss += __shfl_xor_sync(0xFFFFFFFFu, ss, o);
        float inv = rsqrtf(ss * (1.0f / 64.0f) + 1e-6f) * 1.2f;
        g_kh[base + lane] = __float2half(r1 * inv);
        g_kh[base + 32 + lane] = __float2half(r2 * inv);
    }
    {   // v: gated ve add
        float p = (lane < 12) ? x[(size_t)tok * Cz + lane] * Wg[h * 12 + lane] : 0.f;
#pragma unroll
        for (int o = 16; o > 0; o >>= 1) p += __shfl_xor_sync(0xFFFFFFFFu, p, o);
        float gate = 3.0f / (1.0f + __expf(-p));
        float v1 = __half2float(g_qkvh[qkvbase + 2 * Cz + lane])      + gate * ve[base + lane];
        float v2 = __half2float(g_qkvh[qkvbase + 2 * Cz + 32 + lane]) + gate * ve[base + 32 + lane];
        g_vh[base + lane] = __float2half(v1);
        g_vh[base + 32 + lane] = __float2half(v2);
    }
}

// ---------------------------------------------------------------------------
// MMA flash attention, 128-query CTA tile (8 warps), sliding window.
// S = Qhi*K (1-pass); PV = Phi*V (1-pass). Interior tiles skip masking.
// smem: Qh 16K | 2 stages of (Kh 8K + Vh 8K) = 48 KB.
// ---------------------------------------------------------------------------
#define ATT_QH 0
#define ATT_K  16384
#define ATT_STG 16384
#define ATT_SMEM 49152

__global__ __launch_bounds__(256, 2) void attn_mma(const int* __restrict__ winp)
{
    extern __shared__ __align__(1024) char dsm[];
    const uint32_t sb = smem_u32(dsm);
    const int tid = threadIdx.x;
    const int wid = tid >> 5, lane = tid & 31;
    const int qt0 = (gridDim.x - 1 - blockIdx.x) * 128;   // longest-first
    const int h = blockIdx.y;
    const int b = blockIdx.z;
    const int W = *winp;

    const size_t hoff = (size_t)h * HDz;
    const size_t btok = (size_t)b * Tz;

    // ---- load Q
    {
#pragma unroll
        for (int i = 0; i < 4; i++) {
            int row = (i * 256 + tid) >> 3;
            int c16 = tid & 7;
            uint32_t so = (uint32_t)(row * 128 + c16 * 16) ^ (uint32_t)((row & 7) << 4);
            size_t go = (btok + qt0 + row) * Cz + hoff + c16 * 8;
            CPASYNC16(sb + ATT_QH + so, (const char*)(g_qh + go));
        }
        asm volatile("cp.async.commit_group;");
    }

    auto issue_kv = [&](int kt0, int s) {
        uint32_t sbase = sb + ATT_K + s * ATT_STG;
#pragma unroll
        for (int i = 0; i < 2; i++) {
            int row = (i * 256 + tid) >> 3;
            int c16 = tid & 7;
            uint32_t so = (uint32_t)(row * 128 + c16 * 16) ^ (uint32_t)((row & 7) << 4);
            size_t go = (btok + kt0 + row) * Cz + hoff + c16 * 8;
            CPASYNC16(sbase + so,        (const char*)(g_kh + go));
            CPASYNC16(sbase + 8192 + so, (const char*)(g_vh + go));
        }
        asm volatile("cp.async.commit_group;");
    };

    int lo = qt0 - W; if (lo < 0) lo = 0;
    const int kt_begin = lo & ~63;
    const int nt = ((qt0 + 64 - kt_begin) >> 6) + 1;

    issue_kv(kt_begin, 0);

    const int arow = wid * 16 + (lane & 15);
    const uint32_t aswzQ = (uint32_t)((arow & 7) << 4);
    const uint32_t acol_hi = (uint32_t)((lane >> 4) << 4);

    const int r0 = qt0 + wid * 16 + (lane >> 2);
    const int r1 = r0 + 8;
    const int cbase = (lane & 3) * 2;

    float m0 = -1e30f, m1 = -1e30f, l0 = 0.f, l1 = 0.f;
    float o[8][4];
#pragma unroll
    for (int j = 0; j < 8; j++)
#pragma unroll
        for (int q = 0; q < 4; q++) o[j][q] = 0.f;

#pragma unroll 1
    for (int it = 0; it < nt; ++it) {
        const int kt0 = kt_begin + it * 64;
        if (it + 1 < nt) {
            issue_kv(kt0 + 64, (it + 1) & 1);
            asm volatile("cp.async.wait_group 1;");
        } else {
            asm volatile("cp.async.wait_group 0;");
        }
        __syncthreads();

        const uint32_t kvb = sb + ATT_K + (it & 1) * ATT_STG;

        // ---- S = Q K^T (1-pass)
        float sa[8][4];
#pragma unroll
        for (int j = 0; j < 8; j++)
#pragma unroll
            for (int q = 0; q < 4; q++) sa[j][q] = 0.f;

#pragma unroll
        for (int kk = 0; kk < 4; ++kk) {
            uint32_t ah[4];
            {
                uint32_t bc = ((uint32_t)(kk * 32) + acol_hi) ^ aswzQ;
                uint32_t ra = sb + ATT_QH + (uint32_t)(arow * 128) + bc;
                LDSM4(ah, ra);
            }
            uint32_t kh[4][4];
            {
                const int grp = lane >> 3;
                const int krow_off = (grp >> 1) * 8 + (lane & 7);
                const uint32_t bc_off = (uint32_t)(kk * 32 + (grp & 1) * 16);
#pragma unroll
                for (int p = 0; p < 4; p++) {
                    int krow = p * 16 + krow_off;
                    uint32_t so = (uint32_t)(krow * 128) + (bc_off ^ ((uint32_t)(krow & 7) << 4));
                    LDSM4(kh[p], kvb + so);
                }
            }
#pragma unroll
            for (int p = 0; p < 4; p++) {
                MMAH(sa[2 * p],     ah, kh[p][0], kh[p][1]);
                MMAH(sa[2 * p + 1], ah, kh[p][2], kh[p][3]);
            }
        }

        // ---- online softmax; interior tiles (fully in-window) skip masking
        const bool full = (kt0 + 63 <= qt0) && (qt0 + 127 - kt0 <= W);
        float rm0 = -1e30f, rm1 = -1e30f;
        if (full) {
#pragma unroll
            for (int j = 0; j < 8; j++) {
                sa[j][0] *= 0.125f; sa[j][1] *= 0.125f;
                sa[j][2] *= 0.125f; sa[j][3] *= 0.125f;
                rm0 = fmaxf(rm0, fmaxf(sa[j][0], sa[j][1]));
                rm1 = fmaxf(rm1, fmaxf(sa[j][2], sa[j][3]));
            }
        } else {
#pragma unroll
            for (int j = 0; j < 8; j++) {
                const int c0 = kt0 + j * 8 + cbase;
                const int c1 = c0 + 1;
                bool ok00 = (c0 <= r0) && (r0 - c0 <= W);
                bool ok01 = (c1 <= r0) && (r0 - c1 <= W);
                bool ok10 = (c0 <= r1) && (r1 - c0 <= W);
                bool ok11 = (c1 <= r1) && (r1 - c1 <= W);
                sa[j][0] = ok00 ? sa[j][0] * 0.125f : -1e30f;
                sa[j][1] = ok01 ? sa[j][1] * 0.125f : -1e30f;
                sa[j][2] = ok10 ? sa[j][2] * 0.125f : -1e30f;
                sa[j][3] = ok11 ? sa[j][3] * 0.125f : -1e30f;
                rm0 = fmaxf(rm0, fmaxf(sa[j][0], sa[j][1]));
                rm1 = fmaxf(rm1, fmaxf(sa[j][2], sa[j][3]));
            }
        }
#pragma unroll
        for (int off = 1; off <= 2; off <<= 1) {
            rm0 = fmaxf(rm0, __shfl_xor_sync(0xFFFFFFFFu, rm0, off));
            rm1 = fmaxf(rm1, __shfl_xor_sync(0xFFFFFFFFu, rm1, off));
        }
        const float mn0 = fmaxf(m0, rm0);
        const float mn1 = fmaxf(m1, rm1);
        const float corr0 = __expf(m0 - mn0);
        const float corr1 = __expf(m1 - mn1);
        m0 = mn0; m1 = mn1;

        float rs0 = 0.f, rs1 = 0.f;
        uint32_t aph[4][4];
        if (full) {
#pragma unroll
            for (int p = 0; p < 4; p++) {
#pragma unroll
                for (int jl = 0; jl < 2; jl++) {
                    const int j = 2 * p + jl;
                    float p0 = __expf(sa[j][0] - mn0);
                    float p1 = __expf(sa[j][1] - mn0);
                    float p2 = __expf(sa[j][2] - mn1);
                    float p3 = __expf(sa[j][3] - mn1);
                    rs0 += p0 + p1;
                    rs1 += p2 + p3;
                    aph[p][2 * jl + 0] = packh2(p0, p1);
                    aph[p][2 * jl + 1] = packh2(p2, p3);
                }
            }
        } else {
#pragma unroll
            for (int p = 0; p < 4; p++) {
#pragma unroll
                for (int jl = 0; jl < 2; jl++) {
                    const int j = 2 * p + jl;
                    float p0 = (sa[j][0] > -1e29f) ? __expf(sa[j][0] - mn0) : 0.f;
                    float p1 = (sa[j][1] > -1e29f) ? __expf(sa[j][1] - mn0) : 0.f;
                    float p2 = (sa[j][2] > -1e29f) ? __expf(sa[j][2] - mn1) : 0.f;
                    float p3 = (sa[j][3] > -1e29f) ? __expf(sa[j][3] - mn1) : 0.f;
                    rs0 += p0 + p1;
                    rs1 += p2 + p3;
                    aph[p][2 * jl + 0] = packh2(p0, p1);
                    aph[p][2 * jl + 1] = packh2(p2, p3);
                }
            }
        }
#pragma unroll
        for (int off = 1; off <= 2; off <<= 1) {
            rs0 += __shfl_xor_sync(0xFFFFFFFFu, rs0, off);
            rs1 += __shfl_xor_sync(0xFFFFFFFFu, rs1, off);
        }
        l0 = l0 * corr0 + rs0;
        l1 = l1 * corr1 + rs1;

#pragma unroll
        for (int j = 0; j < 8; j++) {
            o[j][0] *= corr0; o[j][1] *= corr0;
            o[j][2] *= corr1; o[j][3] *= corr1;
        }

        // ---- O += P V
        const uint32_t vbase = kvb + 8192;
        {
            const int vrow_off = lane & 15;
            const uint32_t vcol_hi = (uint32_t)((lane >> 4) << 4);
#pragma unroll
            for (int kk = 0; kk < 4; ++kk) {
                uint32_t vh[4][4];
#pragma unroll
                for (int t = 0; t < 4; t++) {
                    int vrow = kk * 16 + vrow_off;
                    uint32_t bc = ((uint32_t)(t * 32) + vcol_hi) ^ ((uint32_t)(vrow & 7) << 4);
                    LDSM4T(vh[t], vbase + (uint32_t)(vrow * 128) + bc);
                }
#pragma unroll
                for (int t = 0; t < 4; t++) {
                    MMAH(o[2 * t],     aph[kk], vh[t][0], vh[t][1]);
                    MMAH(o[2 * t + 1], aph[kk], vh[t][2], vh[t][3]);
                }
            }
        }
        __syncthreads();
    }

    // epilogue: normalize, write fp16 y
    const float i0 = 1.0f / l0;
    const float i1 = 1.0f / l1;
#pragma unroll
    for (int j = 0; j < 8; j++) {
        size_t col = hoff + j * 8 + cbase;
        size_t idx0 = (btok + r0) * Cz + col;
        size_t idx1 = (btok + r1) * Cz + col;
        *(__half2*)(g_yh + idx0) = __floats2half2_rn(o[j][0] * i0, o[j][1] * i0);
        *(__half2*)(g_yh + idx1) = __floats2half2_rn(o[j][2] * i1, o[j][3] * i1);
    }
}

// ---------------------------------------------------------------------------
extern "C" void kernel_launch(void* const* d_in, const int* in_sizes, int n_in,
                              void* d_out, int out_size)
{
    const float* x     = (const float*)d_in[0];
    const float* ve    = (const float*)d_in[1];
    const float* cosb  = (const float*)d_in[2];
    const float* sinb  = (const float*)d_in[3];
    const float* Wq    = (const float*)d_in[4];
    const float* Wk    = (const float*)d_in[5];
    const float* Wv    = (const float*)d_in[6];
    const float* Wproj = (const float*)d_in[7];
    const float* Wg    = (const float*)d_in[8];
    const int*   win   = (const int*)d_in[9];
    float* out = (float*)d_out;

    __half *qkvh, *xhi, *whi, *yh;
    cudaGetSymbolAddress((void**)&qkvh, g_qkvh);
    cudaGetSymbolAddress((void**)&xhi, g_xhi);
    cudaGetSymbolAddress((void**)&whi, g_whi);
    cudaGetSymbolAddress((void**)&yh, g_yh);

    const int WW = Cz * Cz;
    const int n4x = TOKz * Cz / 4;
    const int n4w = WW / 4;
    const int n4tot = n4x + 4 * n4w;

    cvt_all<<<(n4tot + 255) / 256, 256>>>((const float4*)x,
                                          (const float4*)Wq, (const float4*)Wk,
                                          (const float4*)Wv, (const float4*)Wproj,
                                          xhi, whi, n4x, n4w);

    cudaFuncSetAttribute((const void*)gemm_mma<0, 1>,
                         cudaFuncAttributeMaxDynamicSharedMemorySize, GSMEM);
    cudaFuncSetAttribute((const void*)gemm_mma<0, 0>,
                         cudaFuncAttributeMaxDynamicSharedMemorySize, GSMEM);

    // fused QKV GEMM (1-pass, fp16 out): B = [Wq;Wk;Wv] hi, N = 2304
    gemm_mma<0, 1><<<dim3(QKVN / 128, TOKz / 128), 256, GSMEM>>>(xhi, xhi, whi, qkvh, QKVN);

    rope_rms_gate_kernel<<<TOKz, 384>>>(x, ve, cosb, sinb, Wg);

    cudaFuncSetAttribute(attn_mma, cudaFuncAttributeMaxDynamicSharedMemorySize, ATT_SMEM);
    attn_mma<<<dim3(Tz / 128, NHz, Bz), 256, ATT_SMEM>>>(win);

    // projection GEMM (1-pass, fp32 out): A = y hi, B = Wproj hi
    gemm_mma<0, 0><<<dim3(Cz / 128, TOKz / 128), 256, GSMEM>>>(yh, yh, whi + 3 * WW, out, Cz);
}

// round 11
// speedup vs baseline: 8.7515x; 1.0829x over previous
#include <cuda_runtime.h>
#include <cuda_fp16.h>
#include <math.h>
#include <stdint.h>

// Problem constants
#define Bz 4
#define Tz 2048
#define Cz 768
#define NHz 12
#define HDz 64
#define TOKz (Bz * Tz)   // 8192
#define QKVN 2304        // fused q|k|v output width

// fp16 intermediate: fused qkv GEMM output
__device__ __half g_qkvh[TOKz * QKVN];

// fp16 operands
__device__ __half g_xhi[TOKz * Cz];
__device__ __half g_veh[TOKz * Cz];
__device__ __half g_whi[4 * Cz * Cz];   // [Wq;Wk;Wv;Wproj] hi parts

// attention operands (hi-only; q pre-scaled by 1.2*0.125)
__device__ __half g_qh[TOKz * Cz];
__device__ __half g_kh[TOKz * Cz];
__device__ __half g_vh[TOKz * Cz];

// attention output (A operand of proj GEMM)
__device__ __half g_yh[TOKz * Cz];

// ---------------------------------------------------------------------------
// Helpers
// ---------------------------------------------------------------------------
__device__ __forceinline__ uint32_t smem_u32(const void* p) {
    uint32_t a;
    asm("{ .reg .u64 t; cvta.to.shared.u64 t, %1; cvt.u32.u64 %0, t; }"
        : "=r"(a) : "l"(p));
    return a;
}

#define LDSM4(r, addr)                                                        \
    asm volatile("ldmatrix.sync.aligned.m8n8.x4.shared.b16 {%0,%1,%2,%3}, [%4];" \
                 : "=r"((r)[0]), "=r"((r)[1]), "=r"((r)[2]), "=r"((r)[3])     \
                 : "r"(addr))

#define LDSM4T(r, addr)                                                       \
    asm volatile("ldmatrix.sync.aligned.m8n8.x4.trans.shared.b16 {%0,%1,%2,%3}, [%4];" \
                 : "=r"((r)[0]), "=r"((r)[1]), "=r"((r)[2]), "=r"((r)[3])     \
                 : "r"(addr))

#define LDSM2(r, addr)                                                        \
    asm volatile("ldmatrix.sync.aligned.m8n8.x2.shared.b16 {%0,%1}, [%2];"    \
                 : "=r"((r)[0]), "=r"((r)[1]) : "r"(addr))

#define MMAH(c, a, b0, b1)                                                    \
    asm volatile("mma.sync.aligned.m16n8k16.row.col.f32.f16.f16.f32 "        \
                 "{%0,%1,%2,%3}, {%4,%5,%6,%7}, {%8,%9}, {%0,%1,%2,%3};"     \
                 : "+f"((c)[0]), "+f"((c)[1]), "+f"((c)[2]), "+f"((c)[3])    \
                 : "r"((a)[0]), "r"((a)[1]), "r"((a)[2]), "r"((a)[3]),       \
                   "r"(b0), "r"(b1))

#define CPASYNC16(s, g)                                                       \
    asm volatile("cp.async.ca.shared.global [%0], [%1], 16;" :: "r"(s), "l"(g))

__device__ __forceinline__ uint32_t packh2(float a, float b) {
    __half2 t = __floats2half2_rn(a, b);
    return *(uint32_t*)&t;
}

// ---------------------------------------------------------------------------
// fp16 HMMA GEMM (NT): C[M x N] = A * B^T, K=768, 1-pass (hi-only).
// HALFOUT: write C as fp16 (else fp32). Block 128x128, chunks of 64, occ 2.
// ---------------------------------------------------------------------------
#define GK 768
#define NCH 12
#define ARR 16384                 // one 128x64 fp16 array (swizzled)
#define STG2 (2 * ARR)            // Ahi, Bhi = 32 KB
#define GSMEM (2 * STG2)          // 64 KB

template <int HALFOUT>
__global__ __launch_bounds__(256, 2) void gemm_mma(
    const __half* __restrict__ Ahi,
    const __half* __restrict__ Bh, void* __restrict__ Cout, int ldc)
{
    extern __shared__ __align__(1024) char dsm[];
    const uint32_t sb = smem_u32(dsm);
    const int tid = threadIdx.x;
    const int wid = tid >> 5, lane = tid & 31;
    const int bm = blockIdx.y << 7;
    const int bn = blockIdx.x << 7;
    const int warp_m = wid >> 2;
    const int warp_n = wid & 3;

    const __half* gA0 = Ahi + (size_t)bm * GK;
    const __half* gB  = Bh  + (size_t)bn * GK;

    const int lrow = tid >> 3;
    const int lc16 = tid & 7;

    float acc[4][4][4];
#pragma unroll
    for (int i = 0; i < 4; i++)
#pragma unroll
        for (int j = 0; j < 4; j++)
#pragma unroll
            for (int k = 0; k < 4; k++) acc[i][j][k] = 0.f;

    auto issue = [&](int c, int s) {
        uint32_t sbase = sb + s * STG2;
#pragma unroll
        for (int i = 0; i < 4; i++) {
            int row = lrow + i * 32;
            uint32_t so = (uint32_t)(row * 128 + lc16 * 16) ^ (uint32_t)((row & 7) << 4);
            size_t go = (size_t)row * GK + c * 64 + lc16 * 8;
            CPASYNC16(sbase + so,       (const char*)(gA0 + go));
            CPASYNC16(sbase + ARR + so, (const char*)(gB + go));
        }
        asm volatile("cp.async.commit_group;");
    };

    issue(0, 0);

    const uint32_t aswz = (uint32_t)((lane & 7) << 4);
    const int arow = warp_m * 64 + (lane & 15);
    const int brow = warp_n * 32 + (lane & 7);
    const uint32_t akhi = (uint32_t)((lane >> 4) << 4);
    const uint32_t bkhi = (uint32_t)(((lane >> 3) & 1) << 4);

#pragma unroll 1
    for (int c = 0; c < NCH; ++c) {
        if (c + 1 < NCH) {
            issue(c + 1, (c + 1) & 1);
            asm volatile("cp.async.wait_group 1;");
        } else {
            asm volatile("cp.async.wait_group 0;");
        }
        __syncthreads();

        const uint32_t sbase = sb + (c & 1) * STG2;
#pragma unroll
        for (int ks = 0; ks < 4; ++ks) {
            uint32_t ah[4][4], bh[4][2];
            const uint32_t ak = ((uint32_t)(ks * 32) + akhi) ^ aswz;
            const uint32_t bk = ((uint32_t)(ks * 32) + bkhi) ^ aswz;
#pragma unroll
            for (int mt = 0; mt < 4; mt++) {
                uint32_t ra = sbase + (uint32_t)((arow + mt * 16) * 128) + ak;
                LDSM4(ah[mt], ra);
            }
#pragma unroll
            for (int nt = 0; nt < 4; nt++) {
                uint32_t rb = sbase + ARR + (uint32_t)((brow + nt * 8) * 128) + bk;
                LDSM2(bh[nt], rb);
            }
#pragma unroll
            for (int mt = 0; mt < 4; mt++)
#pragma unroll
                for (int nt = 0; nt < 4; nt++)
                    MMAH(acc[mt][nt], ah[mt], bh[nt][0], bh[nt][1]);
        }
        __syncthreads();
    }

    const int crow = bm + warp_m * 64 + (lane >> 2);
    const int ccol = bn + warp_n * 32 + (lane & 3) * 2;
    if (HALFOUT) {
        __half* C = (__half*)Cout;
#pragma unroll
        for (int mt = 0; mt < 4; mt++)
#pragma unroll
            for (int nt = 0; nt < 4; nt++) {
                __half* p0 = C + (size_t)(crow + mt * 16) * ldc + ccol + nt * 8;
                __half* p1 = p0 + 8 * ldc;
                *(__half2*)p0 = __floats2half2_rn(acc[mt][nt][0], acc[mt][nt][1]);
                *(__half2*)p1 = __floats2half2_rn(acc[mt][nt][2], acc[mt][nt][3]);
            }
    } else {
        float* C = (float*)Cout;
#pragma unroll
        for (int mt = 0; mt < 4; mt++)
#pragma unroll
            for (int nt = 0; nt < 4; nt++) {
                float* p0 = C + (size_t)(crow + mt * 16) * ldc + ccol + nt * 8;
                float* p1 = p0 + 8 * ldc;
                *(float2*)p0 = make_float2(acc[mt][nt][0], acc[mt][nt][1]);
                *(float2*)p1 = make_float2(acc[mt][nt][2], acc[mt][nt][3]);
            }
    }
}

// ---------------------------------------------------------------------------
// Fused fp32 -> fp16 convert: x, ve, then 4 weight matrices
// ---------------------------------------------------------------------------
__global__ void cvt_all(const float4* __restrict__ x, const float4* __restrict__ ve,
                        const float4* __restrict__ w0, const float4* __restrict__ w1,
                        const float4* __restrict__ w2, const float4* __restrict__ w3,
                        __half* __restrict__ xhi, __half* __restrict__ veh,
                        __half* __restrict__ whi, int n4x, int n4w)
{
    int i = blockIdx.x * 256 + threadIdx.x;
    const float4* src;
    __half* dst;
    int r;
    if (i < n4x) {
        src = x; dst = xhi; r = i;
    } else if (i < 2 * n4x) {
        src = ve; dst = veh; r = i - n4x;
    } else {
        int j = i - 2 * n4x;
        int m = j / n4w;
        if (m >= 4) return;
        r = j - m * n4w;
        src = (m == 0) ? w0 : (m == 1) ? w1 : (m == 2) ? w2 : w3;
        dst = whi + (size_t)m * (Cz * Cz);
    }
    float4 v = src[r];
    ((__half2*)dst)[2 * r]     = __half2(__float2half(v.x), __float2half(v.y));
    ((__half2*)dst)[2 * r + 1] = __half2(__float2half(v.z), __float2half(v.w));
}

// ---------------------------------------------------------------------------
// RoPE + RMSNorm + gated ve add; q gets the softmax scale folded in
// (1.2 * 0.125 = 0.15; 0.125 is a power of two -> fp16 rounding unchanged)
// ---------------------------------------------------------------------------
__global__ __launch_bounds__(384) void rope_rms_gate_kernel(
    const float* __restrict__ x,
    const float* __restrict__ cosb, const float* __restrict__ sinb,
    const float* __restrict__ Wg)
{
    const int tok = blockIdx.x;
    const int t = tok & (Tz - 1);
    const int h = threadIdx.x >> 5;
    const int lane = threadIdx.x & 31;
    const size_t qkvbase = (size_t)tok * QKVN + h * HDz;
    const size_t base = (size_t)tok * Cz + h * HDz;

    const float cv = cosb[t * 32 + lane];
    const float sv = sinb[t * 32 + lane];

    {   // q: rope + rms (* 1.2 * 0.125)
        float x1 = __half2float(g_qkvh[qkvbase + lane]);
        float x2 = __half2float(g_qkvh[qkvbase + 32 + lane]);
        float r1 = x1 * cv - x2 * sv;
        float r2 = x1 * sv + x2 * cv;
        float ss = r1 * r1 + r2 * r2;
#pragma unroll
        for (int o = 16; o > 0; o >>= 1) ss += __shfl_xor_sync(0xFFFFFFFFu, ss, o);
        float inv = rsqrtf(ss * (1.0f / 64.0f) + 1e-6f) * 0.15f;
        g_qh[base + lane] = __float2half(r1 * inv);
        g_qh[base + 32 + lane] = __float2half(r2 * inv);
    }
    {   // k: rope + rms (* 1.2)
        float x1 = __half2float(g_qkvh[qkvbase + Cz + lane]);
        float x2 = __half2float(g_qkvh[qkvbase + Cz + 32 + lane]);
        float r1 = x1 * cv - x2 * sv;
        float r2 = x1 * sv + x2 * cv;
        float ss = r1 * r1 + r2 * r2;
#pragma unroll
        for (int o = 16; o > 0; o >>= 1) ss += __shfl_xor_sync(0xFFFFFFFFu, ss, o);
        float inv = rsqrtf(ss * (1.0f / 64.0f) + 1e-6f) * 1.2f;
        g_kh[base + lane] = __float2half(r1 * inv);
        g_kh[base + 32 + lane] = __float2half(r2 * inv);
    }
    {   // v: gated ve add (ve in fp16)
        float p = (lane < 12) ? x[(size_t)tok * Cz + lane] * Wg[h * 12 + lane] : 0.f;
#pragma unroll
        for (int o = 16; o > 0; o >>= 1) p += __shfl_xor_sync(0xFFFFFFFFu, p, o);
        float gate = 3.0f / (1.0f + __expf(-p));
        float v1 = __half2float(g_qkvh[qkvbase + 2 * Cz + lane])
                 + gate * __half2float(g_veh[base + lane]);
        float v2 = __half2float(g_qkvh[qkvbase + 2 * Cz + 32 + lane])
                 + gate * __half2float(g_veh[base + 32 + lane]);
        g_vh[base + lane] = __float2half(v1);
        g_vh[base + 32 + lane] = __float2half(v2);
    }
}

// ---------------------------------------------------------------------------
// MMA flash attention, 64-query CTA (4 warps, 128 thr, occ 4), sliding window.
// S = Q*K (1-pass, scale pre-folded into q); PV = P*V (1-pass).
// smem: Q 8K | 2 stages of (K 8K + V 8K) = 40 KB.
// ---------------------------------------------------------------------------
#define ATT_QH 0
#define ATT_K  8192
#define ATT_STG 16384
#define ATT_SMEM (8192 + 2 * ATT_STG)   // 40960

__global__ __launch_bounds__(128, 4) void attn_mma(const int* __restrict__ winp)
{
    extern __shared__ __align__(1024) char dsm[];
    const uint32_t sb = smem_u32(dsm);
    const int tid = threadIdx.x;
    const int wid = tid >> 5, lane = tid & 31;
    const int qt0 = (gridDim.x - 1 - blockIdx.x) * 64;   // longest-first
    const int h = blockIdx.y;
    const int b = blockIdx.z;
    const int W = *winp;

    const size_t hoff = (size_t)h * HDz;
    const size_t btok = (size_t)b * Tz;

    // ---- load Q: 64 rows x 8 chunks = 512 segs, 4 iters of 128 threads
    {
#pragma unroll
        for (int i = 0; i < 4; i++) {
            int row = (i * 128 + tid) >> 3;
            int c16 = tid & 7;
            uint32_t so = (uint32_t)(row * 128 + c16 * 16) ^ (uint32_t)((row & 7) << 4);
            size_t go = (btok + qt0 + row) * Cz + hoff + c16 * 8;
            CPASYNC16(sb + ATT_QH + so, (const char*)(g_qh + go));
        }
        asm volatile("cp.async.commit_group;");
    }

    auto issue_kv = [&](int kt0, int s) {
        uint32_t sbase = sb + ATT_K + s * ATT_STG;
#pragma unroll
        for (int i = 0; i < 4; i++) {
            int row = (i * 128 + tid) >> 3;
            int c16 = tid & 7;
            uint32_t so = (uint32_t)(row * 128 + c16 * 16) ^ (uint32_t)((row & 7) << 4);
            size_t go = (btok + kt0 + row) * Cz + hoff + c16 * 8;
            CPASYNC16(sbase + so,        (const char*)(g_kh + go));
            CPASYNC16(sbase + 8192 + so, (const char*)(g_vh + go));
        }
        asm volatile("cp.async.commit_group;");
    };

    int lo = qt0 - W; if (lo < 0) lo = 0;
    const int kt_begin = lo & ~63;
    const int nt = ((qt0 - kt_begin) >> 6) + 1;

    issue_kv(kt_begin, 0);

    const int arow = wid * 16 + (lane & 15);
    const uint32_t aswzQ = (uint32_t)((arow & 7) << 4);
    const uint32_t acol_hi = (uint32_t)((lane >> 4) << 4);

    const int r0 = qt0 + wid * 16 + (lane >> 2);
    const int r1 = r0 + 8;
    const int cbase = (lane & 3) * 2;

    float m0 = -1e30f, m1 = -1e30f, l0 = 0.f, l1 = 0.f;
    float o[8][4];
#pragma unroll
    for (int j = 0; j < 8; j++)
#pragma unroll
        for (int q = 0; q < 4; q++) o[j][q] = 0.f;

#pragma unroll 1
    for (int it = 0; it < nt; ++it) {
        const int kt0 = kt_begin + it * 64;
        if (it + 1 < nt) {
            issue_kv(kt0 + 64, (it + 1) & 1);
            asm volatile("cp.async.wait_group 1;");
        } else {
            asm volatile("cp.async.wait_group 0;");
        }
        __syncthreads();

        const uint32_t kvb = sb + ATT_K + (it & 1) * ATT_STG;

        // ---- S = Q K^T (1-pass; scale already in q)
        float sa[8][4];
#pragma unroll
        for (int j = 0; j < 8; j++)
#pragma unroll
            for (int q = 0; q < 4; q++) sa[j][q] = 0.f;

#pragma unroll
        for (int kk = 0; kk < 4; ++kk) {
            uint32_t ah[4];
            {
                uint32_t bc = ((uint32_t)(kk * 32) + acol_hi) ^ aswzQ;
                uint32_t ra = sb + ATT_QH + (uint32_t)(arow * 128) + bc;
                LDSM4(ah, ra);
            }
            uint32_t kh[4][4];
            {
                const int grp = lane >> 3;
                const int krow_off = (grp >> 1) * 8 + (lane & 7);
                const uint32_t bc_off = (uint32_t)(kk * 32 + (grp & 1) * 16);
#pragma unroll
                for (int p = 0; p < 4; p++) {
                    int krow = p * 16 + krow_off;
                    uint32_t so = (uint32_t)(krow * 128) + (bc_off ^ ((uint32_t)(krow & 7) << 4));
                    LDSM4(kh[p], kvb + so);
                }
            }
#pragma unroll
            for (int p = 0; p < 4; p++) {
                MMAH(sa[2 * p],     ah, kh[p][0], kh[p][1]);
                MMAH(sa[2 * p + 1], ah, kh[p][2], kh[p][3]);
            }
        }

        // ---- online softmax; fully-interior tiles skip masking
        const bool full = (kt0 + 63 <= qt0) && (qt0 + 63 - kt0 <= W);
        float rm0 = -1e30f, rm1 = -1e30f;
        if (full) {
#pragma unroll
            for (int j = 0; j < 8; j++) {
                rm0 = fmaxf(rm0, fmaxf(sa[j][0], sa[j][1]));
                rm1 = fmaxf(rm1, fmaxf(sa[j][2], sa[j][3]));
            }
        } else {
#pragma unroll
            for (int j = 0; j < 8; j++) {
                const int c0 = kt0 + j * 8 + cbase;
                const int c1 = c0 + 1;
                bool ok00 = (c0 <= r0) && (r0 - c0 <= W);
                bool ok01 = (c1 <= r0) && (r0 - c1 <= W);
                bool ok10 = (c0 <= r1) && (r1 - c0 <= W);
                bool ok11 = (c1 <= r1) && (r1 - c1 <= W);
                sa[j][0] = ok00 ? sa[j][0] : -1e30f;
                sa[j][1] = ok01 ? sa[j][1] : -1e30f;
                sa[j][2] = ok10 ? sa[j][2] : -1e30f;
                sa[j][3] = ok11 ? sa[j][3] : -1e30f;
                rm0 = fmaxf(rm0, fmaxf(sa[j][0], sa[j][1]));
                rm1 = fmaxf(rm1, fmaxf(sa[j][2], sa[j][3]));
            }
        }
#pragma unroll
        for (int off = 1; off <= 2; off <<= 1) {
            rm0 = fmaxf(rm0, __shfl_xor_sync(0xFFFFFFFFu, rm0, off));
            rm1 = fmaxf(rm1, __shfl_xor_sync(0xFFFFFFFFu, rm1, off));
        }
        const float mn0 = fmaxf(m0, rm0);
        const float mn1 = fmaxf(m1, rm1);
        const float corr0 = __expf(m0 - mn0);
        const float corr1 = __expf(m1 - mn1);
        m0 = mn0; m1 = mn1;

        float rs0 = 0.f, rs1 = 0.f;
        uint32_t aph[4][4];
        if (full) {
#pragma unroll
            for (int p = 0; p < 4; p++) {
#pragma unroll
                for (int jl = 0; jl < 2; jl++) {
                    const int j = 2 * p + jl;
                    float p0 = __expf(sa[j][0] - mn0);
                    float p1 = __expf(sa[j][1] - mn0);
                    float p2 = __expf(sa[j][2] - mn1);
                    float p3 = __expf(sa[j][3] - mn1);
                    rs0 += p0 + p1;
                    rs1 += p2 + p3;
                    aph[p][2 * jl + 0] = packh2(p0, p1);
                    aph[p][2 * jl + 1] = packh2(p2, p3);
                }
            }
        } else {
#pragma unroll
            for (int p = 0; p < 4; p++) {
#pragma unroll
                for (int jl = 0; jl < 2; jl++) {
                    const int j = 2 * p + jl;
                    float p0 = (sa[j][0] > -1e29f) ? __expf(sa[j][0] - mn0) : 0.f;
                    float p1 = (sa[j][1] > -1e29f) ? __expf(sa[j][1] - mn0) : 0.f;
                    float p2 = (sa[j][2] > -1e29f) ? __expf(sa[j][2] - mn1) : 0.f;
                    float p3 = (sa[j][3] > -1e29f) ? __expf(sa[j][3] - mn1) : 0.f;
                    rs0 += p0 + p1;
                    rs1 += p2 + p3;
                    aph[p][2 * jl + 0] = packh2(p0, p1);
                    aph[p][2 * jl + 1] = packh2(p2, p3);
                }
            }
        }
#pragma unroll
        for (int off = 1; off <= 2; off <<= 1) {
            rs0 += __shfl_xor_sync(0xFFFFFFFFu, rs0, off);
            rs1 += __shfl_xor_sync(0xFFFFFFFFu, rs1, off);
        }
        l0 = l0 * corr0 + rs0;
        l1 = l1 * corr1 + rs1;

#pragma unroll
        for (int j = 0; j < 8; j++) {
            o[j][0] *= corr0; o[j][1] *= corr0;
            o[j][2] *= corr1; o[j][3] *= corr1;
        }

        // ---- O += P V
        const uint32_t vbase = kvb + 8192;
        {
            const int vrow_off = lane & 15;
            const uint32_t vcol_hi = (uint32_t)((lane >> 4) << 4);
#pragma unroll
            for (int kk = 0; kk < 4; ++kk) {
                uint32_t vh[4][4];
#pragma unroll
                for (int t = 0; t < 4; t++) {
                    int vrow = kk * 16 + vrow_off;
                    uint32_t bc = ((uint32_t)(t * 32) + vcol_hi) ^ ((uint32_t)(vrow & 7) << 4);
                    LDSM4T(vh[t], vbase + (uint32_t)(vrow * 128) + bc);
                }
#pragma unroll
                for (int t = 0; t < 4; t++) {
                    MMAH(o[2 * t],     aph[kk], vh[t][0], vh[t][1]);
                    MMAH(o[2 * t + 1], aph[kk], vh[t][2], vh[t][3]);
                }
            }
        }
        __syncthreads();
    }

    // epilogue: normalize, write fp16 y
    const float i0 = 1.0f / l0;
    const float i1 = 1.0f / l1;
#pragma unroll
    for (int j = 0; j < 8; j++) {
        size_t col = hoff + j * 8 + cbase;
        size_t idx0 = (btok + r0) * Cz + col;
        size_t idx1 = (btok + r1) * Cz + col;
        *(__half2*)(g_yh + idx0) = __floats2half2_rn(o[j][0] * i0, o[j][1] * i0);
        *(__half2*)(g_yh + idx1) = __floats2half2_rn(o[j][2] * i1, o[j][3] * i1);
    }
}

// ---------------------------------------------------------------------------
extern "C" void kernel_launch(void* const* d_in, const int* in_sizes, int n_in,
                              void* d_out, int out_size)
{
    const float* x     = (const float*)d_in[0];
    const float* ve    = (const float*)d_in[1];
    const float* cosb  = (const float*)d_in[2];
    const float* sinb  = (const float*)d_in[3];
    const float* Wq    = (const float*)d_in[4];
    const float* Wk    = (const float*)d_in[5];
    const float* Wv    = (const float*)d_in[6];
    const float* Wproj = (const float*)d_in[7];
    const float* Wg    = (const float*)d_in[8];
    const int*   win   = (const int*)d_in[9];
    float* out = (float*)d_out;

    __half *qkvh, *xhi, *veh, *whi, *yh;
    cudaGetSymbolAddress((void**)&qkvh, g_qkvh);
    cudaGetSymbolAddress((void**)&xhi, g_xhi);
    cudaGetSymbolAddress((void**)&veh, g_veh);
    cudaGetSymbolAddress((void**)&whi, g_whi);
    cudaGetSymbolAddress((void**)&yh, g_yh);

    const int WW = Cz * Cz;
    const int n4x = TOKz * Cz / 4;
    const int n4w = WW / 4;
    const int n4tot = 2 * n4x + 4 * n4w;

    cvt_all<<<(n4tot + 255) / 256, 256>>>((const float4*)x, (const float4*)ve,
                                          (const float4*)Wq, (const float4*)Wk,
                                          (const float4*)Wv, (const float4*)Wproj,
                                          xhi, veh, whi, n4x, n4w);

    cudaFuncSetAttribute((const void*)gemm_mma<1>,
                         cudaFuncAttributeMaxDynamicSharedMemorySize, GSMEM);
    cudaFuncSetAttribute((const void*)gemm_mma<0>,
                         cudaFuncAttributeMaxDynamicSharedMemorySize, GSMEM);

    // fused QKV GEMM (fp16 out): B = [Wq;Wk;Wv], N = 2304
    gemm_mma<1><<<dim3(QKVN / 128, TOKz / 128), 256, GSMEM>>>(xhi, whi, qkvh, QKVN);

    rope_rms_gate_kernel<<<TOKz, 384>>>(x, cosb, sinb, Wg);

    cudaFuncSetAttribute(attn_mma, cudaFuncAttributeMaxDynamicSharedMemorySize, ATT_SMEM);
    attn_mma<<<dim3(Tz / 64, NHz, Bz), 128, ATT_SMEM>>>(win);

    // projection GEMM (fp32 out): A = y, B = Wproj
    gemm_mma<0><<<dim3(Cz / 128, TOKz / 128), 256, GSMEM>>>(yh, whi + 3 * WW, out, Cz);
}